// round 1
// baseline (speedup 1.0000x reference)
#include <cuda_runtime.h>
#include <math.h>

#define BB 8
#define SS 512
#define HH 1024
#define NHEAD 16
#define HDIM 64
#define FFD 4096
#define MTOK (BB*SS)   // 4096 tokens

// ---------------- scratch (static __device__, no allocs) ----------------
__device__ float g_q[MTOK*HH];
__device__ float g_k[MTOK*HH];
__device__ float g_v[MTOK*HH];
__device__ float g_ctx[MTOK*HH];
__device__ float g_t1[MTOK*HH];
__device__ float g_attn[MTOK*HH];
__device__ float g_inter[(size_t)MTOK*FFD];
__device__ float g_t2[MTOK*HH];

// ---------------- SGEMM: C = A[M,K] @ B[K,N] + bias (+epilogue) ---------
// EPI: 0 = bias only, 1 = gelu(bias+x), 2 = bias + residual
template<int EPI>
__global__ __launch_bounds__(256, 2)
void sgemm_kernel(const float* __restrict__ A, const float* __restrict__ B,
                  const float* __restrict__ bias, const float* __restrict__ res,
                  float* __restrict__ C, int M, int N, int K)
{
    constexpr int BM = 128, BN = 128, BK = 8, TM = 8, TN = 8;
    __shared__ float As[BK][BM];
    __shared__ float Bs[BK][BN];

    const int tid = threadIdx.x;
    const int tx = tid % 16;          // 16x16 thread grid, 8x8 microtile
    const int ty = tid / 16;

    const int aRow = tid >> 1;        // 0..127
    const int aCol = (tid & 1) * 4;   // 0 or 4
    const int bRow = tid >> 5;        // 0..7
    const int bCol = (tid & 31) * 4;  // 0..124

    const float* Ab = A + (size_t)blockIdx.y * BM * K;
    const float* Bb = B + blockIdx.x * BN;

    float acc[TM][TN];
#pragma unroll
    for (int i = 0; i < TM; i++)
#pragma unroll
        for (int j = 0; j < TN; j++) acc[i][j] = 0.f;

    for (int k0 = 0; k0 < K; k0 += BK) {
        float4 a4 = *(const float4*)(Ab + (size_t)aRow * K + k0 + aCol);
        As[aCol + 0][aRow] = a4.x;
        As[aCol + 1][aRow] = a4.y;
        As[aCol + 2][aRow] = a4.z;
        As[aCol + 3][aRow] = a4.w;
        float4 b4 = *(const float4*)(Bb + (size_t)(k0 + bRow) * N + bCol);
        *(float4*)&Bs[bRow][bCol] = b4;
        __syncthreads();

#pragma unroll
        for (int kk = 0; kk < BK; kk++) {
            float ar[TM], br[TN];
            *(float4*)(ar)     = *(const float4*)&As[kk][ty * TM];
            *(float4*)(ar + 4) = *(const float4*)&As[kk][ty * TM + 4];
            *(float4*)(br)     = *(const float4*)&Bs[kk][tx * TN];
            *(float4*)(br + 4) = *(const float4*)&Bs[kk][tx * TN + 4];
#pragma unroll
            for (int i = 0; i < TM; i++)
#pragma unroll
                for (int j = 0; j < TN; j++)
                    acc[i][j] += ar[i] * br[j];
        }
        __syncthreads();
    }

    const int row0 = blockIdx.y * BM + ty * TM;
    const int col0 = blockIdx.x * BN + tx * TN;
#pragma unroll
    for (int i = 0; i < TM; i++) {
        const int row = row0 + i;
#pragma unroll
        for (int j = 0; j < TN; j++) {
            const int col = col0 + j;
            float v = acc[i][j] + bias[col];
            if (EPI == 1) v = 0.5f * v * (1.0f + erff(v * 0.70710678118654752440f));
            if (EPI == 2) v += res[(size_t)row * N + col];
            C[(size_t)row * N + col] = v;
        }
    }
}

// ---------------- attention: softmax(QK^T/8 + mask) @ V -----------------
// grid: (32 q-blocks of 16, 16 heads, 8 batch); 256 threads
__global__ __launch_bounds__(256)
void attn_kernel(const float* __restrict__ Q, const float* __restrict__ K,
                 const float* __restrict__ V, const float* __restrict__ mask,
                 float* __restrict__ O)
{
    __shared__ float Qs[16][65];
    __shared__ float KVs[32][65];
    __shared__ float Sc[16][512];
    __shared__ float red[16][16];

    const int qb = blockIdx.x, h = blockIdx.y, b = blockIdx.z;
    const int tid = threadIdx.x;
    const int base = (b * SS) * HH + h * HDIM;
    const int q0 = qb * 16;

    // load Q tile [16,64]
    for (int i = tid; i < 16 * HDIM; i += 256) {
        int r = i / HDIM, d = i % HDIM;
        Qs[r][d] = Q[base + (q0 + r) * HH + d];
    }
    __syncthreads();

    // scores = Q K^T * 0.125 + mask
    {
        const int kj = tid & 31;       // k row within tile
        const int q2 = tid >> 5;       // 0..7
        for (int kt = 0; kt < SS; kt += 32) {
            for (int i = tid; i < 32 * HDIM; i += 256) {
                int r = i / HDIM, d = i % HDIM;
                KVs[r][d] = K[base + (kt + r) * HH + d];
            }
            __syncthreads();
            const float mk = mask[b * SS + kt + kj];
#pragma unroll
            for (int qq = 0; qq < 2; qq++) {
                const int qi = q2 + qq * 8;
                float s = 0.f;
#pragma unroll
                for (int d = 0; d < HDIM; d++) s += Qs[qi][d] * KVs[kj][d];
                Sc[qi][kt + kj] = s * 0.125f + mk;
            }
            __syncthreads();
        }
    }

    // softmax over each of the 16 rows (16 threads/row, 32 cols each)
    {
        const int qi = tid >> 4;
        const int t = tid & 15;
        float m = -1e30f;
        for (int j = t * 32; j < t * 32 + 32; j++) m = fmaxf(m, Sc[qi][j]);
        red[qi][t] = m;
        __syncthreads();
        if (t == 0) {
            float mm = -1e30f;
            for (int j = 0; j < 16; j++) mm = fmaxf(mm, red[qi][j]);
            red[qi][0] = mm;
        }
        __syncthreads();
        const float rowmax = red[qi][0];
        float sum = 0.f;
        for (int j = t * 32; j < t * 32 + 32; j++) {
            float e = __expf(Sc[qi][j] - rowmax);
            Sc[qi][j] = e;
            sum += e;
        }
        __syncthreads();           // everyone has read rowmax before reuse
        red[qi][t] = sum;
        __syncthreads();
        if (t == 0) {
            float tt = 0.f;
            for (int j = 0; j < 16; j++) tt += red[qi][j];
            red[qi][0] = tt;
        }
        __syncthreads();
    }

    // ctx = P @ V   (thread: dj = tid%64 output dim, 4 q-rows)
    {
        const int dj = tid & 63;
        const int qg = tid >> 6;   // 0..3
        float acc[4] = {0.f, 0.f, 0.f, 0.f};
        for (int vt = 0; vt < SS; vt += 32) {
            __syncthreads();       // protect KVs overwrite
            for (int i = tid; i < 32 * HDIM; i += 256) {
                int r = i / HDIM, d = i % HDIM;
                KVs[r][d] = V[base + (vt + r) * HH + d];
            }
            __syncthreads();
#pragma unroll 8
            for (int r = 0; r < 32; r++) {
                const float vv = KVs[r][dj];
#pragma unroll
                for (int qq = 0; qq < 4; qq++)
                    acc[qq] += Sc[qq * 4 + qg][vt + r] * vv;
            }
        }
#pragma unroll
        for (int qq = 0; qq < 4; qq++) {
            const int qi = qq * 4 + qg;
            const float inv = 1.f / red[qi][0];
            O[base + (q0 + qi) * HH + dj] = acc[qq] * inv;
        }
    }
}

// ---------------- layernorm: one block per token row --------------------
__global__ __launch_bounds__(256)
void ln_kernel(const float* __restrict__ x, const float* __restrict__ g,
               const float* __restrict__ bt, float* __restrict__ y)
{
    const int row = blockIdx.x;
    const int tid = threadIdx.x;
    const float* xr = x + (size_t)row * HH;
    float v[4];
    float s = 0.f;
#pragma unroll
    for (int i = 0; i < 4; i++) { v[i] = xr[tid + i * 256]; s += v[i]; }

    __shared__ float sm[8];
    __shared__ float mu_s, var_s;
#pragma unroll
    for (int o = 16; o; o >>= 1) s += __shfl_xor_sync(0xffffffffu, s, o);
    if ((tid & 31) == 0) sm[tid >> 5] = s;
    __syncthreads();
    if (tid < 32) {
        float t = (tid < 8) ? sm[tid] : 0.f;
#pragma unroll
        for (int o = 4; o; o >>= 1) t += __shfl_xor_sync(0xffffffffu, t, o);
        if (tid == 0) mu_s = t * (1.f / HH);
    }
    __syncthreads();
    const float mu = mu_s;
    float s2 = 0.f;
#pragma unroll
    for (int i = 0; i < 4; i++) { float d = v[i] - mu; s2 += d * d; }
#pragma unroll
    for (int o = 16; o; o >>= 1) s2 += __shfl_xor_sync(0xffffffffu, s2, o);
    __syncthreads();               // sm reuse
    if ((tid & 31) == 0) sm[tid >> 5] = s2;
    __syncthreads();
    if (tid < 32) {
        float t = (tid < 8) ? sm[tid] : 0.f;
#pragma unroll
        for (int o = 4; o; o >>= 1) t += __shfl_xor_sync(0xffffffffu, t, o);
        if (tid == 0) var_s = t * (1.f / HH);
    }
    __syncthreads();
    const float inv = rsqrtf(var_s + 1e-5f);
#pragma unroll
    for (int i = 0; i < 4; i++) {
        const int c = tid + i * 256;
        y[(size_t)row * HH + c] = (v[i] - mu) * inv * g[c] + bt[c];
    }
}

// ---------------- host ----------------
extern "C" void kernel_launch(void* const* d_in, const int* in_sizes, int n_in,
                              void* d_out, int out_size)
{
    (void)in_sizes; (void)n_in; (void)out_size;
    const float* x     = (const float*)d_in[0];
    const float* mask  = (const float*)d_in[1];
    const float* wq    = (const float*)d_in[2];
    const float* bq    = (const float*)d_in[3];
    const float* wk    = (const float*)d_in[4];
    const float* bk    = (const float*)d_in[5];
    const float* wv    = (const float*)d_in[6];
    const float* bv    = (const float*)d_in[7];
    const float* wo    = (const float*)d_in[8];
    const float* bo    = (const float*)d_in[9];
    const float* ln1g  = (const float*)d_in[10];
    const float* ln1b  = (const float*)d_in[11];
    const float* wi    = (const float*)d_in[12];
    const float* bi    = (const float*)d_in[13];
    const float* wo2   = (const float*)d_in[14];
    const float* bo2   = (const float*)d_in[15];
    const float* ln2g  = (const float*)d_in[16];
    const float* ln2b  = (const float*)d_in[17];
    float* out = (float*)d_out;

    float *q, *k, *v, *ctx, *t1, *attn, *inter, *t2;
    cudaGetSymbolAddress((void**)&q,     g_q);
    cudaGetSymbolAddress((void**)&k,     g_k);
    cudaGetSymbolAddress((void**)&v,     g_v);
    cudaGetSymbolAddress((void**)&ctx,   g_ctx);
    cudaGetSymbolAddress((void**)&t1,    g_t1);
    cudaGetSymbolAddress((void**)&attn,  g_attn);
    cudaGetSymbolAddress((void**)&inter, g_inter);
    cudaGetSymbolAddress((void**)&t2,    g_t2);

    const dim3 blk(256);
    const dim3 gH(HH / 128, MTOK / 128);     // N=1024 GEMMs
    const dim3 gF(FFD / 128, MTOK / 128);    // N=4096 GEMM

    // QKV projections
    sgemm_kernel<0><<<gH, blk>>>(x, wq, bq, nullptr, q, MTOK, HH, HH);
    sgemm_kernel<0><<<gH, blk>>>(x, wk, bk, nullptr, k, MTOK, HH, HH);
    sgemm_kernel<0><<<gH, blk>>>(x, wv, bv, nullptr, v, MTOK, HH, HH);

    // attention
    attn_kernel<<<dim3(SS / 16, NHEAD, BB), blk>>>(q, k, v, mask, ctx);

    // output proj + residual, LN1
    sgemm_kernel<2><<<gH, blk>>>(ctx, wo, bo, x, t1, MTOK, HH, HH);
    ln_kernel<<<MTOK, blk>>>(t1, ln1g, ln1b, attn);

    // FFN
    sgemm_kernel<1><<<gF, blk>>>(attn, wi, bi, nullptr, inter, MTOK, FFD, HH);
    sgemm_kernel<2><<<gH, blk>>>(inter, wo2, bo2, attn, t2, MTOK, HH, FFD);
    ln_kernel<<<MTOK, blk>>>(t2, ln2g, ln2b, out);
}

// round 3
// speedup vs baseline: 1.7147x; 1.7147x over previous
#include <cuda_runtime.h>
#include <cuda_bf16.h>
#include <cstdint>
#include <math.h>

#define BB 8
#define SS 512
#define HH 1024
#define NHEAD 16
#define HDIM 64
#define FFD 4096
#define MTOK (BB*SS)   // 4096 tokens

// ---------------- scratch (static __device__, no allocs) ----------------
__device__ float g_q[MTOK*HH];
__device__ float g_k[MTOK*HH];
__device__ float g_v[MTOK*HH];
__device__ float g_ctx[MTOK*HH];
__device__ float g_t1[MTOK*HH];
__device__ float g_attn[MTOK*HH];
__device__ float g_inter[(size_t)MTOK*FFD];
__device__ float g_t2[MTOK*HH];

// ==================== helpers ====================
__device__ __forceinline__ uint32_t smem_u32(const void* p) {
    uint32_t a;
    asm("{ .reg .u64 t; cvta.to.shared.u64 t, %1; cvt.u32.u64 %0, t; }" : "=r"(a) : "l"(p));
    return a;
}
__device__ __forceinline__ uint32_t lds32(uint32_t a) {
    uint32_t v; asm volatile("ld.shared.b32 %0, [%1];" : "=r"(v) : "r"(a)); return v;
}
__device__ __forceinline__ void sts32(uint32_t a, uint32_t v) {
    asm volatile("st.shared.b32 [%0], %1;" :: "r"(a), "r"(v));
}
__device__ __forceinline__ uint32_t pack2(__nv_bfloat16 a, __nv_bfloat16 b) {
    return (uint32_t)__bfloat16_as_ushort(a) | ((uint32_t)__bfloat16_as_ushort(b) << 16);
}
__device__ __forceinline__ void mma_bf16(float& d0, float& d1, float& d2, float& d3,
                                         uint32_t a0, uint32_t a1, uint32_t a2, uint32_t a3,
                                         uint32_t b0, uint32_t b1) {
    asm volatile(
        "mma.sync.aligned.m16n8k16.row.col.f32.bf16.bf16.f32 "
        "{%0,%1,%2,%3}, {%4,%5,%6,%7}, {%8,%9}, {%0,%1,%2,%3};"
        : "+f"(d0), "+f"(d1), "+f"(d2), "+f"(d3)
        : "r"(a0), "r"(a1), "r"(a2), "r"(a3), "r"(b0), "r"(b1));
}

// ==================== HMMA GEMM (bf16 hi/lo split, fp32 accum) ==========
// C[M,N] = A[M,K] @ B[K,N] + bias (+epilogue). CTA 128x128, BK=32.
// 256 threads = 8 warps (2m x 4n), warp tile 64x32.
// EPI: 0 = bias, 1 = gelu(bias+x), 2 = bias + residual

#define GPAD 34                // bf16 elems per padded row (32 used + 2 pad)
#define ROWB (GPAD*2)          // 68 bytes per row
#define AH_OFF 0
#define AL_OFF 8704
#define BH_OFF 17408
#define BL_OFF 26112
#define STAGE  34816
#define GEMM_SMEM (2*STAGE)    // 69632

template<int EPI>
__global__ __launch_bounds__(256)
void gemm_hmma(const float* __restrict__ A, const float* __restrict__ B,
               const float* __restrict__ bias, const float* __restrict__ res,
               float* __restrict__ C, int M, int N, int K)
{
    extern __shared__ char sm[];
    const uint32_t smb = smem_u32(sm);
    const int tid = threadIdx.x;
    const int m0 = blockIdx.y * 128, n0 = blockIdx.x * 128;

    const int wid = tid >> 5, lane = tid & 31;
    const int wm = wid >> 2, wn = wid & 3;      // warp grid 2x4
    const int g = lane >> 2, q = lane & 3;

    // global-load coordinates
    const int arow = tid >> 1;
    const int acol = (tid & 1) * 16;
    const int bn   = tid & 127;
    const int bks  = (tid >> 7) * 16;

    float acc[4][4][4];
#pragma unroll
    for (int i = 0; i < 4; i++)
#pragma unroll
        for (int j = 0; j < 4; j++)
#pragma unroll
            for (int t = 0; t < 4; t++) acc[i][j][t] = 0.f;

    // ---- load a k-stage into registers ----
    float4 av[4];
    float  bv[16];
    auto load_regs = [&](int k0) {
        const float* Ap = A + (size_t)(m0 + arow) * K + k0 + acol;
#pragma unroll
        for (int i = 0; i < 4; i++) av[i] = *(const float4*)(Ap + i * 4);
        const float* Bp = B + (size_t)(k0 + bks) * N + n0 + bn;
#pragma unroll
        for (int j = 0; j < 16; j++) bv[j] = Bp[(size_t)j * N];
    };
    // ---- convert + store registers to a smem stage ----
    auto store_regs = [&](uint32_t sb) {
#pragma unroll
        for (int i = 0; i < 4; i++) {
            float fx[4] = {av[i].x, av[i].y, av[i].z, av[i].w};
            __nv_bfloat16 h[4], l[4];
#pragma unroll
            for (int t = 0; t < 4; t++) {
                h[t] = __float2bfloat16_rn(fx[t]);
                l[t] = __float2bfloat16_rn(fx[t] - __bfloat162float(h[t]));
            }
            uint32_t ba = sb + (uint32_t)(arow * ROWB + (acol + i * 4) * 2);
            sts32(ba + AH_OFF,     pack2(h[0], h[1]));
            sts32(ba + AH_OFF + 4, pack2(h[2], h[3]));
            sts32(ba + AL_OFF,     pack2(l[0], l[1]));
            sts32(ba + AL_OFF + 4, pack2(l[2], l[3]));
        }
#pragma unroll
        for (int j = 0; j < 16; j += 2) {
            __nv_bfloat16 h0 = __float2bfloat16_rn(bv[j]);
            __nv_bfloat16 h1 = __float2bfloat16_rn(bv[j + 1]);
            __nv_bfloat16 l0 = __float2bfloat16_rn(bv[j]     - __bfloat162float(h0));
            __nv_bfloat16 l1 = __float2bfloat16_rn(bv[j + 1] - __bfloat162float(h1));
            uint32_t ba = sb + (uint32_t)(bn * ROWB + (bks + j) * 2);
            sts32(ba + BH_OFF, pack2(h0, h1));
            sts32(ba + BL_OFF, pack2(l0, l1));
        }
    };
    // ---- consume one smem stage (2x k16) ----
    auto compute_stage = [&](uint32_t sb) {
#pragma unroll
        for (int kk = 0; kk < 32; kk += 16) {
            uint32_t ah[4][4], al[4][4];
            const uint32_t cb = (uint32_t)((kk + q * 2) * 2);
#pragma unroll
            for (int mt = 0; mt < 4; mt++) {
                uint32_t r = sb + (uint32_t)((wm * 64 + mt * 16 + g) * ROWB) + cb;
                ah[mt][0] = lds32(r + AH_OFF);
                ah[mt][1] = lds32(r + AH_OFF + 8 * ROWB);
                ah[mt][2] = lds32(r + AH_OFF + 16);
                ah[mt][3] = lds32(r + AH_OFF + 8 * ROWB + 16);
                al[mt][0] = lds32(r + AL_OFF);
                al[mt][1] = lds32(r + AL_OFF + 8 * ROWB);
                al[mt][2] = lds32(r + AL_OFF + 16);
                al[mt][3] = lds32(r + AL_OFF + 8 * ROWB + 16);
            }
#pragma unroll
            for (int nt = 0; nt < 4; nt++) {
                uint32_t rb = sb + (uint32_t)((wn * 32 + nt * 8 + g) * ROWB) + cb;
                uint32_t bh0 = lds32(rb + BH_OFF), bh1 = lds32(rb + BH_OFF + 16);
                uint32_t bl0 = lds32(rb + BL_OFF), bl1 = lds32(rb + BL_OFF + 16);
#pragma unroll
                for (int mt = 0; mt < 4; mt++) {
                    mma_bf16(acc[mt][nt][0], acc[mt][nt][1], acc[mt][nt][2], acc[mt][nt][3],
                             ah[mt][0], ah[mt][1], ah[mt][2], ah[mt][3], bh0, bh1);
                    mma_bf16(acc[mt][nt][0], acc[mt][nt][1], acc[mt][nt][2], acc[mt][nt][3],
                             ah[mt][0], ah[mt][1], ah[mt][2], ah[mt][3], bl0, bl1);
                    mma_bf16(acc[mt][nt][0], acc[mt][nt][1], acc[mt][nt][2], acc[mt][nt][3],
                             al[mt][0], al[mt][1], al[mt][2], al[mt][3], bh0, bh1);
                }
            }
        }
    };

    // ---- main loop: double-buffered ----
    load_regs(0);
    store_regs(smb);
    __syncthreads();
    const int NC = K >> 5;
    for (int c = 0; c < NC; c++) {
        const uint32_t cur = smb + (uint32_t)((c & 1) * STAGE);
        if (c + 1 < NC) load_regs((c + 1) << 5);       // LDGs in flight
        compute_stage(cur);                            // hide LDG latency
        if (c + 1 < NC) store_regs(smb + (uint32_t)(((c + 1) & 1) * STAGE));
        __syncthreads();
    }

    // ---- epilogue ----
#pragma unroll
    for (int mt = 0; mt < 4; mt++) {
        const int r0 = m0 + wm * 64 + mt * 16 + g;
#pragma unroll
        for (int nt = 0; nt < 4; nt++) {
            const int col = n0 + wn * 32 + nt * 8 + q * 2;
            float b0 = bias[col], b1 = bias[col + 1];
#pragma unroll
            for (int h = 0; h < 2; h++) {
                const int row = r0 + h * 8;
                float v0 = acc[mt][nt][h * 2 + 0] + b0;
                float v1 = acc[mt][nt][h * 2 + 1] + b1;
                if (EPI == 1) {
                    v0 = 0.5f * v0 * (1.0f + erff(v0 * 0.70710678118654752440f));
                    v1 = 0.5f * v1 * (1.0f + erff(v1 * 0.70710678118654752440f));
                }
                if (EPI == 2) {
                    float2 r2 = *(const float2*)(res + (size_t)row * N + col);
                    v0 += r2.x; v1 += r2.y;
                }
                *(float2*)(C + (size_t)row * N + col) = make_float2(v0, v1);
            }
        }
    }
}

// ==================== attention ====================
// per CTA: (b, h, 64-row q tile). smem: Qs[d][q], KV[.][.], Sc[q][512], red
#define QS_OFF 0
#define KV_OFF (64*68)
#define SC_OFF (2*64*68)
#define RED_OFF (SC_OFF + 64*516)
#define ATTN_SMEM ((RED_OFF + 64*8) * 4)

__global__ __launch_bounds__(256)
void attn_kernel(const float* __restrict__ Q, const float* __restrict__ K,
                 const float* __restrict__ V, const float* __restrict__ mask,
                 float* __restrict__ O)
{
    extern __shared__ float sf[];
    float* Qs  = sf + QS_OFF;    // [64 d][68 pad] (transposed: [d][q])
    float* KV  = sf + KV_OFF;    // K: [d][k]; V: [k][d]
    float* Sc  = sf + SC_OFF;    // [64 q][516 pad]
    float* red = sf + RED_OFF;   // [64][8]

    const int qt = blockIdx.x, h = blockIdx.y, b = blockIdx.z;
    const int tid = threadIdx.x;
    const int q0 = qt * 64;
    const int base = (b * SS) * HH + h * HDIM;

    const int lr = tid >> 2;            // load row 0..63
    const int ld0 = (tid & 3) * 16;     // load col group

    // load Q tile transposed: Qs[d][q]
#pragma unroll
    for (int i = 0; i < 4; i++) {
        float4 v = *(const float4*)(Q + base + (q0 + lr) * HH + ld0 + i * 4);
        Qs[(ld0 + i * 4 + 0) * 68 + lr] = v.x;
        Qs[(ld0 + i * 4 + 1) * 68 + lr] = v.y;
        Qs[(ld0 + i * 4 + 2) * 68 + lr] = v.z;
        Qs[(ld0 + i * 4 + 3) * 68 + lr] = v.w;
    }

    const int tx = tid & 15;            // micro col group (k or d)
    const int ty = tid >> 4;            // micro row group (q)

    // ---- phase 1: scores ----
    for (int kt = 0; kt < SS; kt += 64) {
        // load K tile transposed: KV[d][k]
#pragma unroll
        for (int i = 0; i < 4; i++) {
            float4 v = *(const float4*)(K + base + (kt + lr) * HH + ld0 + i * 4);
            KV[(ld0 + i * 4 + 0) * 68 + lr] = v.x;
            KV[(ld0 + i * 4 + 1) * 68 + lr] = v.y;
            KV[(ld0 + i * 4 + 2) * 68 + lr] = v.z;
            KV[(ld0 + i * 4 + 3) * 68 + lr] = v.w;
        }
        __syncthreads();
        float a[4][4];
#pragma unroll
        for (int i = 0; i < 4; i++)
#pragma unroll
            for (int j = 0; j < 4; j++) a[i][j] = 0.f;
#pragma unroll 4
        for (int d = 0; d < 64; d++) {
            float4 qv = *(const float4*)(Qs + d * 68 + ty * 4);
            float4 kv = *(const float4*)(KV + d * 68 + tx * 4);
            const float qa[4] = {qv.x, qv.y, qv.z, qv.w};
            const float ka[4] = {kv.x, kv.y, kv.z, kv.w};
#pragma unroll
            for (int i = 0; i < 4; i++)
#pragma unroll
                for (int j = 0; j < 4; j++) a[i][j] += qa[i] * ka[j];
        }
#pragma unroll
        for (int j = 0; j < 4; j++) {
            const float mk = mask[b * SS + kt + tx * 4 + j];
#pragma unroll
            for (int i = 0; i < 4; i++)
                Sc[(ty * 4 + i) * 516 + kt + tx * 4 + j] = a[i][j] * 0.125f + mk;
        }
        __syncthreads();
    }

    // ---- phase 2: softmax (row = tid>>2, seg of 128 = tid&3) ----
    {
        const int row = tid >> 2, seg = tid & 3;
        float* Sr = Sc + row * 516 + seg * 128;
        float m = -1e30f;
#pragma unroll 8
        for (int j = 0; j < 128; j++) m = fmaxf(m, Sr[j]);
        red[row * 8 + seg] = m;
        __syncthreads();
        if (seg == 0) {
            float mm = fmaxf(fmaxf(red[row * 8], red[row * 8 + 1]),
                             fmaxf(red[row * 8 + 2], red[row * 8 + 3]));
            red[row * 8 + 4] = mm;
        }
        __syncthreads();
        const float rowmax = red[row * 8 + 4];
        float s = 0.f;
#pragma unroll 8
        for (int j = 0; j < 128; j++) {
            float e = __expf(Sr[j] - rowmax);
            Sr[j] = e;
            s += e;
        }
        __syncthreads();
        red[row * 8 + seg] = s;
        __syncthreads();
        if (seg == 0)
            red[row * 8 + 4] = red[row * 8] + red[row * 8 + 1] + red[row * 8 + 2] + red[row * 8 + 3];
        __syncthreads();
    }

    // ---- phase 3: ctx = P @ V ----
    float a2[4][4];
#pragma unroll
    for (int i = 0; i < 4; i++)
#pragma unroll
        for (int j = 0; j < 4; j++) a2[i][j] = 0.f;

    for (int vt = 0; vt < SS; vt += 64) {
        __syncthreads();
        // load V tile natural: KV[k][d]
#pragma unroll
        for (int i = 0; i < 4; i++) {
            float4 v = *(const float4*)(V + base + (vt + lr) * HH + ld0 + i * 4);
            *(float4*)(KV + lr * 68 + ld0 + i * 4) = v;
        }
        __syncthreads();
#pragma unroll 4
        for (int k = 0; k < 64; k++) {
            float4 vv = *(const float4*)(KV + k * 68 + tx * 4);
            const float va[4] = {vv.x, vv.y, vv.z, vv.w};
#pragma unroll
            for (int i = 0; i < 4; i++) {
                const float s = Sc[(ty * 4 + i) * 516 + vt + k];
#pragma unroll
                for (int j = 0; j < 4; j++) a2[i][j] += s * va[j];
            }
        }
    }
#pragma unroll
    for (int i = 0; i < 4; i++) {
        const int qi = ty * 4 + i;
        const float inv = 1.f / red[qi * 8 + 4];
        float4 o = make_float4(a2[i][0] * inv, a2[i][1] * inv, a2[i][2] * inv, a2[i][3] * inv);
        *(float4*)(O + base + (q0 + qi) * HH + tx * 4) = o;
    }
}

// ---------------- layernorm ----------------
__global__ __launch_bounds__(256)
void ln_kernel(const float* __restrict__ x, const float* __restrict__ g,
               const float* __restrict__ bt, float* __restrict__ y)
{
    const int row = blockIdx.x;
    const int tid = threadIdx.x;
    const float* xr = x + (size_t)row * HH;
    float v[4];
    float s = 0.f;
#pragma unroll
    for (int i = 0; i < 4; i++) { v[i] = xr[tid + i * 256]; s += v[i]; }

    __shared__ float smr[8];
    __shared__ float mu_s, var_s;
#pragma unroll
    for (int o = 16; o; o >>= 1) s += __shfl_xor_sync(0xffffffffu, s, o);
    if ((tid & 31) == 0) smr[tid >> 5] = s;
    __syncthreads();
    if (tid < 32) {
        float t = (tid < 8) ? smr[tid] : 0.f;
#pragma unroll
        for (int o = 4; o; o >>= 1) t += __shfl_xor_sync(0xffffffffu, t, o);
        if (tid == 0) mu_s = t * (1.f / HH);
    }
    __syncthreads();
    const float mu = mu_s;
    float s2 = 0.f;
#pragma unroll
    for (int i = 0; i < 4; i++) { float d = v[i] - mu; s2 += d * d; }
#pragma unroll
    for (int o = 16; o; o >>= 1) s2 += __shfl_xor_sync(0xffffffffu, s2, o);
    __syncthreads();
    if ((tid & 31) == 0) smr[tid >> 5] = s2;
    __syncthreads();
    if (tid < 32) {
        float t = (tid < 8) ? smr[tid] : 0.f;
#pragma unroll
        for (int o = 4; o; o >>= 1) t += __shfl_xor_sync(0xffffffffu, t, o);
        if (tid == 0) var_s = t * (1.f / HH);
    }
    __syncthreads();
    const float inv = rsqrtf(var_s + 1e-5f);
#pragma unroll
    for (int i = 0; i < 4; i++) {
        const int c = tid + i * 256;
        y[(size_t)row * HH + c] = (v[i] - mu) * inv * g[c] + bt[c];
    }
}

// ---------------- host ----------------
extern "C" void kernel_launch(void* const* d_in, const int* in_sizes, int n_in,
                              void* d_out, int out_size)
{
    (void)in_sizes; (void)n_in; (void)out_size;
    const float* x     = (const float*)d_in[0];
    const float* mask  = (const float*)d_in[1];
    const float* wq    = (const float*)d_in[2];
    const float* bq    = (const float*)d_in[3];
    const float* wk    = (const float*)d_in[4];
    const float* bk    = (const float*)d_in[5];
    const float* wv    = (const float*)d_in[6];
    const float* bv    = (const float*)d_in[7];
    const float* wo    = (const float*)d_in[8];
    const float* bo    = (const float*)d_in[9];
    const float* ln1g  = (const float*)d_in[10];
    const float* ln1b  = (const float*)d_in[11];
    const float* wi    = (const float*)d_in[12];
    const float* bi    = (const float*)d_in[13];
    const float* wo2   = (const float*)d_in[14];
    const float* bo2   = (const float*)d_in[15];
    const float* ln2g  = (const float*)d_in[16];
    const float* ln2b  = (const float*)d_in[17];
    float* out = (float*)d_out;

    float *q, *k, *v, *ctx, *t1, *attn, *inter, *t2;
    cudaGetSymbolAddress((void**)&q,     g_q);
    cudaGetSymbolAddress((void**)&k,     g_k);
    cudaGetSymbolAddress((void**)&v,     g_v);
    cudaGetSymbolAddress((void**)&ctx,   g_ctx);
    cudaGetSymbolAddress((void**)&t1,    g_t1);
    cudaGetSymbolAddress((void**)&attn,  g_attn);
    cudaGetSymbolAddress((void**)&inter, g_inter);
    cudaGetSymbolAddress((void**)&t2,    g_t2);

    cudaFuncSetAttribute(gemm_hmma<0>, cudaFuncAttributeMaxDynamicSharedMemorySize, GEMM_SMEM);
    cudaFuncSetAttribute(gemm_hmma<1>, cudaFuncAttributeMaxDynamicSharedMemorySize, GEMM_SMEM);
    cudaFuncSetAttribute(gemm_hmma<2>, cudaFuncAttributeMaxDynamicSharedMemorySize, GEMM_SMEM);
    cudaFuncSetAttribute(attn_kernel,  cudaFuncAttributeMaxDynamicSharedMemorySize, ATTN_SMEM);

    const dim3 blkG(256);
    const dim3 gH(HH / 128, MTOK / 128);     // N=1024
    const dim3 gF(FFD / 128, MTOK / 128);    // N=4096

    // QKV projections
    gemm_hmma<0><<<gH, blkG, GEMM_SMEM>>>(x, wq, bq, nullptr, q, MTOK, HH, HH);
    gemm_hmma<0><<<gH, blkG, GEMM_SMEM>>>(x, wk, bk, nullptr, k, MTOK, HH, HH);
    gemm_hmma<0><<<gH, blkG, GEMM_SMEM>>>(x, wv, bv, nullptr, v, MTOK, HH, HH);

    // attention
    attn_kernel<<<dim3(SS / 64, NHEAD, BB), dim3(256), ATTN_SMEM>>>(q, k, v, mask, ctx);

    // output proj + residual, LN1
    gemm_hmma<2><<<gH, blkG, GEMM_SMEM>>>(ctx, wo, bo, x, t1, MTOK, HH, HH);
    ln_kernel<<<MTOK, dim3(256)>>>(t1, ln1g, ln1b, attn);

    // FFN
    gemm_hmma<1><<<gF, blkG, GEMM_SMEM>>>(attn, wi, bi, nullptr, inter, MTOK, FFD, HH);
    gemm_hmma<2><<<gH, blkG, GEMM_SMEM>>>(inter, wo2, bo2, attn, t2, MTOK, HH, FFD);
    ln_kernel<<<MTOK, dim3(256)>>>(t2, ln2g, ln2b, out);
}

// round 4
// speedup vs baseline: 1.8962x; 1.1058x over previous
#include <cuda_runtime.h>
#include <cuda_fp16.h>
#include <cstdint>
#include <math.h>

#define BB 8
#define SS 512
#define HH 1024
#define NHEAD 16
#define HDIM 64
#define FFD 4096
#define MTOK (BB*SS)   // 4096 tokens

// ---------------- scratch (static __device__, no allocs) ----------------
__device__ float g_q[MTOK*HH];
__device__ float g_k[MTOK*HH];
__device__ float g_v[MTOK*HH];
__device__ float g_ctx[MTOK*HH];
__device__ float g_t1[MTOK*HH];
__device__ float g_attn[MTOK*HH];
__device__ float g_inter[(size_t)MTOK*FFD];
__device__ float g_t2[MTOK*HH];

// ==================== helpers ====================
__device__ __forceinline__ uint32_t smem_u32(const void* p) {
    uint32_t a;
    asm("{ .reg .u64 t; cvta.to.shared.u64 t, %1; cvt.u32.u64 %0, t; }" : "=r"(a) : "l"(p));
    return a;
}
__device__ __forceinline__ uint32_t lds32(uint32_t a) {
    uint32_t v; asm volatile("ld.shared.b32 %0, [%1];" : "=r"(v) : "r"(a)); return v;
}
__device__ __forceinline__ void sts32(uint32_t a, uint32_t v) {
    asm volatile("st.shared.b32 [%0], %1;" :: "r"(a), "r"(v));
}
__device__ __forceinline__ uint32_t pack2h(__half a, __half b) {
    return (uint32_t)__half_as_ushort(a) | ((uint32_t)__half_as_ushort(b) << 16);
}
__device__ __forceinline__ void mma_f16(float& d0, float& d1, float& d2, float& d3,
                                        uint32_t a0, uint32_t a1, uint32_t a2, uint32_t a3,
                                        uint32_t b0, uint32_t b1) {
    asm volatile(
        "mma.sync.aligned.m16n8k16.row.col.f32.f16.f16.f32 "
        "{%0,%1,%2,%3}, {%4,%5,%6,%7}, {%8,%9}, {%0,%1,%2,%3};"
        : "+f"(d0), "+f"(d1), "+f"(d2), "+f"(d3)
        : "r"(a0), "r"(a1), "r"(a2), "r"(a3), "r"(b0), "r"(b1));
}

// ==================== HMMA GEMM (fp16 2-term split, fp32 accum) =========
// C[M,N] = A[M,K] @ B[K,N] + bias (+epilogue). CTA 128x128, BK=32.
// A split into fp16 hi+lo (exact to ~2^-22); B rounded once to fp16.
// D = (Ah + Al) * Bh : 2 MMAs per k16 slice.
// EPI: 0 = bias, 1 = gelu(bias+x), 2 = bias + residual

#define GPAD 34                // fp16 elems per padded row (32 used + 2 pad)
#define ROWB (GPAD*2)          // 68 bytes per row
#define AH_OFF 0
#define AL_OFF 8704
#define BH_OFF 17408
#define STAGE  26112
#define GEMM_SMEM (2*STAGE)    // 52224

template<int EPI>
__global__ __launch_bounds__(256)
void gemm_hmma(const float* __restrict__ A, const float* __restrict__ B,
               const float* __restrict__ bias, const float* __restrict__ res,
               float* __restrict__ C, int M, int N, int K)
{
    extern __shared__ char sm[];
    const uint32_t smb = smem_u32(sm);
    const int tid = threadIdx.x;
    const int m0 = blockIdx.y * 128, n0 = blockIdx.x * 128;

    const int wid = tid >> 5, lane = tid & 31;
    const int wm = wid >> 2, wn = wid & 3;      // warp grid 2x4
    const int g = lane >> 2, q = lane & 3;

    // global-load coordinates
    const int arow = tid >> 1;
    const int acol = (tid & 1) * 16;
    const int bn   = tid & 127;
    const int bks  = (tid >> 7) * 16;

    float acc[4][4][4];
#pragma unroll
    for (int i = 0; i < 4; i++)
#pragma unroll
        for (int j = 0; j < 4; j++)
#pragma unroll
            for (int t = 0; t < 4; t++) acc[i][j][t] = 0.f;

    // ---- load a k-stage into registers ----
    float4 av[4];
    float  bv[16];
    auto load_regs = [&](int k0) {
        const float* Ap = A + (size_t)(m0 + arow) * K + k0 + acol;
#pragma unroll
        for (int i = 0; i < 4; i++) av[i] = *(const float4*)(Ap + i * 4);
        const float* Bp = B + (size_t)(k0 + bks) * N + n0 + bn;
#pragma unroll
        for (int j = 0; j < 16; j++) bv[j] = Bp[(size_t)j * N];
    };
    // ---- convert + store registers to a smem stage ----
    auto store_regs = [&](uint32_t sb) {
#pragma unroll
        for (int i = 0; i < 4; i++) {
            float fx[4] = {av[i].x, av[i].y, av[i].z, av[i].w};
            __half h[4], l[4];
#pragma unroll
            for (int t = 0; t < 4; t++) {
                h[t] = __float2half_rn(fx[t]);
                l[t] = __float2half_rn(fx[t] - __half2float(h[t]));
            }
            uint32_t ba = sb + (uint32_t)(arow * ROWB + (acol + i * 4) * 2);
            sts32(ba + AH_OFF,     pack2h(h[0], h[1]));
            sts32(ba + AH_OFF + 4, pack2h(h[2], h[3]));
            sts32(ba + AL_OFF,     pack2h(l[0], l[1]));
            sts32(ba + AL_OFF + 4, pack2h(l[2], l[3]));
        }
#pragma unroll
        for (int j = 0; j < 16; j += 2) {
            __half h0 = __float2half_rn(bv[j]);
            __half h1 = __float2half_rn(bv[j + 1]);
            uint32_t ba = sb + (uint32_t)(bn * ROWB + (bks + j) * 2);
            sts32(ba + BH_OFF, pack2h(h0, h1));
        }
    };
    // ---- consume one smem stage (2x k16) ----
    auto compute_stage = [&](uint32_t sb) {
#pragma unroll
        for (int kk = 0; kk < 32; kk += 16) {
            uint32_t ah[4][4], al[4][4];
            const uint32_t cb = (uint32_t)((kk + q * 2) * 2);
#pragma unroll
            for (int mt = 0; mt < 4; mt++) {
                uint32_t r = sb + (uint32_t)((wm * 64 + mt * 16 + g) * ROWB) + cb;
                ah[mt][0] = lds32(r + AH_OFF);
                ah[mt][1] = lds32(r + AH_OFF + 8 * ROWB);
                ah[mt][2] = lds32(r + AH_OFF + 16);
                ah[mt][3] = lds32(r + AH_OFF + 8 * ROWB + 16);
                al[mt][0] = lds32(r + AL_OFF);
                al[mt][1] = lds32(r + AL_OFF + 8 * ROWB);
                al[mt][2] = lds32(r + AL_OFF + 16);
                al[mt][3] = lds32(r + AL_OFF + 8 * ROWB + 16);
            }
#pragma unroll
            for (int nt = 0; nt < 4; nt++) {
                uint32_t rb = sb + (uint32_t)((wn * 32 + nt * 8 + g) * ROWB) + cb;
                uint32_t bh0 = lds32(rb + BH_OFF), bh1 = lds32(rb + BH_OFF + 16);
#pragma unroll
                for (int mt = 0; mt < 4; mt++) {
                    mma_f16(acc[mt][nt][0], acc[mt][nt][1], acc[mt][nt][2], acc[mt][nt][3],
                            ah[mt][0], ah[mt][1], ah[mt][2], ah[mt][3], bh0, bh1);
                    mma_f16(acc[mt][nt][0], acc[mt][nt][1], acc[mt][nt][2], acc[mt][nt][3],
                            al[mt][0], al[mt][1], al[mt][2], al[mt][3], bh0, bh1);
                }
            }
        }
    };

    // ---- main loop: double-buffered ----
    load_regs(0);
    store_regs(smb);
    __syncthreads();
    const int NC = K >> 5;
    for (int c = 0; c < NC; c++) {
        const uint32_t cur = smb + (uint32_t)((c & 1) * STAGE);
        if (c + 1 < NC) load_regs((c + 1) << 5);       // LDGs in flight
        compute_stage(cur);                            // hide LDG latency
        if (c + 1 < NC) store_regs(smb + (uint32_t)(((c + 1) & 1) * STAGE));
        __syncthreads();
    }

    // ---- epilogue ----
#pragma unroll
    for (int mt = 0; mt < 4; mt++) {
        const int r0 = m0 + wm * 64 + mt * 16 + g;
#pragma unroll
        for (int nt = 0; nt < 4; nt++) {
            const int col = n0 + wn * 32 + nt * 8 + q * 2;
            float b0 = bias[col], b1 = bias[col + 1];
#pragma unroll
            for (int h = 0; h < 2; h++) {
                const int row = r0 + h * 8;
                float v0 = acc[mt][nt][h * 2 + 0] + b0;
                float v1 = acc[mt][nt][h * 2 + 1] + b1;
                if (EPI == 1) {
                    v0 = 0.5f * v0 * (1.0f + erff(v0 * 0.70710678118654752440f));
                    v1 = 0.5f * v1 * (1.0f + erff(v1 * 0.70710678118654752440f));
                }
                if (EPI == 2) {
                    float2 r2 = *(const float2*)(res + (size_t)row * N + col);
                    v0 += r2.x; v1 += r2.y;
                }
                *(float2*)(C + (size_t)row * N + col) = make_float2(v0, v1);
            }
        }
    }
}

// ==================== attention ====================
// per CTA: (b, h, 32-row q tile). smem ~93.8 KB -> 2 CTAs/SM.
#define QT 32
#define QS_OFF 0                         // Qs[d][36]  (transposed [d][q])
#define KV_OFF 2304                      // KV: K as [d][68]; V as [k][68]
#define SC_OFF 6656                      // Sc[32][516]
#define RED_OFF 23168                    // red[32][9]
#define ATTN_SMEM ((RED_OFF + 32*9) * 4)

__global__ __launch_bounds__(256)
void attn_kernel(const float* __restrict__ Q, const float* __restrict__ K,
                 const float* __restrict__ V, const float* __restrict__ mask,
                 float* __restrict__ O)
{
    extern __shared__ float sf[];
    float* Qs  = sf + QS_OFF;
    float* KV  = sf + KV_OFF;
    float* Sc  = sf + SC_OFF;
    float* red = sf + RED_OFF;

    const int qt = blockIdx.x, h = blockIdx.y, b = blockIdx.z;
    const int tid = threadIdx.x;
    const int q0 = qt * QT;
    const int base = (b * SS) * HH + h * HDIM;

    // Q tile load (transposed): 32 rows x 64 cols
    {
        const int qr = tid >> 3;           // 0..31
        const int qc0 = (tid & 7) * 8;     // 0..56
#pragma unroll
        for (int i = 0; i < 2; i++) {
            float4 v = *(const float4*)(Q + base + (q0 + qr) * HH + qc0 + i * 4);
            Qs[(qc0 + i * 4 + 0) * 36 + qr] = v.x;
            Qs[(qc0 + i * 4 + 1) * 36 + qr] = v.y;
            Qs[(qc0 + i * 4 + 2) * 36 + qr] = v.z;
            Qs[(qc0 + i * 4 + 3) * 36 + qr] = v.w;
        }
    }

    const int lr = tid >> 2;            // KV load row 0..63
    const int ld0 = (tid & 3) * 16;
    const int tx = tid & 15;            // micro col group (k or d): 4 cols
    const int ty = tid >> 4;            // micro row group: 2 q rows

    // ---- phase 1: scores ----
    for (int kt = 0; kt < SS; kt += 64) {
        // K tile transposed: KV[d][k]
#pragma unroll
        for (int i = 0; i < 4; i++) {
            float4 v = *(const float4*)(K + base + (kt + lr) * HH + ld0 + i * 4);
            KV[(ld0 + i * 4 + 0) * 68 + lr] = v.x;
            KV[(ld0 + i * 4 + 1) * 68 + lr] = v.y;
            KV[(ld0 + i * 4 + 2) * 68 + lr] = v.z;
            KV[(ld0 + i * 4 + 3) * 68 + lr] = v.w;
        }
        __syncthreads();
        float a[2][4];
#pragma unroll
        for (int i = 0; i < 2; i++)
#pragma unroll
            for (int j = 0; j < 4; j++) a[i][j] = 0.f;
#pragma unroll 4
        for (int d = 0; d < 64; d++) {
            float2 qv = *(const float2*)(Qs + d * 36 + ty * 2);
            float4 kv = *(const float4*)(KV + d * 68 + tx * 4);
            const float qa[2] = {qv.x, qv.y};
            const float ka[4] = {kv.x, kv.y, kv.z, kv.w};
#pragma unroll
            for (int i = 0; i < 2; i++)
#pragma unroll
                for (int j = 0; j < 4; j++) a[i][j] += qa[i] * ka[j];
        }
#pragma unroll
        for (int j = 0; j < 4; j++) {
            const float mk = mask[b * SS + kt + tx * 4 + j];
#pragma unroll
            for (int i = 0; i < 2; i++)
                Sc[(ty * 2 + i) * 516 + kt + tx * 4 + j] = a[i][j] * 0.125f + mk;
        }
        __syncthreads();
    }

    // ---- phase 2: softmax (row = tid>>3, seg of 64 = tid&7) ----
    {
        const int row = tid >> 3, seg = tid & 7;
        float* Sr = Sc + row * 516 + seg * 64;
        float m = -1e30f;
#pragma unroll 8
        for (int j = 0; j < 64; j++) m = fmaxf(m, Sr[j]);
        red[row * 9 + seg] = m;
        __syncthreads();
        if (seg == 0) {
            float mm = -1e30f;
#pragma unroll
            for (int j = 0; j < 8; j++) mm = fmaxf(mm, red[row * 9 + j]);
            red[row * 9 + 8] = mm;
        }
        __syncthreads();
        const float rowmax = red[row * 9 + 8];
        float s = 0.f;
#pragma unroll 8
        for (int j = 0; j < 64; j++) {
            float e = __expf(Sr[j] - rowmax);
            Sr[j] = e;
            s += e;
        }
        __syncthreads();
        red[row * 9 + seg] = s;
        __syncthreads();
        if (seg == 0) {
            float tt = 0.f;
#pragma unroll
            for (int j = 0; j < 8; j++) tt += red[row * 9 + j];
            red[row * 9 + 8] = tt;
        }
        __syncthreads();
    }

    // ---- phase 3: ctx = P @ V ----
    float a2[2][4];
#pragma unroll
    for (int i = 0; i < 2; i++)
#pragma unroll
        for (int j = 0; j < 4; j++) a2[i][j] = 0.f;

    for (int vt = 0; vt < SS; vt += 64) {
        __syncthreads();
        // V tile natural: KV[k][d]
#pragma unroll
        for (int i = 0; i < 4; i++) {
            float4 v = *(const float4*)(V + base + (vt + lr) * HH + ld0 + i * 4);
            *(float4*)(KV + lr * 68 + ld0 + i * 4) = v;
        }
        __syncthreads();
#pragma unroll 4
        for (int k = 0; k < 64; k++) {
            float4 vv = *(const float4*)(KV + k * 68 + tx * 4);
            const float va[4] = {vv.x, vv.y, vv.z, vv.w};
#pragma unroll
            for (int i = 0; i < 2; i++) {
                const float s = Sc[(ty * 2 + i) * 516 + vt + k];
#pragma unroll
                for (int j = 0; j < 4; j++) a2[i][j] += s * va[j];
            }
        }
    }
#pragma unroll
    for (int i = 0; i < 2; i++) {
        const int qi = ty * 2 + i;
        const float inv = 1.f / red[qi * 9 + 8];
        float4 o = make_float4(a2[i][0] * inv, a2[i][1] * inv, a2[i][2] * inv, a2[i][3] * inv);
        *(float4*)(O + base + (q0 + qi) * HH + tx * 4) = o;
    }
}

// ---------------- layernorm ----------------
__global__ __launch_bounds__(256)
void ln_kernel(const float* __restrict__ x, const float* __restrict__ g,
               const float* __restrict__ bt, float* __restrict__ y)
{
    const int row = blockIdx.x;
    const int tid = threadIdx.x;
    const float* xr = x + (size_t)row * HH;
    float v[4];
    float s = 0.f;
#pragma unroll
    for (int i = 0; i < 4; i++) { v[i] = xr[tid + i * 256]; s += v[i]; }

    __shared__ float smr[8];
    __shared__ float mu_s, var_s;
#pragma unroll
    for (int o = 16; o; o >>= 1) s += __shfl_xor_sync(0xffffffffu, s, o);
    if ((tid & 31) == 0) smr[tid >> 5] = s;
    __syncthreads();
    if (tid < 32) {
        float t = (tid < 8) ? smr[tid] : 0.f;
#pragma unroll
        for (int o = 4; o; o >>= 1) t += __shfl_xor_sync(0xffffffffu, t, o);
        if (tid == 0) mu_s = t * (1.f / HH);
    }
    __syncthreads();
    const float mu = mu_s;
    float s2 = 0.f;
#pragma unroll
    for (int i = 0; i < 4; i++) { float d = v[i] - mu; s2 += d * d; }
#pragma unroll
    for (int o = 16; o; o >>= 1) s2 += __shfl_xor_sync(0xffffffffu, s2, o);
    __syncthreads();
    if ((tid & 31) == 0) smr[tid >> 5] = s2;
    __syncthreads();
    if (tid < 32) {
        float t = (tid < 8) ? smr[tid] : 0.f;
#pragma unroll
        for (int o = 4; o; o >>= 1) t += __shfl_xor_sync(0xffffffffu, t, o);
        if (tid == 0) var_s = t * (1.f / HH);
    }
    __syncthreads();
    const float inv = rsqrtf(var_s + 1e-5f);
#pragma unroll
    for (int i = 0; i < 4; i++) {
        const int c = tid + i * 256;
        y[(size_t)row * HH + c] = (v[i] - mu) * inv * g[c] + bt[c];
    }
}

// ---------------- host ----------------
extern "C" void kernel_launch(void* const* d_in, const int* in_sizes, int n_in,
                              void* d_out, int out_size)
{
    (void)in_sizes; (void)n_in; (void)out_size;
    const float* x     = (const float*)d_in[0];
    const float* mask  = (const float*)d_in[1];
    const float* wq    = (const float*)d_in[2];
    const float* bq    = (const float*)d_in[3];
    const float* wk    = (const float*)d_in[4];
    const float* bk    = (const float*)d_in[5];
    const float* wv    = (const float*)d_in[6];
    const float* bv    = (const float*)d_in[7];
    const float* wo    = (const float*)d_in[8];
    const float* bo    = (const float*)d_in[9];
    const float* ln1g  = (const float*)d_in[10];
    const float* ln1b  = (const float*)d_in[11];
    const float* wi    = (const float*)d_in[12];
    const float* bi    = (const float*)d_in[13];
    const float* wo2   = (const float*)d_in[14];
    const float* bo2   = (const float*)d_in[15];
    const float* ln2g  = (const float*)d_in[16];
    const float* ln2b  = (const float*)d_in[17];
    float* out = (float*)d_out;

    float *q, *k, *v, *ctx, *t1, *attn, *inter, *t2;
    cudaGetSymbolAddress((void**)&q,     g_q);
    cudaGetSymbolAddress((void**)&k,     g_k);
    cudaGetSymbolAddress((void**)&v,     g_v);
    cudaGetSymbolAddress((void**)&ctx,   g_ctx);
    cudaGetSymbolAddress((void**)&t1,    g_t1);
    cudaGetSymbolAddress((void**)&attn,  g_attn);
    cudaGetSymbolAddress((void**)&inter, g_inter);
    cudaGetSymbolAddress((void**)&t2,    g_t2);

    cudaFuncSetAttribute(gemm_hmma<0>, cudaFuncAttributeMaxDynamicSharedMemorySize, GEMM_SMEM);
    cudaFuncSetAttribute(gemm_hmma<1>, cudaFuncAttributeMaxDynamicSharedMemorySize, GEMM_SMEM);
    cudaFuncSetAttribute(gemm_hmma<2>, cudaFuncAttributeMaxDynamicSharedMemorySize, GEMM_SMEM);
    cudaFuncSetAttribute(attn_kernel,  cudaFuncAttributeMaxDynamicSharedMemorySize, ATTN_SMEM);

    const dim3 blkG(256);
    const dim3 gH(HH / 128, MTOK / 128);     // N=1024
    const dim3 gF(FFD / 128, MTOK / 128);    // N=4096

    // QKV projections
    gemm_hmma<0><<<gH, blkG, GEMM_SMEM>>>(x, wq, bq, nullptr, q, MTOK, HH, HH);
    gemm_hmma<0><<<gH, blkG, GEMM_SMEM>>>(x, wk, bk, nullptr, k, MTOK, HH, HH);
    gemm_hmma<0><<<gH, blkG, GEMM_SMEM>>>(x, wv, bv, nullptr, v, MTOK, HH, HH);

    // attention
    attn_kernel<<<dim3(SS / QT, NHEAD, BB), dim3(256), ATTN_SMEM>>>(q, k, v, mask, ctx);

    // output proj + residual, LN1
    gemm_hmma<2><<<gH, blkG, GEMM_SMEM>>>(ctx, wo, bo, x, t1, MTOK, HH, HH);
    ln_kernel<<<MTOK, dim3(256)>>>(t1, ln1g, ln1b, attn);

    // FFN
    gemm_hmma<1><<<gF, blkG, GEMM_SMEM>>>(attn, wi, bi, nullptr, inter, MTOK, FFD, HH);
    gemm_hmma<2><<<gH, blkG, GEMM_SMEM>>>(inter, wo2, bo2, attn, t2, MTOK, HH, FFD);
    ln_kernel<<<MTOK, dim3(256)>>>(t2, ln2g, ln2b, out);
}

// round 5
// speedup vs baseline: 2.3594x; 1.2443x over previous
#include <cuda_runtime.h>
#include <cuda_fp16.h>
#include <cstdint>
#include <math.h>

#define BB 8
#define SS 512
#define HH 1024
#define NHEAD 16
#define HDIM 64
#define FFD 4096
#define MTOK (BB*SS)   // 4096 tokens

// ---------------- scratch (static __device__, no allocs) ----------------
__device__ float g_q[MTOK*HH];
__device__ float g_k[MTOK*HH];
__device__ float g_v[MTOK*HH];
__device__ float g_ctx[MTOK*HH];
__device__ float g_t1[MTOK*HH];
__device__ float g_attn[MTOK*HH];
__device__ float g_inter[(size_t)MTOK*FFD];
__device__ float g_t2[MTOK*HH];

// ==================== helpers ====================
__device__ __forceinline__ uint32_t smem_u32(const void* p) {
    uint32_t a;
    asm("{ .reg .u64 t; cvta.to.shared.u64 t, %1; cvt.u32.u64 %0, t; }" : "=r"(a) : "l"(p));
    return a;
}
__device__ __forceinline__ uint32_t lds32(uint32_t a) {
    uint32_t v; asm volatile("ld.shared.b32 %0, [%1];" : "=r"(v) : "r"(a)); return v;
}
__device__ __forceinline__ void sts32(uint32_t a, uint32_t v) {
    asm volatile("st.shared.b32 [%0], %1;" :: "r"(a), "r"(v));
}
__device__ __forceinline__ uint32_t pack2h(__half a, __half b) {
    return (uint32_t)__half_as_ushort(a) | ((uint32_t)__half_as_ushort(b) << 16);
}
__device__ __forceinline__ void mma_f16(float& d0, float& d1, float& d2, float& d3,
                                        uint32_t a0, uint32_t a1, uint32_t a2, uint32_t a3,
                                        uint32_t b0, uint32_t b1) {
    asm volatile(
        "mma.sync.aligned.m16n8k16.row.col.f32.f16.f16.f32 "
        "{%0,%1,%2,%3}, {%4,%5,%6,%7}, {%8,%9}, {%0,%1,%2,%3};"
        : "+f"(d0), "+f"(d1), "+f"(d2), "+f"(d3)
        : "r"(a0), "r"(a1), "r"(a2), "r"(a3), "r"(b0), "r"(b1));
}
__device__ __forceinline__ void ldsm_x4(uint32_t& r0, uint32_t& r1, uint32_t& r2, uint32_t& r3, uint32_t a) {
    asm volatile("ldmatrix.sync.aligned.m8n8.x4.shared.b16 {%0,%1,%2,%3}, [%4];"
        : "=r"(r0), "=r"(r1), "=r"(r2), "=r"(r3) : "r"(a));
}
__device__ __forceinline__ void ldsm_x4_t(uint32_t& r0, uint32_t& r1, uint32_t& r2, uint32_t& r3, uint32_t a) {
    asm volatile("ldmatrix.sync.aligned.m8n8.x4.trans.shared.b16 {%0,%1,%2,%3}, [%4];"
        : "=r"(r0), "=r"(r1), "=r"(r2), "=r"(r3) : "r"(a));
}

// ==================== HMMA GEMM (fp16 2-term split, fp32 accum) =========
#define GPAD 34
#define ROWB (GPAD*2)
#define AH_OFF 0
#define AL_OFF 8704
#define BH_OFF 17408
#define STAGE  26112
#define GEMM_SMEM (2*STAGE)

template<int EPI>
__global__ __launch_bounds__(256)
void gemm_hmma(const float* __restrict__ A, const float* __restrict__ B,
               const float* __restrict__ bias, const float* __restrict__ res,
               float* __restrict__ C, int M, int N, int K)
{
    extern __shared__ char sm[];
    const uint32_t smb = smem_u32(sm);
    const int tid = threadIdx.x;
    const int m0 = blockIdx.y * 128, n0 = blockIdx.x * 128;

    const int wid = tid >> 5, lane = tid & 31;
    const int wm = wid >> 2, wn = wid & 3;
    const int g = lane >> 2, q = lane & 3;

    const int arow = tid >> 1;
    const int acol = (tid & 1) * 16;
    const int bn   = tid & 127;
    const int bks  = (tid >> 7) * 16;

    float acc[4][4][4];
#pragma unroll
    for (int i = 0; i < 4; i++)
#pragma unroll
        for (int j = 0; j < 4; j++)
#pragma unroll
            for (int t = 0; t < 4; t++) acc[i][j][t] = 0.f;

    float4 av[4];
    float  bv[16];
    auto load_regs = [&](int k0) {
        const float* Ap = A + (size_t)(m0 + arow) * K + k0 + acol;
#pragma unroll
        for (int i = 0; i < 4; i++) av[i] = *(const float4*)(Ap + i * 4);
        const float* Bp = B + (size_t)(k0 + bks) * N + n0 + bn;
#pragma unroll
        for (int j = 0; j < 16; j++) bv[j] = Bp[(size_t)j * N];
    };
    auto store_regs = [&](uint32_t sb) {
#pragma unroll
        for (int i = 0; i < 4; i++) {
            float fx[4] = {av[i].x, av[i].y, av[i].z, av[i].w};
            __half h[4], l[4];
#pragma unroll
            for (int t = 0; t < 4; t++) {
                h[t] = __float2half_rn(fx[t]);
                l[t] = __float2half_rn(fx[t] - __half2float(h[t]));
            }
            uint32_t ba = sb + (uint32_t)(arow * ROWB + (acol + i * 4) * 2);
            sts32(ba + AH_OFF,     pack2h(h[0], h[1]));
            sts32(ba + AH_OFF + 4, pack2h(h[2], h[3]));
            sts32(ba + AL_OFF,     pack2h(l[0], l[1]));
            sts32(ba + AL_OFF + 4, pack2h(l[2], l[3]));
        }
#pragma unroll
        for (int j = 0; j < 16; j += 2) {
            __half h0 = __float2half_rn(bv[j]);
            __half h1 = __float2half_rn(bv[j + 1]);
            uint32_t ba = sb + (uint32_t)(bn * ROWB + (bks + j) * 2);
            sts32(ba + BH_OFF, pack2h(h0, h1));
        }
    };
    auto compute_stage = [&](uint32_t sb) {
#pragma unroll
        for (int kk = 0; kk < 32; kk += 16) {
            uint32_t ah[4][4], al[4][4];
            const uint32_t cb = (uint32_t)((kk + q * 2) * 2);
#pragma unroll
            for (int mt = 0; mt < 4; mt++) {
                uint32_t r = sb + (uint32_t)((wm * 64 + mt * 16 + g) * ROWB) + cb;
                ah[mt][0] = lds32(r + AH_OFF);
                ah[mt][1] = lds32(r + AH_OFF + 8 * ROWB);
                ah[mt][2] = lds32(r + AH_OFF + 16);
                ah[mt][3] = lds32(r + AH_OFF + 8 * ROWB + 16);
                al[mt][0] = lds32(r + AL_OFF);
                al[mt][1] = lds32(r + AL_OFF + 8 * ROWB);
                al[mt][2] = lds32(r + AL_OFF + 16);
                al[mt][3] = lds32(r + AL_OFF + 8 * ROWB + 16);
            }
#pragma unroll
            for (int nt = 0; nt < 4; nt++) {
                uint32_t rb = sb + (uint32_t)((wn * 32 + nt * 8 + g) * ROWB) + cb;
                uint32_t bh0 = lds32(rb + BH_OFF), bh1 = lds32(rb + BH_OFF + 16);
#pragma unroll
                for (int mt = 0; mt < 4; mt++) {
                    mma_f16(acc[mt][nt][0], acc[mt][nt][1], acc[mt][nt][2], acc[mt][nt][3],
                            ah[mt][0], ah[mt][1], ah[mt][2], ah[mt][3], bh0, bh1);
                    mma_f16(acc[mt][nt][0], acc[mt][nt][1], acc[mt][nt][2], acc[mt][nt][3],
                            al[mt][0], al[mt][1], al[mt][2], al[mt][3], bh0, bh1);
                }
            }
        }
    };

    load_regs(0);
    store_regs(smb);
    __syncthreads();
    const int NC = K >> 5;
    for (int c = 0; c < NC; c++) {
        const uint32_t cur = smb + (uint32_t)((c & 1) * STAGE);
        if (c + 1 < NC) load_regs((c + 1) << 5);
        compute_stage(cur);
        if (c + 1 < NC) store_regs(smb + (uint32_t)(((c + 1) & 1) * STAGE));
        __syncthreads();
    }

#pragma unroll
    for (int mt = 0; mt < 4; mt++) {
        const int r0 = m0 + wm * 64 + mt * 16 + g;
#pragma unroll
        for (int nt = 0; nt < 4; nt++) {
            const int col = n0 + wn * 32 + nt * 8 + q * 2;
            float b0 = bias[col], b1 = bias[col + 1];
#pragma unroll
            for (int h = 0; h < 2; h++) {
                const int row = r0 + h * 8;
                float v0 = acc[mt][nt][h * 2 + 0] + b0;
                float v1 = acc[mt][nt][h * 2 + 1] + b1;
                if (EPI == 1) {
                    v0 = 0.5f * v0 * (1.0f + erff(v0 * 0.70710678118654752440f));
                    v1 = 0.5f * v1 * (1.0f + erff(v1 * 0.70710678118654752440f));
                }
                if (EPI == 2) {
                    float2 r2 = *(const float2*)(res + (size_t)row * N + col);
                    v0 += r2.x; v1 += r2.y;
                }
                *(float2*)(C + (size_t)row * N + col) = make_float2(v0, v1);
            }
        }
    }
}

// ==================== flash attention (HMMA, online softmax) ============
// CTA: (b, h, 64 q rows); 4 warps x 16 q rows. kv tiles of 64.
#define APAD 72    // halfs per smem row (64 + 8)

__global__ __launch_bounds__(128)
void attn_kernel(const float* __restrict__ Q, const float* __restrict__ K,
                 const float* __restrict__ V, const float* __restrict__ mask,
                 float* __restrict__ O)
{
    __shared__ __align__(16) __half Qh[64*APAD];
    __shared__ __align__(16) __half Ql[64*APAD];
    __shared__ __align__(16) __half Ksm[64*APAD];
    __shared__ __align__(16) __half Vh[64*APAD];
    __shared__ __align__(16) __half Vl[64*APAD];
    __shared__ float msk[64];

    const int qt = blockIdx.x, h = blockIdx.y, b = blockIdx.z;
    const int tid = threadIdx.x;
    const int wid = tid >> 5, lane = tid & 31;
    const int g = lane >> 2, t4 = lane & 3;
    const int q0 = qt * 64;
    const int base = (b * SS) * HH + h * HDIM;
    const int w16 = wid * 16;

    // ---- stage Q (hi/lo split) ----
    {
        const int r = tid >> 1, c0 = (tid & 1) * 32;
#pragma unroll
        for (int i = 0; i < 8; i++) {
            const int c = c0 + i * 4;
            float4 qv = *(const float4*)(Q + base + (size_t)(q0 + r) * HH + c);
            float fx[4] = {qv.x, qv.y, qv.z, qv.w};
            __half hh[4], ll[4];
#pragma unroll
            for (int t = 0; t < 4; t++) {
                hh[t] = __float2half_rn(fx[t]);
                ll[t] = __float2half_rn(fx[t] - __half2float(hh[t]));
            }
            *(uint32_t*)&Qh[r * APAD + c]     = pack2h(hh[0], hh[1]);
            *(uint32_t*)&Qh[r * APAD + c + 2] = pack2h(hh[2], hh[3]);
            *(uint32_t*)&Ql[r * APAD + c]     = pack2h(ll[0], ll[1]);
            *(uint32_t*)&Ql[r * APAD + c + 2] = pack2h(ll[2], ll[3]);
        }
    }
    __syncthreads();

    // ---- per-warp Q fragments (4 k16 steps) ----
    uint32_t qhf[4][4], qlf[4][4];
    {
        const int row = w16 + (lane & 15);
        const int colb = (lane >> 4) << 3;
#pragma unroll
        for (int kk = 0; kk < 4; kk++) {
            uint32_t a = smem_u32(&Qh[row * APAD + kk * 16 + colb]);
            ldsm_x4(qhf[kk][0], qhf[kk][1], qhf[kk][2], qhf[kk][3], a);
            a = smem_u32(&Ql[row * APAD + kk * 16 + colb]);
            ldsm_x4(qlf[kk][0], qlf[kk][1], qlf[kk][2], qlf[kk][3], a);
        }
    }

    float oacc[8][4];
#pragma unroll
    for (int j = 0; j < 8; j++)
#pragma unroll
        for (int t = 0; t < 4; t++) oacc[j][t] = 0.f;
    float m0 = -1e30f, m1 = -1e30f, l0 = 0.f, l1 = 0.f;

    // ldmatrix address offsets (precomputed lane roles)
    const int krow_off = (lane & 7) + ((lane >> 4) << 3);   // + n0
    const int kcol_off = (lane & 8);                         // + k0
    const int vrow_off = (lane & 7) + (lane & 8);            // + kv0
    const int vcol_off = ((lane >> 4) << 3);                 // + d0

    for (int kt = 0; kt < SS; kt += 64) {
        __syncthreads();
        // ---- load K (fp16), V (hi/lo), mask ----
        {
            const int r = tid >> 1, c0 = (tid & 1) * 32;
            const float* Kp = K + base + (size_t)(kt + r) * HH;
            const float* Vp = V + base + (size_t)(kt + r) * HH;
#pragma unroll
            for (int i = 0; i < 8; i++) {
                const int c = c0 + i * 4;
                float4 kf = *(const float4*)(Kp + c);
                *(uint32_t*)&Ksm[r * APAD + c]     = pack2h(__float2half_rn(kf.x), __float2half_rn(kf.y));
                *(uint32_t*)&Ksm[r * APAD + c + 2] = pack2h(__float2half_rn(kf.z), __float2half_rn(kf.w));
                float4 vf = *(const float4*)(Vp + c);
                float fx[4] = {vf.x, vf.y, vf.z, vf.w};
                __half hh[4], ll[4];
#pragma unroll
                for (int t = 0; t < 4; t++) {
                    hh[t] = __float2half_rn(fx[t]);
                    ll[t] = __float2half_rn(fx[t] - __half2float(hh[t]));
                }
                *(uint32_t*)&Vh[r * APAD + c]     = pack2h(hh[0], hh[1]);
                *(uint32_t*)&Vh[r * APAD + c + 2] = pack2h(hh[2], hh[3]);
                *(uint32_t*)&Vl[r * APAD + c]     = pack2h(ll[0], ll[1]);
                *(uint32_t*)&Vl[r * APAD + c + 2] = pack2h(ll[2], ll[3]);
            }
            if (tid < 64) msk[tid] = mask[b * SS + kt + tid];
        }
        __syncthreads();

        // ---- scores: S = Q K^T (2-term) ----
        float sacc[8][4];
#pragma unroll
        for (int j = 0; j < 8; j++)
#pragma unroll
            for (int t = 0; t < 4; t++) sacc[j][t] = 0.f;
#pragma unroll
        for (int jp = 0; jp < 4; jp++) {
#pragma unroll
            for (int kk = 0; kk < 4; kk++) {
                uint32_t r0, r1, r2, r3;
                uint32_t a = smem_u32(&Ksm[(jp * 16 + krow_off) * APAD + kk * 16 + kcol_off]);
                ldsm_x4(r0, r1, r2, r3, a);
                mma_f16(sacc[2*jp][0], sacc[2*jp][1], sacc[2*jp][2], sacc[2*jp][3],
                        qhf[kk][0], qhf[kk][1], qhf[kk][2], qhf[kk][3], r0, r1);
                mma_f16(sacc[2*jp][0], sacc[2*jp][1], sacc[2*jp][2], sacc[2*jp][3],
                        qlf[kk][0], qlf[kk][1], qlf[kk][2], qlf[kk][3], r0, r1);
                mma_f16(sacc[2*jp+1][0], sacc[2*jp+1][1], sacc[2*jp+1][2], sacc[2*jp+1][3],
                        qhf[kk][0], qhf[kk][1], qhf[kk][2], qhf[kk][3], r2, r3);
                mma_f16(sacc[2*jp+1][0], sacc[2*jp+1][1], sacc[2*jp+1][2], sacc[2*jp+1][3],
                        qlf[kk][0], qlf[kk][1], qlf[kk][2], qlf[kk][3], r2, r3);
            }
        }

        // ---- scale + mask + online softmax ----
        float tm0 = -1e30f, tm1 = -1e30f;
#pragma unroll
        for (int j = 0; j < 8; j++) {
            const float mv0 = msk[j * 8 + 2 * t4], mv1 = msk[j * 8 + 2 * t4 + 1];
            sacc[j][0] = sacc[j][0] * 0.125f + mv0;
            sacc[j][1] = sacc[j][1] * 0.125f + mv1;
            sacc[j][2] = sacc[j][2] * 0.125f + mv0;
            sacc[j][3] = sacc[j][3] * 0.125f + mv1;
            tm0 = fmaxf(tm0, fmaxf(sacc[j][0], sacc[j][1]));
            tm1 = fmaxf(tm1, fmaxf(sacc[j][2], sacc[j][3]));
        }
        tm0 = fmaxf(tm0, __shfl_xor_sync(0xffffffffu, tm0, 1));
        tm0 = fmaxf(tm0, __shfl_xor_sync(0xffffffffu, tm0, 2));
        tm1 = fmaxf(tm1, __shfl_xor_sync(0xffffffffu, tm1, 1));
        tm1 = fmaxf(tm1, __shfl_xor_sync(0xffffffffu, tm1, 2));
        const float mn0 = fmaxf(m0, tm0), mn1 = fmaxf(m1, tm1);
        const float al0 = __expf(m0 - mn0), al1 = __expf(m1 - mn1);
        m0 = mn0; m1 = mn1;
        float ls0 = 0.f, ls1 = 0.f;
#pragma unroll
        for (int j = 0; j < 8; j++) {
            sacc[j][0] = __expf(sacc[j][0] - mn0);
            sacc[j][1] = __expf(sacc[j][1] - mn0);
            sacc[j][2] = __expf(sacc[j][2] - mn1);
            sacc[j][3] = __expf(sacc[j][3] - mn1);
            ls0 += sacc[j][0] + sacc[j][1];
            ls1 += sacc[j][2] + sacc[j][3];
        }
        l0 = l0 * al0 + ls0;
        l1 = l1 * al1 + ls1;
#pragma unroll
        for (int j = 0; j < 8; j++) {
            oacc[j][0] *= al0; oacc[j][1] *= al0;
            oacc[j][2] *= al1; oacc[j][3] *= al1;
        }

        // ---- P fragments (accum layout == A-frag layout) ----
        uint32_t pf[4][4];
#pragma unroll
        for (int kk = 0; kk < 4; kk++) {
            pf[kk][0] = pack2h(__float2half_rn(sacc[2*kk][0]),   __float2half_rn(sacc[2*kk][1]));
            pf[kk][1] = pack2h(__float2half_rn(sacc[2*kk][2]),   __float2half_rn(sacc[2*kk][3]));
            pf[kk][2] = pack2h(__float2half_rn(sacc[2*kk+1][0]), __float2half_rn(sacc[2*kk+1][1]));
            pf[kk][3] = pack2h(__float2half_rn(sacc[2*kk+1][2]), __float2half_rn(sacc[2*kk+1][3]));
        }

        // ---- O += P @ (Vh + Vl) ----
#pragma unroll
        for (int dp = 0; dp < 4; dp++) {
#pragma unroll
            for (int kk = 0; kk < 4; kk++) {
                uint32_t r0, r1, r2, r3;
                uint32_t a = smem_u32(&Vh[(kk * 16 + vrow_off) * APAD + dp * 16 + vcol_off]);
                ldsm_x4_t(r0, r1, r2, r3, a);
                mma_f16(oacc[2*dp][0], oacc[2*dp][1], oacc[2*dp][2], oacc[2*dp][3],
                        pf[kk][0], pf[kk][1], pf[kk][2], pf[kk][3], r0, r1);
                mma_f16(oacc[2*dp+1][0], oacc[2*dp+1][1], oacc[2*dp+1][2], oacc[2*dp+1][3],
                        pf[kk][0], pf[kk][1], pf[kk][2], pf[kk][3], r2, r3);
                a = smem_u32(&Vl[(kk * 16 + vrow_off) * APAD + dp * 16 + vcol_off]);
                ldsm_x4_t(r0, r1, r2, r3, a);
                mma_f16(oacc[2*dp][0], oacc[2*dp][1], oacc[2*dp][2], oacc[2*dp][3],
                        pf[kk][0], pf[kk][1], pf[kk][2], pf[kk][3], r0, r1);
                mma_f16(oacc[2*dp+1][0], oacc[2*dp+1][1], oacc[2*dp+1][2], oacc[2*dp+1][3],
                        pf[kk][0], pf[kk][1], pf[kk][2], pf[kk][3], r2, r3);
            }
        }
    }

    // ---- finalize: reduce l over quad, divide, store ----
    l0 += __shfl_xor_sync(0xffffffffu, l0, 1);
    l0 += __shfl_xor_sync(0xffffffffu, l0, 2);
    l1 += __shfl_xor_sync(0xffffffffu, l1, 1);
    l1 += __shfl_xor_sync(0xffffffffu, l1, 2);
    const float inv0 = 1.f / l0, inv1 = 1.f / l1;
    const int row0 = q0 + w16 + g;
#pragma unroll
    for (int j = 0; j < 8; j++) {
        const int col = j * 8 + 2 * t4;
        *(float2*)(O + base + (size_t)row0 * HH + col) =
            make_float2(oacc[j][0] * inv0, oacc[j][1] * inv0);
        *(float2*)(O + base + (size_t)(row0 + 8) * HH + col) =
            make_float2(oacc[j][2] * inv1, oacc[j][3] * inv1);
    }
}

// ---------------- layernorm ----------------
__global__ __launch_bounds__(256)
void ln_kernel(const float* __restrict__ x, const float* __restrict__ g,
               const float* __restrict__ bt, float* __restrict__ y)
{
    const int row = blockIdx.x;
    const int tid = threadIdx.x;
    const float* xr = x + (size_t)row * HH;
    float v[4];
    float s = 0.f;
#pragma unroll
    for (int i = 0; i < 4; i++) { v[i] = xr[tid + i * 256]; s += v[i]; }

    __shared__ float smr[8];
    __shared__ float mu_s, var_s;
#pragma unroll
    for (int o = 16; o; o >>= 1) s += __shfl_xor_sync(0xffffffffu, s, o);
    if ((tid & 31) == 0) smr[tid >> 5] = s;
    __syncthreads();
    if (tid < 32) {
        float t = (tid < 8) ? smr[tid] : 0.f;
#pragma unroll
        for (int o = 4; o; o >>= 1) t += __shfl_xor_sync(0xffffffffu, t, o);
        if (tid == 0) mu_s = t * (1.f / HH);
    }
    __syncthreads();
    const float mu = mu_s;
    float s2 = 0.f;
#pragma unroll
    for (int i = 0; i < 4; i++) { float d = v[i] - mu; s2 += d * d; }
#pragma unroll
    for (int o = 16; o; o >>= 1) s2 += __shfl_xor_sync(0xffffffffu, s2, o);
    __syncthreads();
    if ((tid & 31) == 0) smr[tid >> 5] = s2;
    __syncthreads();
    if (tid < 32) {
        float t = (tid < 8) ? smr[tid] : 0.f;
#pragma unroll
        for (int o = 4; o; o >>= 1) t += __shfl_xor_sync(0xffffffffu, t, o);
        if (tid == 0) var_s = t * (1.f / HH);
    }
    __syncthreads();
    const float inv = rsqrtf(var_s + 1e-5f);
#pragma unroll
    for (int i = 0; i < 4; i++) {
        const int c = tid + i * 256;
        y[(size_t)row * HH + c] = (v[i] - mu) * inv * g[c] + bt[c];
    }
}

// ---------------- host ----------------
extern "C" void kernel_launch(void* const* d_in, const int* in_sizes, int n_in,
                              void* d_out, int out_size)
{
    (void)in_sizes; (void)n_in; (void)out_size;
    const float* x     = (const float*)d_in[0];
    const float* mask  = (const float*)d_in[1];
    const float* wq    = (const float*)d_in[2];
    const float* bq    = (const float*)d_in[3];
    const float* wk    = (const float*)d_in[4];
    const float* bk    = (const float*)d_in[5];
    const float* wv    = (const float*)d_in[6];
    const float* bv    = (const float*)d_in[7];
    const float* wo    = (const float*)d_in[8];
    const float* bo    = (const float*)d_in[9];
    const float* ln1g  = (const float*)d_in[10];
    const float* ln1b  = (const float*)d_in[11];
    const float* wi    = (const float*)d_in[12];
    const float* bi    = (const float*)d_in[13];
    const float* wo2   = (const float*)d_in[14];
    const float* bo2   = (const float*)d_in[15];
    const float* ln2g  = (const float*)d_in[16];
    const float* ln2b  = (const float*)d_in[17];
    float* out = (float*)d_out;

    float *q, *k, *v, *ctx, *t1, *attn, *inter, *t2;
    cudaGetSymbolAddress((void**)&q,     g_q);
    cudaGetSymbolAddress((void**)&k,     g_k);
    cudaGetSymbolAddress((void**)&v,     g_v);
    cudaGetSymbolAddress((void**)&ctx,   g_ctx);
    cudaGetSymbolAddress((void**)&t1,    g_t1);
    cudaGetSymbolAddress((void**)&attn,  g_attn);
    cudaGetSymbolAddress((void**)&inter, g_inter);
    cudaGetSymbolAddress((void**)&t2,    g_t2);

    cudaFuncSetAttribute(gemm_hmma<0>, cudaFuncAttributeMaxDynamicSharedMemorySize, GEMM_SMEM);
    cudaFuncSetAttribute(gemm_hmma<1>, cudaFuncAttributeMaxDynamicSharedMemorySize, GEMM_SMEM);
    cudaFuncSetAttribute(gemm_hmma<2>, cudaFuncAttributeMaxDynamicSharedMemorySize, GEMM_SMEM);

    const dim3 blkG(256);
    const dim3 gH(HH / 128, MTOK / 128);
    const dim3 gF(FFD / 128, MTOK / 128);

    gemm_hmma<0><<<gH, blkG, GEMM_SMEM>>>(x, wq, bq, nullptr, q, MTOK, HH, HH);
    gemm_hmma<0><<<gH, blkG, GEMM_SMEM>>>(x, wk, bk, nullptr, k, MTOK, HH, HH);
    gemm_hmma<0><<<gH, blkG, GEMM_SMEM>>>(x, wv, bv, nullptr, v, MTOK, HH, HH);

    attn_kernel<<<dim3(SS / 64, NHEAD, BB), dim3(128)>>>(q, k, v, mask, ctx);

    gemm_hmma<2><<<gH, blkG, GEMM_SMEM>>>(ctx, wo, bo, x, t1, MTOK, HH, HH);
    ln_kernel<<<MTOK, dim3(256)>>>(t1, ln1g, ln1b, attn);

    gemm_hmma<1><<<gF, blkG, GEMM_SMEM>>>(attn, wi, bi, nullptr, inter, MTOK, FFD, HH);
    gemm_hmma<2><<<gH, blkG, GEMM_SMEM>>>(inter, wo2, bo2, attn, t2, MTOK, HH, FFD);
    ln_kernel<<<MTOK, dim3(256)>>>(t2, ln2g, ln2b, out);
}

// round 7
// speedup vs baseline: 4.5369x; 1.9229x over previous
#include <cuda_runtime.h>
#include <cuda_fp16.h>
#include <cstdint>
#include <math.h>

#define BB 8
#define SS 512
#define HH 1024
#define NHEAD 16
#define HDIM 64
#define FFD 4096
#define MTOK (BB*SS)   // 4096 tokens

// ---------------- scratch (static __device__, no allocs) ----------------
__device__ float g_q[MTOK*HH];
__device__ float g_k[MTOK*HH];
__device__ float g_v[MTOK*HH];
__device__ float g_ctx[MTOK*HH];
__device__ float g_t1[MTOK*HH];
__device__ float g_attn[MTOK*HH];
__device__ float g_inter[(size_t)MTOK*FFD];
__device__ float g_t2[MTOK*HH];

// ==================== helpers ====================
__device__ __forceinline__ uint32_t smem_u32(const void* p) {
    uint32_t a;
    asm("{ .reg .u64 t; cvta.to.shared.u64 t, %1; cvt.u32.u64 %0, t; }" : "=r"(a) : "l"(p));
    return a;
}
__device__ __forceinline__ uint32_t pack2h(__half a, __half b) {
    return (uint32_t)__half_as_ushort(a) | ((uint32_t)__half_as_ushort(b) << 16);
}
__device__ __forceinline__ void mma_f16(float& d0, float& d1, float& d2, float& d3,
                                        uint32_t a0, uint32_t a1, uint32_t a2, uint32_t a3,
                                        uint32_t b0, uint32_t b1) {
    asm volatile(
        "mma.sync.aligned.m16n8k16.row.col.f32.f16.f16.f32 "
        "{%0,%1,%2,%3}, {%4,%5,%6,%7}, {%8,%9}, {%0,%1,%2,%3};"
        : "+f"(d0), "+f"(d1), "+f"(d2), "+f"(d3)
        : "r"(a0), "r"(a1), "r"(a2), "r"(a3), "r"(b0), "r"(b1));
}
__device__ __forceinline__ void ldsm_x4(uint32_t& r0, uint32_t& r1, uint32_t& r2, uint32_t& r3, uint32_t a) {
    asm volatile("ldmatrix.sync.aligned.m8n8.x4.shared.b16 {%0,%1,%2,%3}, [%4];"
        : "=r"(r0), "=r"(r1), "=r"(r2), "=r"(r3) : "r"(a));
}
__device__ __forceinline__ void ldsm_x4_t(uint32_t& r0, uint32_t& r1, uint32_t& r2, uint32_t& r3, uint32_t a) {
    asm volatile("ldmatrix.sync.aligned.m8n8.x4.trans.shared.b16 {%0,%1,%2,%3}, [%4];"
        : "=r"(r0), "=r"(r1), "=r"(r2), "=r"(r3) : "r"(a));
}

// ==================== HMMA GEMM (pure fp16, fp32 accum, ldmatrix) =======
// C[M,N] = A[M,K] @ B[K,N] + bias (+epilogue). CTA 128x128, BK=32.
// 8 warps (2m x 4n), warp tile 64x32.
// Row stride GP=40 halfs = 80 bytes: 16B-aligned for ldmatrix, +5 mod 8
// bank step per row -> conflict-free.
// EPI: 0 = bias, 1 = gelu(bias+x), 2 = bias + residual

#define GP 40                    // padded halfs per 32-elem row (stride 80B)
#define A_OFF 0                  // 128*80 = 10240 B
#define B_OFF 10240
#define STAGE 20480
#define GEMM_SMEM (2*STAGE)      // 40960

template<int EPI>
__global__ __launch_bounds__(256)
void gemm_hmma(const float* __restrict__ A, const float* __restrict__ B,
               const float* __restrict__ bias, const float* __restrict__ res,
               float* __restrict__ C, int M, int N, int K)
{
    extern __shared__ __half smh[];
    const int tid = threadIdx.x;
    const int m0 = blockIdx.y * 128, n0 = blockIdx.x * 128;

    const int wid = tid >> 5, lane = tid & 31;
    const int wm = wid >> 2, wn = wid & 3;      // warp grid 2x4
    const int g = lane >> 2, q = lane & 3;

    // global-load coordinates
    const int arow = tid >> 1;
    const int acol = (tid & 1) * 16;
    const int bn   = tid & 127;
    const int bks  = (tid >> 7) * 16;

    // ldmatrix lane roles
    const int a_row_off = lane & 15;
    const int a_col_off = ((lane >> 4) << 3);
    const int b_row_off = (lane & 7) + ((lane >> 4) << 3);
    const int b_col_off = (lane & 8);

    float acc[4][4][4];
#pragma unroll
    for (int i = 0; i < 4; i++)
#pragma unroll
        for (int j = 0; j < 4; j++)
#pragma unroll
            for (int t = 0; t < 4; t++) acc[i][j][t] = 0.f;

    float4 av[4];
    float  bv[16];
    auto load_regs = [&](int k0) {
        const float* Ap = A + (size_t)(m0 + arow) * K + k0 + acol;
#pragma unroll
        for (int i = 0; i < 4; i++) av[i] = *(const float4*)(Ap + i * 4);
        const float* Bp = B + (size_t)(k0 + bks) * N + n0 + bn;
#pragma unroll
        for (int j = 0; j < 16; j++) bv[j] = Bp[(size_t)j * N];
    };
    auto store_regs = [&](int sbase) {
        __half* sA = smh + sbase;                 // [128][GP]
        __half* sB = smh + sbase + B_OFF / 2;     // [128][GP] (rows = n)
#pragma unroll
        for (int i = 0; i < 4; i++) {
            uint2 p;
            p.x = pack2h(__float2half_rn(av[i].x), __float2half_rn(av[i].y));
            p.y = pack2h(__float2half_rn(av[i].z), __float2half_rn(av[i].w));
            *(uint2*)&sA[arow * GP + acol + i * 4] = p;
        }
#pragma unroll
        for (int j = 0; j < 16; j += 2) {
            *(uint32_t*)&sB[bn * GP + bks + j] =
                pack2h(__float2half_rn(bv[j]), __float2half_rn(bv[j + 1]));
        }
    };
    auto compute_stage = [&](int sbase) {
        const __half* sA = smh + sbase;
        const __half* sB = smh + sbase + B_OFF / 2;
#pragma unroll
        for (int kk = 0; kk < 2; kk++) {
            uint32_t af[4][4];
#pragma unroll
            for (int mt = 0; mt < 4; mt++) {
                uint32_t a = smem_u32(&sA[(wm * 64 + mt * 16 + a_row_off) * GP + kk * 16 + a_col_off]);
                ldsm_x4(af[mt][0], af[mt][1], af[mt][2], af[mt][3], a);
            }
#pragma unroll
            for (int np = 0; np < 2; np++) {
                uint32_t r0, r1, r2, r3;
                uint32_t a = smem_u32(&sB[(wn * 32 + np * 16 + b_row_off) * GP + kk * 16 + b_col_off]);
                ldsm_x4(r0, r1, r2, r3, a);
#pragma unroll
                for (int mt = 0; mt < 4; mt++) {
                    mma_f16(acc[mt][2*np][0], acc[mt][2*np][1], acc[mt][2*np][2], acc[mt][2*np][3],
                            af[mt][0], af[mt][1], af[mt][2], af[mt][3], r0, r1);
                    mma_f16(acc[mt][2*np+1][0], acc[mt][2*np+1][1], acc[mt][2*np+1][2], acc[mt][2*np+1][3],
                            af[mt][0], af[mt][1], af[mt][2], af[mt][3], r2, r3);
                }
            }
        }
    };

    // ---- main loop: double-buffered ----
    load_regs(0);
    store_regs(0);
    __syncthreads();
    const int NC = K >> 5;
    for (int c = 0; c < NC; c++) {
        const int cur = (c & 1) * (STAGE / 2);
        if (c + 1 < NC) load_regs((c + 1) << 5);       // LDGs in flight
        compute_stage(cur);                            // hide LDG latency
        if (c + 1 < NC) store_regs(((c + 1) & 1) * (STAGE / 2));
        __syncthreads();
    }

    // ---- epilogue ----
#pragma unroll
    for (int mt = 0; mt < 4; mt++) {
        const int r0 = m0 + wm * 64 + mt * 16 + g;
#pragma unroll
        for (int nt = 0; nt < 4; nt++) {
            const int col = n0 + wn * 32 + nt * 8 + q * 2;
            float b0 = bias[col], b1 = bias[col + 1];
#pragma unroll
            for (int h = 0; h < 2; h++) {
                const int row = r0 + h * 8;
                float v0 = acc[mt][nt][h * 2 + 0] + b0;
                float v1 = acc[mt][nt][h * 2 + 1] + b1;
                if (EPI == 1) {
                    v0 = 0.5f * v0 * (1.0f + erff(v0 * 0.70710678118654752440f));
                    v1 = 0.5f * v1 * (1.0f + erff(v1 * 0.70710678118654752440f));
                }
                if (EPI == 2) {
                    float2 r2 = *(const float2*)(res + (size_t)row * N + col);
                    v0 += r2.x; v1 += r2.y;
                }
                *(float2*)(C + (size_t)row * N + col) = make_float2(v0, v1);
            }
        }
    }
}

// ==================== flash attention (HMMA, online softmax) ============
// CTA: (b, h, 64 q rows); 4 warps x 16 q rows. kv tiles of 64.
#define APAD 72    // halfs per smem row (64 + 8) = 144 B, 16B-aligned

__global__ __launch_bounds__(128)
void attn_kernel(const float* __restrict__ Q, const float* __restrict__ K,
                 const float* __restrict__ V, const float* __restrict__ mask,
                 float* __restrict__ O)
{
    __shared__ __align__(16) __half Qh[64*APAD];
    __shared__ __align__(16) __half Ql[64*APAD];
    __shared__ __align__(16) __half Ksm[64*APAD];
    __shared__ __align__(16) __half Vh[64*APAD];
    __shared__ __align__(16) __half Vl[64*APAD];
    __shared__ float msk[64];

    const int qt = blockIdx.x, h = blockIdx.y, b = blockIdx.z;
    const int tid = threadIdx.x;
    const int wid = tid >> 5, lane = tid & 31;
    const int g = lane >> 2, t4 = lane & 3;
    const int q0 = qt * 64;
    const int base = (b * SS) * HH + h * HDIM;
    const int w16 = wid * 16;

    // ---- stage Q (hi/lo split) ----
    {
        const int r = tid >> 1, c0 = (tid & 1) * 32;
#pragma unroll
        for (int i = 0; i < 8; i++) {
            const int c = c0 + i * 4;
            float4 qv = *(const float4*)(Q + base + (size_t)(q0 + r) * HH + c);
            float fx[4] = {qv.x, qv.y, qv.z, qv.w};
            __half hh[4], ll[4];
#pragma unroll
            for (int t = 0; t < 4; t++) {
                hh[t] = __float2half_rn(fx[t]);
                ll[t] = __float2half_rn(fx[t] - __half2float(hh[t]));
            }
            *(uint32_t*)&Qh[r * APAD + c]     = pack2h(hh[0], hh[1]);
            *(uint32_t*)&Qh[r * APAD + c + 2] = pack2h(hh[2], hh[3]);
            *(uint32_t*)&Ql[r * APAD + c]     = pack2h(ll[0], ll[1]);
            *(uint32_t*)&Ql[r * APAD + c + 2] = pack2h(ll[2], ll[3]);
        }
    }
    __syncthreads();

    // ---- per-warp Q fragments (4 k16 steps) ----
    uint32_t qhf[4][4], qlf[4][4];
    {
        const int row = w16 + (lane & 15);
        const int colb = (lane >> 4) << 3;
#pragma unroll
        for (int kk = 0; kk < 4; kk++) {
            uint32_t a = smem_u32(&Qh[row * APAD + kk * 16 + colb]);
            ldsm_x4(qhf[kk][0], qhf[kk][1], qhf[kk][2], qhf[kk][3], a);
            a = smem_u32(&Ql[row * APAD + kk * 16 + colb]);
            ldsm_x4(qlf[kk][0], qlf[kk][1], qlf[kk][2], qlf[kk][3], a);
        }
    }

    float oacc[8][4];
#pragma unroll
    for (int j = 0; j < 8; j++)
#pragma unroll
        for (int t = 0; t < 4; t++) oacc[j][t] = 0.f;
    float m0 = -1e30f, m1 = -1e30f, l0 = 0.f, l1 = 0.f;

    const int krow_off = (lane & 7) + ((lane >> 4) << 3);
    const int kcol_off = (lane & 8);
    const int vrow_off = (lane & 7) + (lane & 8);
    const int vcol_off = ((lane >> 4) << 3);

    for (int kt = 0; kt < SS; kt += 64) {
        __syncthreads();
        {
            const int r = tid >> 1, c0 = (tid & 1) * 32;
            const float* Kp = K + base + (size_t)(kt + r) * HH;
            const float* Vp = V + base + (size_t)(kt + r) * HH;
#pragma unroll
            for (int i = 0; i < 8; i++) {
                const int c = c0 + i * 4;
                float4 kf = *(const float4*)(Kp + c);
                *(uint32_t*)&Ksm[r * APAD + c]     = pack2h(__float2half_rn(kf.x), __float2half_rn(kf.y));
                *(uint32_t*)&Ksm[r * APAD + c + 2] = pack2h(__float2half_rn(kf.z), __float2half_rn(kf.w));
                float4 vf = *(const float4*)(Vp + c);
                float fx[4] = {vf.x, vf.y, vf.z, vf.w};
                __half hh[4], ll[4];
#pragma unroll
                for (int t = 0; t < 4; t++) {
                    hh[t] = __float2half_rn(fx[t]);
                    ll[t] = __float2half_rn(fx[t] - __half2float(hh[t]));
                }
                *(uint32_t*)&Vh[r * APAD + c]     = pack2h(hh[0], hh[1]);
                *(uint32_t*)&Vh[r * APAD + c + 2] = pack2h(hh[2], hh[3]);
                *(uint32_t*)&Vl[r * APAD + c]     = pack2h(ll[0], ll[1]);
                *(uint32_t*)&Vl[r * APAD + c + 2] = pack2h(ll[2], ll[3]);
            }
            if (tid < 64) msk[tid] = mask[b * SS + kt + tid];
        }
        __syncthreads();

        float sacc[8][4];
#pragma unroll
        for (int j = 0; j < 8; j++)
#pragma unroll
            for (int t = 0; t < 4; t++) sacc[j][t] = 0.f;
#pragma unroll
        for (int jp = 0; jp < 4; jp++) {
#pragma unroll
            for (int kk = 0; kk < 4; kk++) {
                uint32_t r0, r1, r2, r3;
                uint32_t a = smem_u32(&Ksm[(jp * 16 + krow_off) * APAD + kk * 16 + kcol_off]);
                ldsm_x4(r0, r1, r2, r3, a);
                mma_f16(sacc[2*jp][0], sacc[2*jp][1], sacc[2*jp][2], sacc[2*jp][3],
                        qhf[kk][0], qhf[kk][1], qhf[kk][2], qhf[kk][3], r0, r1);
                mma_f16(sacc[2*jp][0], sacc[2*jp][1], sacc[2*jp][2], sacc[2*jp][3],
                        qlf[kk][0], qlf[kk][1], qlf[kk][2], qlf[kk][3], r0, r1);
                mma_f16(sacc[2*jp+1][0], sacc[2*jp+1][1], sacc[2*jp+1][2], sacc[2*jp+1][3],
                        qhf[kk][0], qhf[kk][1], qhf[kk][2], qhf[kk][3], r2, r3);
                mma_f16(sacc[2*jp+1][0], sacc[2*jp+1][1], sacc[2*jp+1][2], sacc[2*jp+1][3],
                        qlf[kk][0], qlf[kk][1], qlf[kk][2], qlf[kk][3], r2, r3);
            }
        }

        float tm0 = -1e30f, tm1 = -1e30f;
#pragma unroll
        for (int j = 0; j < 8; j++) {
            const float mv0 = msk[j * 8 + 2 * t4], mv1 = msk[j * 8 + 2 * t4 + 1];
            sacc[j][0] = sacc[j][0] * 0.125f + mv0;
            sacc[j][1] = sacc[j][1] * 0.125f + mv1;
            sacc[j][2] = sacc[j][2] * 0.125f + mv0;
            sacc[j][3] = sacc[j][3] * 0.125f + mv1;
            tm0 = fmaxf(tm0, fmaxf(sacc[j][0], sacc[j][1]));
            tm1 = fmaxf(tm1, fmaxf(sacc[j][2], sacc[j][3]));
        }
        tm0 = fmaxf(tm0, __shfl_xor_sync(0xffffffffu, tm0, 1));
        tm0 = fmaxf(tm0, __shfl_xor_sync(0xffffffffu, tm0, 2));
        tm1 = fmaxf(tm1, __shfl_xor_sync(0xffffffffu, tm1, 1));
        tm1 = fmaxf(tm1, __shfl_xor_sync(0xffffffffu, tm1, 2));
        const float mn0 = fmaxf(m0, tm0), mn1 = fmaxf(m1, tm1);
        const float al0 = __expf(m0 - mn0), al1 = __expf(m1 - mn1);
        m0 = mn0; m1 = mn1;
        float ls0 = 0.f, ls1 = 0.f;
#pragma unroll
        for (int j = 0; j < 8; j++) {
            sacc[j][0] = __expf(sacc[j][0] - mn0);
            sacc[j][1] = __expf(sacc[j][1] - mn0);
            sacc[j][2] = __expf(sacc[j][2] - mn1);
            sacc[j][3] = __expf(sacc[j][3] - mn1);
            ls0 += sacc[j][0] + sacc[j][1];
            ls1 += sacc[j][2] + sacc[j][3];
        }
        l0 = l0 * al0 + ls0;
        l1 = l1 * al1 + ls1;
#pragma unroll
        for (int j = 0; j < 8; j++) {
            oacc[j][0] *= al0; oacc[j][1] *= al0;
            oacc[j][2] *= al1; oacc[j][3] *= al1;
        }

        uint32_t pf[4][4];
#pragma unroll
        for (int kk = 0; kk < 4; kk++) {
            pf[kk][0] = pack2h(__float2half_rn(sacc[2*kk][0]),   __float2half_rn(sacc[2*kk][1]));
            pf[kk][1] = pack2h(__float2half_rn(sacc[2*kk][2]),   __float2half_rn(sacc[2*kk][3]));
            pf[kk][2] = pack2h(__float2half_rn(sacc[2*kk+1][0]), __float2half_rn(sacc[2*kk+1][1]));
            pf[kk][3] = pack2h(__float2half_rn(sacc[2*kk+1][2]), __float2half_rn(sacc[2*kk+1][3]));
        }

#pragma unroll
        for (int dp = 0; dp < 4; dp++) {
#pragma unroll
            for (int kk = 0; kk < 4; kk++) {
                uint32_t r0, r1, r2, r3;
                uint32_t a = smem_u32(&Vh[(kk * 16 + vrow_off) * APAD + dp * 16 + vcol_off]);
                ldsm_x4_t(r0, r1, r2, r3, a);
                mma_f16(oacc[2*dp][0], oacc[2*dp][1], oacc[2*dp][2], oacc[2*dp][3],
                        pf[kk][0], pf[kk][1], pf[kk][2], pf[kk][3], r0, r1);
                mma_f16(oacc[2*dp+1][0], oacc[2*dp+1][1], oacc[2*dp+1][2], oacc[2*dp+1][3],
                        pf[kk][0], pf[kk][1], pf[kk][2], pf[kk][3], r2, r3);
                a = smem_u32(&Vl[(kk * 16 + vrow_off) * APAD + dp * 16 + vcol_off]);
                ldsm_x4_t(r0, r1, r2, r3, a);
                mma_f16(oacc[2*dp][0], oacc[2*dp][1], oacc[2*dp][2], oacc[2*dp][3],
                        pf[kk][0], pf[kk][1], pf[kk][2], pf[kk][3], r0, r1);
                mma_f16(oacc[2*dp+1][0], oacc[2*dp+1][1], oacc[2*dp+1][2], oacc[2*dp+1][3],
                        pf[kk][0], pf[kk][1], pf[kk][2], pf[kk][3], r2, r3);
            }
        }
    }

    l0 += __shfl_xor_sync(0xffffffffu, l0, 1);
    l0 += __shfl_xor_sync(0xffffffffu, l0, 2);
    l1 += __shfl_xor_sync(0xffffffffu, l1, 1);
    l1 += __shfl_xor_sync(0xffffffffu, l1, 2);
    const float inv0 = 1.f / l0, inv1 = 1.f / l1;
    const int row0 = q0 + w16 + g;
#pragma unroll
    for (int j = 0; j < 8; j++) {
        const int col = j * 8 + 2 * t4;
        *(float2*)(O + base + (size_t)row0 * HH + col) =
            make_float2(oacc[j][0] * inv0, oacc[j][1] * inv0);
        *(float2*)(O + base + (size_t)(row0 + 8) * HH + col) =
            make_float2(oacc[j][2] * inv1, oacc[j][3] * inv1);
    }
}

// ---------------- layernorm ----------------
__global__ __launch_bounds__(256)
void ln_kernel(const float* __restrict__ x, const float* __restrict__ g,
               const float* __restrict__ bt, float* __restrict__ y)
{
    const int row = blockIdx.x;
    const int tid = threadIdx.x;
    const float* xr = x + (size_t)row * HH;
    float v[4];
    float s = 0.f;
#pragma unroll
    for (int i = 0; i < 4; i++) { v[i] = xr[tid + i * 256]; s += v[i]; }

    __shared__ float smr[8];
    __shared__ float mu_s, var_s;
#pragma unroll
    for (int o = 16; o; o >>= 1) s += __shfl_xor_sync(0xffffffffu, s, o);
    if ((tid & 31) == 0) smr[tid >> 5] = s;
    __syncthreads();
    if (tid < 32) {
        float t = (tid < 8) ? smr[tid] : 0.f;
#pragma unroll
        for (int o = 4; o; o >>= 1) t += __shfl_xor_sync(0xffffffffu, t, o);
        if (tid == 0) mu_s = t * (1.f / HH);
    }
    __syncthreads();
    const float mu = mu_s;
    float s2 = 0.f;
#pragma unroll
    for (int i = 0; i < 4; i++) { float d = v[i] - mu; s2 += d * d; }
#pragma unroll
    for (int o = 16; o; o >>= 1) s2 += __shfl_xor_sync(0xffffffffu, s2, o);
    __syncthreads();
    if ((tid & 31) == 0) smr[tid >> 5] = s2;
    __syncthreads();
    if (tid < 32) {
        float t = (tid < 8) ? smr[tid] : 0.f;
#pragma unroll
        for (int o = 4; o; o >>= 1) t += __shfl_xor_sync(0xffffffffu, t, o);
        if (tid == 0) var_s = t * (1.f / HH);
    }
    __syncthreads();
    const float inv = rsqrtf(var_s + 1e-5f);
#pragma unroll
    for (int i = 0; i < 4; i++) {
        const int c = tid + i * 256;
        y[(size_t)row * HH + c] = (v[i] - mu) * inv * g[c] + bt[c];
    }
}

// ---------------- host ----------------
extern "C" void kernel_launch(void* const* d_in, const int* in_sizes, int n_in,
                              void* d_out, int out_size)
{
    (void)in_sizes; (void)n_in; (void)out_size;
    const float* x     = (const float*)d_in[0];
    const float* mask  = (const float*)d_in[1];
    const float* wq    = (const float*)d_in[2];
    const float* bq    = (const float*)d_in[3];
    const float* wk    = (const float*)d_in[4];
    const float* bk    = (const float*)d_in[5];
    const float* wv    = (const float*)d_in[6];
    const float* bv    = (const float*)d_in[7];
    const float* wo    = (const float*)d_in[8];
    const float* bo    = (const float*)d_in[9];
    const float* ln1g  = (const float*)d_in[10];
    const float* ln1b  = (const float*)d_in[11];
    const float* wi    = (const float*)d_in[12];
    const float* bi    = (const float*)d_in[13];
    const float* wo2   = (const float*)d_in[14];
    const float* bo2   = (const float*)d_in[15];
    const float* ln2g  = (const float*)d_in[16];
    const float* ln2b  = (const float*)d_in[17];
    float* out = (float*)d_out;

    float *q, *k, *v, *ctx, *t1, *attn, *inter, *t2;
    cudaGetSymbolAddress((void**)&q,     g_q);
    cudaGetSymbolAddress((void**)&k,     g_k);
    cudaGetSymbolAddress((void**)&v,     g_v);
    cudaGetSymbolAddress((void**)&ctx,   g_ctx);
    cudaGetSymbolAddress((void**)&t1,    g_t1);
    cudaGetSymbolAddress((void**)&attn,  g_attn);
    cudaGetSymbolAddress((void**)&inter, g_inter);
    cudaGetSymbolAddress((void**)&t2,    g_t2);

    cudaFuncSetAttribute(gemm_hmma<0>, cudaFuncAttributeMaxDynamicSharedMemorySize, GEMM_SMEM);
    cudaFuncSetAttribute(gemm_hmma<1>, cudaFuncAttributeMaxDynamicSharedMemorySize, GEMM_SMEM);
    cudaFuncSetAttribute(gemm_hmma<2>, cudaFuncAttributeMaxDynamicSharedMemorySize, GEMM_SMEM);

    const dim3 blkG(256);
    const dim3 gH(HH / 128, MTOK / 128);
    const dim3 gF(FFD / 128, MTOK / 128);

    gemm_hmma<0><<<gH, blkG, GEMM_SMEM>>>(x, wq, bq, nullptr, q, MTOK, HH, HH);
    gemm_hmma<0><<<gH, blkG, GEMM_SMEM>>>(x, wk, bk, nullptr, k, MTOK, HH, HH);
    gemm_hmma<0><<<gH, blkG, GEMM_SMEM>>>(x, wv, bv, nullptr, v, MTOK, HH, HH);

    attn_kernel<<<dim3(SS / 64, NHEAD, BB), dim3(128)>>>(q, k, v, mask, ctx);

    gemm_hmma<2><<<gH, blkG, GEMM_SMEM>>>(ctx, wo, bo, x, t1, MTOK, HH, HH);
    ln_kernel<<<MTOK, dim3(256)>>>(t1, ln1g, ln1b, attn);

    gemm_hmma<1><<<gF, blkG, GEMM_SMEM>>>(attn, wi, bi, nullptr, inter, MTOK, FFD, HH);
    gemm_hmma<2><<<gH, blkG, GEMM_SMEM>>>(inter, wo2, bo2, attn, t2, MTOK, HH, FFD);
    ln_kernel<<<MTOK, dim3(256)>>>(t2, ln2g, ln2b, out);
}

// round 8
// speedup vs baseline: 4.8245x; 1.0634x over previous
#include <cuda_runtime.h>
#include <cuda_fp16.h>
#include <cstdint>
#include <math.h>

#define BB 8
#define SS 512
#define HH 1024
#define NHEAD 16
#define HDIM 64
#define FFD 4096
#define MTOK (BB*SS)   // 4096 tokens

// ---------------- scratch (static __device__, no allocs) ----------------
__device__ __half g_xh[MTOK*HH];
__device__ __half g_wqT[HH*HH];
__device__ __half g_wkT[HH*HH];
__device__ __half g_wvT[HH*HH];
__device__ __half g_woT[HH*HH];
__device__ __half g_wiT[(size_t)HH*FFD];    // [FFD][HH]
__device__ __half g_wo2T[(size_t)FFD*HH];   // [HH][FFD]
__device__ __half g_qh[MTOK*HH];
__device__ __half g_ql[MTOK*HH];
__device__ __half g_kh[MTOK*HH];
__device__ __half g_vh[MTOK*HH];
__device__ __half g_vl[MTOK*HH];
__device__ __half g_ctxh[MTOK*HH];
__device__ float  g_t1[MTOK*HH];
__device__ float  g_attn32[MTOK*HH];
__device__ __half g_attnh[MTOK*HH];
__device__ __half g_interh[(size_t)MTOK*FFD];
__device__ float  g_t2[MTOK*HH];

// ==================== helpers ====================
__device__ __forceinline__ uint32_t smem_u32(const void* p) {
    uint32_t a;
    asm("{ .reg .u64 t; cvta.to.shared.u64 t, %1; cvt.u32.u64 %0, t; }" : "=r"(a) : "l"(p));
    return a;
}
__device__ __forceinline__ uint32_t pack2h(__half a, __half b) {
    return (uint32_t)__half_as_ushort(a) | ((uint32_t)__half_as_ushort(b) << 16);
}
__device__ __forceinline__ void mma_f16(float& d0, float& d1, float& d2, float& d3,
                                        uint32_t a0, uint32_t a1, uint32_t a2, uint32_t a3,
                                        uint32_t b0, uint32_t b1) {
    asm volatile(
        "mma.sync.aligned.m16n8k16.row.col.f32.f16.f16.f32 "
        "{%0,%1,%2,%3}, {%4,%5,%6,%7}, {%8,%9}, {%0,%1,%2,%3};"
        : "+f"(d0), "+f"(d1), "+f"(d2), "+f"(d3)
        : "r"(a0), "r"(a1), "r"(a2), "r"(a3), "r"(b0), "r"(b1));
}
__device__ __forceinline__ void ldsm_x4(uint32_t& r0, uint32_t& r1, uint32_t& r2, uint32_t& r3, uint32_t a) {
    asm volatile("ldmatrix.sync.aligned.m8n8.x4.shared.b16 {%0,%1,%2,%3}, [%4];"
        : "=r"(r0), "=r"(r1), "=r"(r2), "=r"(r3) : "r"(a));
}
__device__ __forceinline__ void ldsm_x4_t(uint32_t& r0, uint32_t& r1, uint32_t& r2, uint32_t& r3, uint32_t a) {
    asm volatile("ldmatrix.sync.aligned.m8n8.x4.trans.shared.b16 {%0,%1,%2,%3}, [%4];"
        : "=r"(r0), "=r"(r1), "=r"(r2), "=r"(r3) : "r"(a));
}

// ==================== pre-pass: weight transpose+convert, x convert =====
__global__ __launch_bounds__(256)
void wt_kernel(const float* __restrict__ W, __half* __restrict__ WT, int K, int N)
{
    __shared__ __half t[32][33];
    const int n0 = blockIdx.x * 32, k0 = blockIdx.y * 32;
    const int tx = threadIdx.x & 31, ty = threadIdx.x >> 5;   // 32 x 8
#pragma unroll
    for (int i = 0; i < 4; i++)
        t[ty + i * 8][tx] = __float2half_rn(W[(size_t)(k0 + ty + i * 8) * N + n0 + tx]);
    __syncthreads();
#pragma unroll
    for (int i = 0; i < 4; i++)
        WT[(size_t)(n0 + ty + i * 8) * K + k0 + tx] = t[tx][ty + i * 8];
}

__global__ __launch_bounds__(256)
void hconv_kernel(const float* __restrict__ x, __half* __restrict__ xh)
{
    const size_t i = ((size_t)blockIdx.x * 256 + threadIdx.x) * 4;
    float4 v = *(const float4*)(x + i);
    uint2 p;
    p.x = pack2h(__float2half_rn(v.x), __float2half_rn(v.y));
    p.y = pack2h(__float2half_rn(v.z), __float2half_rn(v.w));
    *(uint2*)&xh[i] = p;
}

// ==================== HMMA GEMM (fp16 in, fp32 accum, ldmatrix) =========
// C = A[M,K](fp16) @ BT[N,K](fp16)^T + bias. CTA 128x128, BK=32, 8 warps.
// EPI 0: bias -> Ch (+Cl if non-null, hi/lo split of fp32 result)
// EPI 1: gelu(bias+x) -> Ch
// EPI 2: bias + residual -> C32

#define GP 40                    // padded halfs per 32-elem row (80B, 16B-aligned)
#define B_OFF 10240              // 128*80
#define STAGE 20480
#define GEMM_SMEM (2*STAGE)      // 40960 bytes

template<int EPI>
__global__ __launch_bounds__(256)
void gemm_hmma(const __half* __restrict__ A, const __half* __restrict__ BT,
               const float* __restrict__ bias, const float* __restrict__ res,
               float* __restrict__ C32, __half* __restrict__ Ch, __half* __restrict__ Cl,
               int M, int N, int K)
{
    extern __shared__ __half smh[];
    const int tid = threadIdx.x;
    const int m0 = blockIdx.y * 128, n0 = blockIdx.x * 128;

    const int wid = tid >> 5, lane = tid & 31;
    const int wm = wid >> 2, wn = wid & 3;
    const int g = lane >> 2, q = lane & 3;

    const int arow = tid >> 1;
    const int acol = (tid & 1) * 16;
    const int bn   = tid & 127;
    const int bks  = (tid >> 7) * 16;

    const int a_row_off = lane & 15;
    const int a_col_off = ((lane >> 4) << 3);
    const int b_row_off = (lane & 7) + ((lane >> 4) << 3);
    const int b_col_off = (lane & 8);

    float acc[4][4][4];
#pragma unroll
    for (int i = 0; i < 4; i++)
#pragma unroll
        for (int j = 0; j < 4; j++)
#pragma unroll
            for (int t = 0; t < 4; t++) acc[i][j][t] = 0.f;

    uint4 ar[2], br[2];
    auto load_regs = [&](int k0) {
        const __half* Ap = A + (size_t)(m0 + arow) * K + k0 + acol;
        ar[0] = *(const uint4*)Ap;
        ar[1] = *(const uint4*)(Ap + 8);
        const __half* Bp = BT + (size_t)(n0 + bn) * K + k0 + bks;
        br[0] = *(const uint4*)Bp;
        br[1] = *(const uint4*)(Bp + 8);
    };
    auto store_regs = [&](int sbase) {
        __half* sA = smh + sbase;
        __half* sB = smh + sbase + B_OFF / 2;
        *(uint4*)&sA[arow * GP + acol]     = ar[0];
        *(uint4*)&sA[arow * GP + acol + 8] = ar[1];
        *(uint4*)&sB[bn * GP + bks]        = br[0];
        *(uint4*)&sB[bn * GP + bks + 8]    = br[1];
    };
    auto compute_stage = [&](int sbase) {
        const __half* sA = smh + sbase;
        const __half* sB = smh + sbase + B_OFF / 2;
#pragma unroll
        for (int kk = 0; kk < 2; kk++) {
            uint32_t af[4][4];
#pragma unroll
            for (int mt = 0; mt < 4; mt++) {
                uint32_t a = smem_u32(&sA[(wm * 64 + mt * 16 + a_row_off) * GP + kk * 16 + a_col_off]);
                ldsm_x4(af[mt][0], af[mt][1], af[mt][2], af[mt][3], a);
            }
#pragma unroll
            for (int np = 0; np < 2; np++) {
                uint32_t r0, r1, r2, r3;
                uint32_t a = smem_u32(&sB[(wn * 32 + np * 16 + b_row_off) * GP + kk * 16 + b_col_off]);
                ldsm_x4(r0, r1, r2, r3, a);
#pragma unroll
                for (int mt = 0; mt < 4; mt++) {
                    mma_f16(acc[mt][2*np][0], acc[mt][2*np][1], acc[mt][2*np][2], acc[mt][2*np][3],
                            af[mt][0], af[mt][1], af[mt][2], af[mt][3], r0, r1);
                    mma_f16(acc[mt][2*np+1][0], acc[mt][2*np+1][1], acc[mt][2*np+1][2], acc[mt][2*np+1][3],
                            af[mt][0], af[mt][1], af[mt][2], af[mt][3], r2, r3);
                }
            }
        }
    };

    load_regs(0);
    store_regs(0);
    __syncthreads();
    const int NC = K >> 5;
    for (int c = 0; c < NC; c++) {
        const int cur = (c & 1) * (STAGE / 2);
        if (c + 1 < NC) load_regs((c + 1) << 5);
        compute_stage(cur);
        if (c + 1 < NC) store_regs(((c + 1) & 1) * (STAGE / 2));
        __syncthreads();
    }

    // ---- epilogue ----
#pragma unroll
    for (int mt = 0; mt < 4; mt++) {
        const int r0 = m0 + wm * 64 + mt * 16 + g;
#pragma unroll
        for (int nt = 0; nt < 4; nt++) {
            const int col = n0 + wn * 32 + nt * 8 + q * 2;
            float b0 = bias[col], b1 = bias[col + 1];
#pragma unroll
            for (int h = 0; h < 2; h++) {
                const int row = r0 + h * 8;
                float v0 = acc[mt][nt][h * 2 + 0] + b0;
                float v1 = acc[mt][nt][h * 2 + 1] + b1;
                if (EPI == 1) {
                    v0 = 0.5f * v0 * (1.0f + erff(v0 * 0.70710678118654752440f));
                    v1 = 0.5f * v1 * (1.0f + erff(v1 * 0.70710678118654752440f));
                }
                if (EPI == 0 || EPI == 1) {
                    __half h0 = __float2half_rn(v0), h1 = __float2half_rn(v1);
                    *(uint32_t*)&Ch[(size_t)row * N + col] = pack2h(h0, h1);
                    if (EPI == 0 && Cl) {
                        __half l0 = __float2half_rn(v0 - __half2float(h0));
                        __half l1 = __float2half_rn(v1 - __half2float(h1));
                        *(uint32_t*)&Cl[(size_t)row * N + col] = pack2h(l0, l1);
                    }
                } else {
                    float2 r2 = *(const float2*)(res + (size_t)row * N + col);
                    *(float2*)(C32 + (size_t)row * N + col) = make_float2(v0 + r2.x, v1 + r2.y);
                }
            }
        }
    }
}

// ==================== flash attention (fp16 in/out, HMMA) ===============
// CTA: (b, h, 64 q rows); 4 warps x 16 q rows. kv tiles of 64.
#define APAD 72    // halfs per smem row (144 B, 16B-aligned)

__global__ __launch_bounds__(128)
void attn_kernel(const __half* __restrict__ Qhg, const __half* __restrict__ Qlg,
                 const __half* __restrict__ Khg,
                 const __half* __restrict__ Vhg, const __half* __restrict__ Vlg,
                 const float* __restrict__ mask, __half* __restrict__ O)
{
    __shared__ __align__(16) __half Qh[64*APAD];
    __shared__ __align__(16) __half Ql[64*APAD];
    __shared__ __align__(16) __half Ksm[64*APAD];
    __shared__ __align__(16) __half Vh[64*APAD];
    __shared__ __align__(16) __half Vl[64*APAD];
    __shared__ float msk[64];

    const int qt = blockIdx.x, h = blockIdx.y, b = blockIdx.z;
    const int tid = threadIdx.x;
    const int wid = tid >> 5, lane = tid & 31;
    const int g = lane >> 2, t4 = lane & 3;
    const int q0 = qt * 64;
    const int base = (b * SS) * HH + h * HDIM;
    const int w16 = wid * 16;

    // ---- stage Q (pre-split hi/lo from global) ----
    {
        const int r = tid >> 1, c0 = (tid & 1) * 32;
        const __half* Qp = Qhg + base + (size_t)(q0 + r) * HH + c0;
        const __half* Lp = Qlg + base + (size_t)(q0 + r) * HH + c0;
#pragma unroll
        for (int i = 0; i < 4; i++) {
            *(uint4*)&Qh[r * APAD + c0 + i * 8] = *(const uint4*)(Qp + i * 8);
            *(uint4*)&Ql[r * APAD + c0 + i * 8] = *(const uint4*)(Lp + i * 8);
        }
    }
    __syncthreads();

    // ---- per-warp Q fragments (4 k16 steps) ----
    uint32_t qhf[4][4], qlf[4][4];
    {
        const int row = w16 + (lane & 15);
        const int colb = (lane >> 4) << 3;
#pragma unroll
        for (int kk = 0; kk < 4; kk++) {
            uint32_t a = smem_u32(&Qh[row * APAD + kk * 16 + colb]);
            ldsm_x4(qhf[kk][0], qhf[kk][1], qhf[kk][2], qhf[kk][3], a);
            a = smem_u32(&Ql[row * APAD + kk * 16 + colb]);
            ldsm_x4(qlf[kk][0], qlf[kk][1], qlf[kk][2], qlf[kk][3], a);
        }
    }

    float oacc[8][4];
#pragma unroll
    for (int j = 0; j < 8; j++)
#pragma unroll
        for (int t = 0; t < 4; t++) oacc[j][t] = 0.f;
    float m0 = -1e30f, m1 = -1e30f, l0 = 0.f, l1 = 0.f;

    const int krow_off = (lane & 7) + ((lane >> 4) << 3);
    const int kcol_off = (lane & 8);
    const int vrow_off = (lane & 7) + (lane & 8);
    const int vcol_off = ((lane >> 4) << 3);

    for (int kt = 0; kt < SS; kt += 64) {
        __syncthreads();
        {
            const int r = tid >> 1, c0 = (tid & 1) * 32;
            const __half* Kp  = Khg + base + (size_t)(kt + r) * HH + c0;
            const __half* Vhp = Vhg + base + (size_t)(kt + r) * HH + c0;
            const __half* Vlp = Vlg + base + (size_t)(kt + r) * HH + c0;
#pragma unroll
            for (int i = 0; i < 4; i++) {
                *(uint4*)&Ksm[r * APAD + c0 + i * 8] = *(const uint4*)(Kp + i * 8);
                *(uint4*)&Vh[r * APAD + c0 + i * 8]  = *(const uint4*)(Vhp + i * 8);
                *(uint4*)&Vl[r * APAD + c0 + i * 8]  = *(const uint4*)(Vlp + i * 8);
            }
            if (tid < 64) msk[tid] = mask[b * SS + kt + tid];
        }
        __syncthreads();

        float sacc[8][4];
#pragma unroll
        for (int j = 0; j < 8; j++)
#pragma unroll
            for (int t = 0; t < 4; t++) sacc[j][t] = 0.f;
#pragma unroll
        for (int jp = 0; jp < 4; jp++) {
#pragma unroll
            for (int kk = 0; kk < 4; kk++) {
                uint32_t r0, r1, r2, r3;
                uint32_t a = smem_u32(&Ksm[(jp * 16 + krow_off) * APAD + kk * 16 + kcol_off]);
                ldsm_x4(r0, r1, r2, r3, a);
                mma_f16(sacc[2*jp][0], sacc[2*jp][1], sacc[2*jp][2], sacc[2*jp][3],
                        qhf[kk][0], qhf[kk][1], qhf[kk][2], qhf[kk][3], r0, r1);
                mma_f16(sacc[2*jp][0], sacc[2*jp][1], sacc[2*jp][2], sacc[2*jp][3],
                        qlf[kk][0], qlf[kk][1], qlf[kk][2], qlf[kk][3], r0, r1);
                mma_f16(sacc[2*jp+1][0], sacc[2*jp+1][1], sacc[2*jp+1][2], sacc[2*jp+1][3],
                        qhf[kk][0], qhf[kk][1], qhf[kk][2], qhf[kk][3], r2, r3);
                mma_f16(sacc[2*jp+1][0], sacc[2*jp+1][1], sacc[2*jp+1][2], sacc[2*jp+1][3],
                        qlf[kk][0], qlf[kk][1], qlf[kk][2], qlf[kk][3], r2, r3);
            }
        }

        float tm0 = -1e30f, tm1 = -1e30f;
#pragma unroll
        for (int j = 0; j < 8; j++) {
            const float mv0 = msk[j * 8 + 2 * t4], mv1 = msk[j * 8 + 2 * t4 + 1];
            sacc[j][0] = sacc[j][0] * 0.125f + mv0;
            sacc[j][1] = sacc[j][1] * 0.125f + mv1;
            sacc[j][2] = sacc[j][2] * 0.125f + mv0;
            sacc[j][3] = sacc[j][3] * 0.125f + mv1;
            tm0 = fmaxf(tm0, fmaxf(sacc[j][0], sacc[j][1]));
            tm1 = fmaxf(tm1, fmaxf(sacc[j][2], sacc[j][3]));
        }
        tm0 = fmaxf(tm0, __shfl_xor_sync(0xffffffffu, tm0, 1));
        tm0 = fmaxf(tm0, __shfl_xor_sync(0xffffffffu, tm0, 2));
        tm1 = fmaxf(tm1, __shfl_xor_sync(0xffffffffu, tm1, 1));
        tm1 = fmaxf(tm1, __shfl_xor_sync(0xffffffffu, tm1, 2));
        const float mn0 = fmaxf(m0, tm0), mn1 = fmaxf(m1, tm1);
        const float al0 = __expf(m0 - mn0), al1 = __expf(m1 - mn1);
        m0 = mn0; m1 = mn1;
        float ls0 = 0.f, ls1 = 0.f;
#pragma unroll
        for (int j = 0; j < 8; j++) {
            sacc[j][0] = __expf(sacc[j][0] - mn0);
            sacc[j][1] = __expf(sacc[j][1] - mn0);
            sacc[j][2] = __expf(sacc[j][2] - mn1);
            sacc[j][3] = __expf(sacc[j][3] - mn1);
            ls0 += sacc[j][0] + sacc[j][1];
            ls1 += sacc[j][2] + sacc[j][3];
        }
        l0 = l0 * al0 + ls0;
        l1 = l1 * al1 + ls1;
#pragma unroll
        for (int j = 0; j < 8; j++) {
            oacc[j][0] *= al0; oacc[j][1] *= al0;
            oacc[j][2] *= al1; oacc[j][3] *= al1;
        }

        uint32_t pf[4][4];
#pragma unroll
        for (int kk = 0; kk < 4; kk++) {
            pf[kk][0] = pack2h(__float2half_rn(sacc[2*kk][0]),   __float2half_rn(sacc[2*kk][1]));
            pf[kk][1] = pack2h(__float2half_rn(sacc[2*kk][2]),   __float2half_rn(sacc[2*kk][3]));
            pf[kk][2] = pack2h(__float2half_rn(sacc[2*kk+1][0]), __float2half_rn(sacc[2*kk+1][1]));
            pf[kk][3] = pack2h(__float2half_rn(sacc[2*kk+1][2]), __float2half_rn(sacc[2*kk+1][3]));
        }

#pragma unroll
        for (int dp = 0; dp < 4; dp++) {
#pragma unroll
            for (int kk = 0; kk < 4; kk++) {
                uint32_t r0, r1, r2, r3;
                uint32_t a = smem_u32(&Vh[(kk * 16 + vrow_off) * APAD + dp * 16 + vcol_off]);
                ldsm_x4_t(r0, r1, r2, r3, a);
                mma_f16(oacc[2*dp][0], oacc[2*dp][1], oacc[2*dp][2], oacc[2*dp][3],
                        pf[kk][0], pf[kk][1], pf[kk][2], pf[kk][3], r0, r1);
                mma_f16(oacc[2*dp+1][0], oacc[2*dp+1][1], oacc[2*dp+1][2], oacc[2*dp+1][3],
                        pf[kk][0], pf[kk][1], pf[kk][2], pf[kk][3], r2, r3);
                a = smem_u32(&Vl[(kk * 16 + vrow_off) * APAD + dp * 16 + vcol_off]);
                ldsm_x4_t(r0, r1, r2, r3, a);
                mma_f16(oacc[2*dp][0], oacc[2*dp][1], oacc[2*dp][2], oacc[2*dp][3],
                        pf[kk][0], pf[kk][1], pf[kk][2], pf[kk][3], r0, r1);
                mma_f16(oacc[2*dp+1][0], oacc[2*dp+1][1], oacc[2*dp+1][2], oacc[2*dp+1][3],
                        pf[kk][0], pf[kk][1], pf[kk][2], pf[kk][3], r2, r3);
            }
        }
    }

    l0 += __shfl_xor_sync(0xffffffffu, l0, 1);
    l0 += __shfl_xor_sync(0xffffffffu, l0, 2);
    l1 += __shfl_xor_sync(0xffffffffu, l1, 1);
    l1 += __shfl_xor_sync(0xffffffffu, l1, 2);
    const float inv0 = 1.f / l0, inv1 = 1.f / l1;
    const int row0 = q0 + w16 + g;
#pragma unroll
    for (int j = 0; j < 8; j++) {
        const int col = j * 8 + 2 * t4;
        *(uint32_t*)&O[base + (size_t)row0 * HH + col] =
            pack2h(__float2half_rn(oacc[j][0] * inv0), __float2half_rn(oacc[j][1] * inv0));
        *(uint32_t*)&O[base + (size_t)(row0 + 8) * HH + col] =
            pack2h(__float2half_rn(oacc[j][2] * inv1), __float2half_rn(oacc[j][3] * inv1));
    }
}

// ---------------- layernorm (fp32 out + optional fp16 out) --------------
__global__ __launch_bounds__(256)
void ln_kernel(const float* __restrict__ x, const float* __restrict__ g,
               const float* __restrict__ bt, float* __restrict__ y,
               __half* __restrict__ yh)
{
    const int row = blockIdx.x;
    const int tid = threadIdx.x;
    const int c = tid * 4;
    const float* xr = x + (size_t)row * HH;
    float4 v4 = *(const float4*)(xr + c);
    float v[4] = {v4.x, v4.y, v4.z, v4.w};
    float s = v[0] + v[1] + v[2] + v[3];

    __shared__ float smr[8];
    __shared__ float mu_s, var_s;
#pragma unroll
    for (int o = 16; o; o >>= 1) s += __shfl_xor_sync(0xffffffffu, s, o);
    if ((tid & 31) == 0) smr[tid >> 5] = s;
    __syncthreads();
    if (tid < 32) {
        float t = (tid < 8) ? smr[tid] : 0.f;
#pragma unroll
        for (int o = 4; o; o >>= 1) t += __shfl_xor_sync(0xffffffffu, t, o);
        if (tid == 0) mu_s = t * (1.f / HH);
    }
    __syncthreads();
    const float mu = mu_s;
    float s2 = 0.f;
#pragma unroll
    for (int i = 0; i < 4; i++) { float d = v[i] - mu; s2 += d * d; }
#pragma unroll
    for (int o = 16; o; o >>= 1) s2 += __shfl_xor_sync(0xffffffffu, s2, o);
    __syncthreads();
    if ((tid & 31) == 0) smr[tid >> 5] = s2;
    __syncthreads();
    if (tid < 32) {
        float t = (tid < 8) ? smr[tid] : 0.f;
#pragma unroll
        for (int o = 4; o; o >>= 1) t += __shfl_xor_sync(0xffffffffu, t, o);
        if (tid == 0) var_s = t * (1.f / HH);
    }
    __syncthreads();
    const float inv = rsqrtf(var_s + 1e-5f);
    float4 g4 = *(const float4*)(g + c);
    float4 b4 = *(const float4*)(bt + c);
    float4 r4;
    r4.x = (v[0] - mu) * inv * g4.x + b4.x;
    r4.y = (v[1] - mu) * inv * g4.y + b4.y;
    r4.z = (v[2] - mu) * inv * g4.z + b4.z;
    r4.w = (v[3] - mu) * inv * g4.w + b4.w;
    *(float4*)(y + (size_t)row * HH + c) = r4;
    if (yh) {
        uint2 p;
        p.x = pack2h(__float2half_rn(r4.x), __float2half_rn(r4.y));
        p.y = pack2h(__float2half_rn(r4.z), __float2half_rn(r4.w));
        *(uint2*)&yh[(size_t)row * HH + c] = p;
    }
}

// ---------------- host ----------------
extern "C" void kernel_launch(void* const* d_in, const int* in_sizes, int n_in,
                              void* d_out, int out_size)
{
    (void)in_sizes; (void)n_in; (void)out_size;
    const float* x     = (const float*)d_in[0];
    const float* mask  = (const float*)d_in[1];
    const float* wq    = (const float*)d_in[2];
    const float* bq    = (const float*)d_in[3];
    const float* wk    = (const float*)d_in[4];
    const float* bk    = (const float*)d_in[5];
    const float* wv    = (const float*)d_in[6];
    const float* bv    = (const float*)d_in[7];
    const float* wo    = (const float*)d_in[8];
    const float* bo    = (const float*)d_in[9];
    const float* ln1g  = (const float*)d_in[10];
    const float* ln1b  = (const float*)d_in[11];
    const float* wi    = (const float*)d_in[12];
    const float* bi    = (const float*)d_in[13];
    const float* wo2   = (const float*)d_in[14];
    const float* bo2   = (const float*)d_in[15];
    const float* ln2g  = (const float*)d_in[16];
    const float* ln2b  = (const float*)d_in[17];
    float* out = (float*)d_out;

    __half *xh, *wqT, *wkT, *wvT, *woT, *wiT, *wo2T;
    __half *qh, *ql, *kh, *vh, *vl, *ctxh, *attnh, *interh;
    float *t1, *attn32, *t2;
    cudaGetSymbolAddress((void**)&xh,     g_xh);
    cudaGetSymbolAddress((void**)&wqT,    g_wqT);
    cudaGetSymbolAddress((void**)&wkT,    g_wkT);
    cudaGetSymbolAddress((void**)&wvT,    g_wvT);
    cudaGetSymbolAddress((void**)&woT,    g_woT);
    cudaGetSymbolAddress((void**)&wiT,    g_wiT);
    cudaGetSymbolAddress((void**)&wo2T,   g_wo2T);
    cudaGetSymbolAddress((void**)&qh,     g_qh);
    cudaGetSymbolAddress((void**)&ql,     g_ql);
    cudaGetSymbolAddress((void**)&kh,     g_kh);
    cudaGetSymbolAddress((void**)&vh,     g_vh);
    cudaGetSymbolAddress((void**)&vl,     g_vl);
    cudaGetSymbolAddress((void**)&ctxh,   g_ctxh);
    cudaGetSymbolAddress((void**)&attnh,  g_attnh);
    cudaGetSymbolAddress((void**)&interh, g_interh);
    cudaGetSymbolAddress((void**)&t1,     g_t1);
    cudaGetSymbolAddress((void**)&attn32, g_attn32);
    cudaGetSymbolAddress((void**)&t2,     g_t2);

    cudaFuncSetAttribute(gemm_hmma<0>, cudaFuncAttributeMaxDynamicSharedMemorySize, GEMM_SMEM);
    cudaFuncSetAttribute(gemm_hmma<1>, cudaFuncAttributeMaxDynamicSharedMemorySize, GEMM_SMEM);
    cudaFuncSetAttribute(gemm_hmma<2>, cudaFuncAttributeMaxDynamicSharedMemorySize, GEMM_SMEM);

    // ---- pre-pass: convert weights (transposed) and x to fp16 ----
    wt_kernel<<<dim3(HH / 32, HH / 32), 256>>>(wq, wqT, HH, HH);
    wt_kernel<<<dim3(HH / 32, HH / 32), 256>>>(wk, wkT, HH, HH);
    wt_kernel<<<dim3(HH / 32, HH / 32), 256>>>(wv, wvT, HH, HH);
    wt_kernel<<<dim3(HH / 32, HH / 32), 256>>>(wo, woT, HH, HH);
    wt_kernel<<<dim3(FFD / 32, HH / 32), 256>>>(wi, wiT, HH, FFD);
    wt_kernel<<<dim3(HH / 32, FFD / 32), 256>>>(wo2, wo2T, FFD, HH);
    hconv_kernel<<<MTOK * HH / 1024, 256>>>(x, xh);

    const dim3 blkG(256);
    const dim3 gH(HH / 128, MTOK / 128);
    const dim3 gF(FFD / 128, MTOK / 128);

    // QKV projections (fp16 outputs; q and v with hi/lo split)
    gemm_hmma<0><<<gH, blkG, GEMM_SMEM>>>(xh, wqT, bq, nullptr, nullptr, qh, ql, MTOK, HH, HH);
    gemm_hmma<0><<<gH, blkG, GEMM_SMEM>>>(xh, wkT, bk, nullptr, nullptr, kh, nullptr, MTOK, HH, HH);
    gemm_hmma<0><<<gH, blkG, GEMM_SMEM>>>(xh, wvT, bv, nullptr, nullptr, vh, vl, MTOK, HH, HH);

    // attention (fp16 in, fp16 ctx out)
    attn_kernel<<<dim3(SS / 64, NHEAD, BB), dim3(128)>>>(qh, ql, kh, vh, vl, mask, ctxh);

    // output proj + residual, LN1
    gemm_hmma<2><<<gH, blkG, GEMM_SMEM>>>(ctxh, woT, bo, x, t1, nullptr, nullptr, MTOK, HH, HH);
    ln_kernel<<<MTOK, dim3(256)>>>(t1, ln1g, ln1b, attn32, attnh);

    // FFN
    gemm_hmma<1><<<gF, blkG, GEMM_SMEM>>>(attnh, wiT, bi, nullptr, nullptr, interh, nullptr, MTOK, FFD, HH);
    gemm_hmma<2><<<gH, blkG, GEMM_SMEM>>>(interh, wo2T, bo2, attn32, t2, nullptr, nullptr, MTOK, HH, FFD);
    ln_kernel<<<MTOK, dim3(256)>>>(t2, ln2g, ln2b, out, nullptr);
}

// round 9
// speedup vs baseline: 6.2995x; 1.3057x over previous
#include <cuda_runtime.h>
#include <cuda_fp16.h>
#include <cstdint>
#include <math.h>

#define BB 8
#define SS 512
#define HH 1024
#define NHEAD 16
#define HDIM 64
#define FFD 4096
#define MTOK (BB*SS)   // 4096 tokens

// ---------------- scratch (static __device__, no allocs) ----------------
__device__ __half g_xh[MTOK*HH];
__device__ __half g_wqT[HH*HH];
__device__ __half g_wkT[HH*HH];
__device__ __half g_wvT[HH*HH];
__device__ __half g_woT[HH*HH];
__device__ __half g_wiT[(size_t)HH*FFD];    // [FFD][HH]
__device__ __half g_wo2T[(size_t)FFD*HH];   // [HH][FFD]
__device__ __half g_qh[MTOK*HH];
__device__ __half g_ql[MTOK*HH];
__device__ __half g_kh[MTOK*HH];
__device__ __half g_vh[MTOK*HH];
__device__ __half g_vl[MTOK*HH];
__device__ __half g_ctxh[MTOK*HH];
__device__ float  g_t1[MTOK*HH];
__device__ float  g_attn32[MTOK*HH];
__device__ __half g_attnh[MTOK*HH];
__device__ __half g_interh[(size_t)MTOK*FFD];
__device__ float  g_t2[MTOK*HH];

// ==================== helpers ====================
__device__ __forceinline__ uint32_t smem_u32(const void* p) {
    uint32_t a;
    asm("{ .reg .u64 t; cvta.to.shared.u64 t, %1; cvt.u32.u64 %0, t; }" : "=r"(a) : "l"(p));
    return a;
}
__device__ __forceinline__ uint32_t pack2h(__half a, __half b) {
    return (uint32_t)__half_as_ushort(a) | ((uint32_t)__half_as_ushort(b) << 16);
}
__device__ __forceinline__ void mma_f16(float& d0, float& d1, float& d2, float& d3,
                                        uint32_t a0, uint32_t a1, uint32_t a2, uint32_t a3,
                                        uint32_t b0, uint32_t b1) {
    asm volatile(
        "mma.sync.aligned.m16n8k16.row.col.f32.f16.f16.f32 "
        "{%0,%1,%2,%3}, {%4,%5,%6,%7}, {%8,%9}, {%0,%1,%2,%3};"
        : "+f"(d0), "+f"(d1), "+f"(d2), "+f"(d3)
        : "r"(a0), "r"(a1), "r"(a2), "r"(a3), "r"(b0), "r"(b1));
}
__device__ __forceinline__ void ldsm_x4(uint32_t& r0, uint32_t& r1, uint32_t& r2, uint32_t& r3, uint32_t a) {
    asm volatile("ldmatrix.sync.aligned.m8n8.x4.shared.b16 {%0,%1,%2,%3}, [%4];"
        : "=r"(r0), "=r"(r1), "=r"(r2), "=r"(r3) : "r"(a));
}
__device__ __forceinline__ void ldsm_x4_t(uint32_t& r0, uint32_t& r1, uint32_t& r2, uint32_t& r3, uint32_t a) {
    asm volatile("ldmatrix.sync.aligned.m8n8.x4.trans.shared.b16 {%0,%1,%2,%3}, [%4];"
        : "=r"(r0), "=r"(r1), "=r"(r2), "=r"(r3) : "r"(a));
}
#define CP_ASYNC16(s, g) asm volatile("cp.async.cg.shared.global [%0], [%1], 16;" :: "r"(s), "l"(g))
#define CP_COMMIT()      asm volatile("cp.async.commit_group;" ::: "memory")
#define CP_WAIT(n)       asm volatile("cp.async.wait_group %0;" :: "n"(n) : "memory")

// ==================== pre-pass: weight transpose+convert, x convert =====
__global__ __launch_bounds__(256)
void wt_kernel(const float* __restrict__ W, __half* __restrict__ WT, int K, int N)
{
    __shared__ __half t[32][33];
    const int n0 = blockIdx.x * 32, k0 = blockIdx.y * 32;
    const int tx = threadIdx.x & 31, ty = threadIdx.x >> 5;   // 32 x 8
#pragma unroll
    for (int i = 0; i < 4; i++)
        t[ty + i * 8][tx] = __float2half_rn(W[(size_t)(k0 + ty + i * 8) * N + n0 + tx]);
    __syncthreads();
#pragma unroll
    for (int i = 0; i < 4; i++)
        WT[(size_t)(n0 + ty + i * 8) * K + k0 + tx] = t[tx][ty + i * 8];
}

__global__ __launch_bounds__(256)
void hconv_kernel(const float* __restrict__ x, __half* __restrict__ xh)
{
    const size_t i = ((size_t)blockIdx.x * 256 + threadIdx.x) * 4;
    float4 v = *(const float4*)(x + i);
    uint2 p;
    p.x = pack2h(__float2half_rn(v.x), __float2half_rn(v.y));
    p.y = pack2h(__float2half_rn(v.z), __float2half_rn(v.w));
    *(uint2*)&xh[i] = p;
}

// ==================== HMMA GEMM (fp16 in, fp32 accum) ===================
// C = A[M,K](fp16) @ BT[N,K](fp16)^T + bias. CTA 128x128, BK=32.
// 4 warps (2m x 2n), warp tile 64x64. cp.async 3-stage pipeline.
// EPI 0: bias -> Ch (+Cl if non-null). EPI 1: gelu -> Ch. EPI 2: +res -> C32.

#define GP 40                    // padded halfs per 32-elem row (80B, 16B-aligned)
#define BH_H 5120                // sB offset in halfs (128*40)
#define ST_H 10240               // stage size in halfs (20480 B)
#define NSTAGE 3
#define GEMM_SMEM (NSTAGE*ST_H*2)   // 61440 bytes

template<int EPI>
__global__ __launch_bounds__(128)
void gemm_hmma(const __half* __restrict__ A, const __half* __restrict__ BT,
               const float* __restrict__ bias, const float* __restrict__ res,
               float* __restrict__ C32, __half* __restrict__ Ch, __half* __restrict__ Cl,
               int M, int N, int K)
{
    extern __shared__ __half smh[];
    const int tid = threadIdx.x;
    const int m0 = blockIdx.y * 128, n0 = blockIdx.x * 128;

    const int wid = tid >> 5, lane = tid & 31;
    const int wm = wid >> 1, wn = wid & 1;      // warp grid 2x2, tile 64x64
    const int g = lane >> 2, q = lane & 3;

    const int a_row_off = lane & 15;
    const int a_col_off = ((lane >> 4) << 3);
    const int b_row_off = (lane & 7) + ((lane >> 4) << 3);
    const int b_col_off = (lane & 8);

    float acc[4][8][4];
#pragma unroll
    for (int i = 0; i < 4; i++)
#pragma unroll
        for (int j = 0; j < 8; j++)
#pragma unroll
            for (int t = 0; t < 4; t++) acc[i][j][t] = 0.f;

    // ---- cp.async stage loader: A tile [128][32], B tile [128][32] ----
    auto load_stage = [&](int k0, int buf) {
        __half* sA = smh + buf * ST_H;
        __half* sB = sA + BH_H;
#pragma unroll
        for (int i = 0; i < 4; i++) {
            const int lin = i * 128 + tid;
            const int row = lin >> 2, ch = (lin & 3) * 8;
            CP_ASYNC16(smem_u32(&sA[row * GP + ch]), A  + (size_t)(m0 + row) * K + k0 + ch);
            CP_ASYNC16(smem_u32(&sB[row * GP + ch]), BT + (size_t)(n0 + row) * K + k0 + ch);
        }
        CP_COMMIT();
    };

    auto compute_stage = [&](int buf) {
        const __half* sA = smh + buf * ST_H;
        const __half* sB = sA + BH_H;
#pragma unroll
        for (int kk = 0; kk < 2; kk++) {
            uint32_t af[4][4];
#pragma unroll
            for (int mt = 0; mt < 4; mt++) {
                uint32_t a = smem_u32(&sA[(wm * 64 + mt * 16 + a_row_off) * GP + kk * 16 + a_col_off]);
                ldsm_x4(af[mt][0], af[mt][1], af[mt][2], af[mt][3], a);
            }
#pragma unroll
            for (int nt = 0; nt < 4; nt++) {
                uint32_t r0, r1, r2, r3;
                uint32_t a = smem_u32(&sB[(wn * 64 + nt * 16 + b_row_off) * GP + kk * 16 + b_col_off]);
                ldsm_x4(r0, r1, r2, r3, a);
#pragma unroll
                for (int mt = 0; mt < 4; mt++) {
                    mma_f16(acc[mt][2*nt][0], acc[mt][2*nt][1], acc[mt][2*nt][2], acc[mt][2*nt][3],
                            af[mt][0], af[mt][1], af[mt][2], af[mt][3], r0, r1);
                    mma_f16(acc[mt][2*nt+1][0], acc[mt][2*nt+1][1], acc[mt][2*nt+1][2], acc[mt][2*nt+1][3],
                            af[mt][0], af[mt][1], af[mt][2], af[mt][3], r2, r3);
                }
            }
        }
    };

    // ---- 3-stage pipeline ----
    const int NC = K >> 5;
    load_stage(0, 0);
    load_stage(32, 1);
    for (int c = 0; c < NC; c++) {
        CP_WAIT(1);
        __syncthreads();
        if (c + 2 < NC) load_stage((c + 2) << 5, (c + 2) % NSTAGE);
        compute_stage(c % NSTAGE);
    }

    // ---- epilogue: warp tile 64x64 ----
#pragma unroll
    for (int mt = 0; mt < 4; mt++) {
        const int r0 = m0 + wm * 64 + mt * 16 + g;
#pragma unroll
        for (int nj = 0; nj < 8; nj++) {
            const int col = n0 + wn * 64 + nj * 8 + q * 2;
            float b0 = bias[col], b1 = bias[col + 1];
#pragma unroll
            for (int h = 0; h < 2; h++) {
                const int row = r0 + h * 8;
                float v0 = acc[mt][nj][h * 2 + 0] + b0;
                float v1 = acc[mt][nj][h * 2 + 1] + b1;
                if (EPI == 1) {
                    v0 = 0.5f * v0 * (1.0f + erff(v0 * 0.70710678118654752440f));
                    v1 = 0.5f * v1 * (1.0f + erff(v1 * 0.70710678118654752440f));
                }
                if (EPI == 0 || EPI == 1) {
                    __half h0 = __float2half_rn(v0), h1 = __float2half_rn(v1);
                    *(uint32_t*)&Ch[(size_t)row * N + col] = pack2h(h0, h1);
                    if (EPI == 0 && Cl) {
                        __half l0 = __float2half_rn(v0 - __half2float(h0));
                        __half l1 = __float2half_rn(v1 - __half2float(h1));
                        *(uint32_t*)&Cl[(size_t)row * N + col] = pack2h(l0, l1);
                    }
                } else {
                    float2 r2 = *(const float2*)(res + (size_t)row * N + col);
                    *(float2*)(C32 + (size_t)row * N + col) = make_float2(v0 + r2.x, v1 + r2.y);
                }
            }
        }
    }
}

// ==================== flash attention (fp16 in/out, HMMA) ===============
// CTA: (b, h, 64 q rows); 4 warps x 16 q rows. kv tiles of 64.
#define APAD 72    // halfs per smem row (144 B, 16B-aligned)

__global__ __launch_bounds__(128)
void attn_kernel(const __half* __restrict__ Qhg, const __half* __restrict__ Qlg,
                 const __half* __restrict__ Khg,
                 const __half* __restrict__ Vhg, const __half* __restrict__ Vlg,
                 const float* __restrict__ mask, __half* __restrict__ O)
{
    __shared__ __align__(16) __half Qh[64*APAD];
    __shared__ __align__(16) __half Ql[64*APAD];
    __shared__ __align__(16) __half Ksm[64*APAD];
    __shared__ __align__(16) __half Vh[64*APAD];
    __shared__ __align__(16) __half Vl[64*APAD];
    __shared__ float msk[64];

    const int qt = blockIdx.x, h = blockIdx.y, b = blockIdx.z;
    const int tid = threadIdx.x;
    const int wid = tid >> 5, lane = tid & 31;
    const int g = lane >> 2, t4 = lane & 3;
    const int q0 = qt * 64;
    const int base = (b * SS) * HH + h * HDIM;
    const int w16 = wid * 16;

    {
        const int r = tid >> 1, c0 = (tid & 1) * 32;
        const __half* Qp = Qhg + base + (size_t)(q0 + r) * HH + c0;
        const __half* Lp = Qlg + base + (size_t)(q0 + r) * HH + c0;
#pragma unroll
        for (int i = 0; i < 4; i++) {
            *(uint4*)&Qh[r * APAD + c0 + i * 8] = *(const uint4*)(Qp + i * 8);
            *(uint4*)&Ql[r * APAD + c0 + i * 8] = *(const uint4*)(Lp + i * 8);
        }
    }
    __syncthreads();

    uint32_t qhf[4][4], qlf[4][4];
    {
        const int row = w16 + (lane & 15);
        const int colb = (lane >> 4) << 3;
#pragma unroll
        for (int kk = 0; kk < 4; kk++) {
            uint32_t a = smem_u32(&Qh[row * APAD + kk * 16 + colb]);
            ldsm_x4(qhf[kk][0], qhf[kk][1], qhf[kk][2], qhf[kk][3], a);
            a = smem_u32(&Ql[row * APAD + kk * 16 + colb]);
            ldsm_x4(qlf[kk][0], qlf[kk][1], qlf[kk][2], qlf[kk][3], a);
        }
    }

    float oacc[8][4];
#pragma unroll
    for (int j = 0; j < 8; j++)
#pragma unroll
        for (int t = 0; t < 4; t++) oacc[j][t] = 0.f;
    float m0 = -1e30f, m1 = -1e30f, l0 = 0.f, l1 = 0.f;

    const int krow_off = (lane & 7) + ((lane >> 4) << 3);
    const int kcol_off = (lane & 8);
    const int vrow_off = (lane & 7) + (lane & 8);
    const int vcol_off = ((lane >> 4) << 3);

    for (int kt = 0; kt < SS; kt += 64) {
        __syncthreads();
        {
            const int r = tid >> 1, c0 = (tid & 1) * 32;
            const __half* Kp  = Khg + base + (size_t)(kt + r) * HH + c0;
            const __half* Vhp = Vhg + base + (size_t)(kt + r) * HH + c0;
            const __half* Vlp = Vlg + base + (size_t)(kt + r) * HH + c0;
#pragma unroll
            for (int i = 0; i < 4; i++) {
                *(uint4*)&Ksm[r * APAD + c0 + i * 8] = *(const uint4*)(Kp + i * 8);
                *(uint4*)&Vh[r * APAD + c0 + i * 8]  = *(const uint4*)(Vhp + i * 8);
                *(uint4*)&Vl[r * APAD + c0 + i * 8]  = *(const uint4*)(Vlp + i * 8);
            }
            if (tid < 64) msk[tid] = mask[b * SS + kt + tid];
        }
        __syncthreads();

        float sacc[8][4];
#pragma unroll
        for (int j = 0; j < 8; j++)
#pragma unroll
            for (int t = 0; t < 4; t++) sacc[j][t] = 0.f;
#pragma unroll
        for (int jp = 0; jp < 4; jp++) {
#pragma unroll
            for (int kk = 0; kk < 4; kk++) {
                uint32_t r0, r1, r2, r3;
                uint32_t a = smem_u32(&Ksm[(jp * 16 + krow_off) * APAD + kk * 16 + kcol_off]);
                ldsm_x4(r0, r1, r2, r3, a);
                mma_f16(sacc[2*jp][0], sacc[2*jp][1], sacc[2*jp][2], sacc[2*jp][3],
                        qhf[kk][0], qhf[kk][1], qhf[kk][2], qhf[kk][3], r0, r1);
                mma_f16(sacc[2*jp][0], sacc[2*jp][1], sacc[2*jp][2], sacc[2*jp][3],
                        qlf[kk][0], qlf[kk][1], qlf[kk][2], qlf[kk][3], r0, r1);
                mma_f16(sacc[2*jp+1][0], sacc[2*jp+1][1], sacc[2*jp+1][2], sacc[2*jp+1][3],
                        qhf[kk][0], qhf[kk][1], qhf[kk][2], qhf[kk][3], r2, r3);
                mma_f16(sacc[2*jp+1][0], sacc[2*jp+1][1], sacc[2*jp+1][2], sacc[2*jp+1][3],
                        qlf[kk][0], qlf[kk][1], qlf[kk][2], qlf[kk][3], r2, r3);
            }
        }

        float tm0 = -1e30f, tm1 = -1e30f;
#pragma unroll
        for (int j = 0; j < 8; j++) {
            const float mv0 = msk[j * 8 + 2 * t4], mv1 = msk[j * 8 + 2 * t4 + 1];
            sacc[j][0] = sacc[j][0] * 0.125f + mv0;
            sacc[j][1] = sacc[j][1] * 0.125f + mv1;
            sacc[j][2] = sacc[j][2] * 0.125f + mv0;
            sacc[j][3] = sacc[j][3] * 0.125f + mv1;
            tm0 = fmaxf(tm0, fmaxf(sacc[j][0], sacc[j][1]));
            tm1 = fmaxf(tm1, fmaxf(sacc[j][2], sacc[j][3]));
        }
        tm0 = fmaxf(tm0, __shfl_xor_sync(0xffffffffu, tm0, 1));
        tm0 = fmaxf(tm0, __shfl_xor_sync(0xffffffffu, tm0, 2));
        tm1 = fmaxf(tm1, __shfl_xor_sync(0xffffffffu, tm1, 1));
        tm1 = fmaxf(tm1, __shfl_xor_sync(0xffffffffu, tm1, 2));
        const float mn0 = fmaxf(m0, tm0), mn1 = fmaxf(m1, tm1);
        const float al0 = __expf(m0 - mn0), al1 = __expf(m1 - mn1);
        m0 = mn0; m1 = mn1;
        float ls0 = 0.f, ls1 = 0.f;
#pragma unroll
        for (int j = 0; j < 8; j++) {
            sacc[j][0] = __expf(sacc[j][0] - mn0);
            sacc[j][1] = __expf(sacc[j][1] - mn0);
            sacc[j][2] = __expf(sacc[j][2] - mn1);
            sacc[j][3] = __expf(sacc[j][3] - mn1);
            ls0 += sacc[j][0] + sacc[j][1];
            ls1 += sacc[j][2] + sacc[j][3];
        }
        l0 = l0 * al0 + ls0;
        l1 = l1 * al1 + ls1;
#pragma unroll
        for (int j = 0; j < 8; j++) {
            oacc[j][0] *= al0; oacc[j][1] *= al0;
            oacc[j][2] *= al1; oacc[j][3] *= al1;
        }

        uint32_t pf[4][4];
#pragma unroll
        for (int kk = 0; kk < 4; kk++) {
            pf[kk][0] = pack2h(__float2half_rn(sacc[2*kk][0]),   __float2half_rn(sacc[2*kk][1]));
            pf[kk][1] = pack2h(__float2half_rn(sacc[2*kk][2]),   __float2half_rn(sacc[2*kk][3]));
            pf[kk][2] = pack2h(__float2half_rn(sacc[2*kk+1][0]), __float2half_rn(sacc[2*kk+1][1]));
            pf[kk][3] = pack2h(__float2half_rn(sacc[2*kk+1][2]), __float2half_rn(sacc[2*kk+1][3]));
        }

#pragma unroll
        for (int dp = 0; dp < 4; dp++) {
#pragma unroll
            for (int kk = 0; kk < 4; kk++) {
                uint32_t r0, r1, r2, r3;
                uint32_t a = smem_u32(&Vh[(kk * 16 + vrow_off) * APAD + dp * 16 + vcol_off]);
                ldsm_x4_t(r0, r1, r2, r3, a);
                mma_f16(oacc[2*dp][0], oacc[2*dp][1], oacc[2*dp][2], oacc[2*dp][3],
                        pf[kk][0], pf[kk][1], pf[kk][2], pf[kk][3], r0, r1);
                mma_f16(oacc[2*dp+1][0], oacc[2*dp+1][1], oacc[2*dp+1][2], oacc[2*dp+1][3],
                        pf[kk][0], pf[kk][1], pf[kk][2], pf[kk][3], r2, r3);
                a = smem_u32(&Vl[(kk * 16 + vrow_off) * APAD + dp * 16 + vcol_off]);
                ldsm_x4_t(r0, r1, r2, r3, a);
                mma_f16(oacc[2*dp][0], oacc[2*dp][1], oacc[2*dp][2], oacc[2*dp][3],
                        pf[kk][0], pf[kk][1], pf[kk][2], pf[kk][3], r0, r1);
                mma_f16(oacc[2*dp+1][0], oacc[2*dp+1][1], oacc[2*dp+1][2], oacc[2*dp+1][3],
                        pf[kk][0], pf[kk][1], pf[kk][2], pf[kk][3], r2, r3);
            }
        }
    }

    l0 += __shfl_xor_sync(0xffffffffu, l0, 1);
    l0 += __shfl_xor_sync(0xffffffffu, l0, 2);
    l1 += __shfl_xor_sync(0xffffffffu, l1, 1);
    l1 += __shfl_xor_sync(0xffffffffu, l1, 2);
    const float inv0 = 1.f / l0, inv1 = 1.f / l1;
    const int row0 = q0 + w16 + g;
#pragma unroll
    for (int j = 0; j < 8; j++) {
        const int col = j * 8 + 2 * t4;
        *(uint32_t*)&O[base + (size_t)row0 * HH + col] =
            pack2h(__float2half_rn(oacc[j][0] * inv0), __float2half_rn(oacc[j][1] * inv0));
        *(uint32_t*)&O[base + (size_t)(row0 + 8) * HH + col] =
            pack2h(__float2half_rn(oacc[j][2] * inv1), __float2half_rn(oacc[j][3] * inv1));
    }
}

// ---------------- layernorm (fp32 out + optional fp16 out) --------------
__global__ __launch_bounds__(256)
void ln_kernel(const float* __restrict__ x, const float* __restrict__ g,
               const float* __restrict__ bt, float* __restrict__ y,
               __half* __restrict__ yh)
{
    const int row = blockIdx.x;
    const int tid = threadIdx.x;
    const int c = tid * 4;
    const float* xr = x + (size_t)row * HH;
    float4 v4 = *(const float4*)(xr + c);
    float v[4] = {v4.x, v4.y, v4.z, v4.w};
    float s = v[0] + v[1] + v[2] + v[3];

    __shared__ float smr[8];
    __shared__ float mu_s, var_s;
#pragma unroll
    for (int o = 16; o; o >>= 1) s += __shfl_xor_sync(0xffffffffu, s, o);
    if ((tid & 31) == 0) smr[tid >> 5] = s;
    __syncthreads();
    if (tid < 32) {
        float t = (tid < 8) ? smr[tid] : 0.f;
#pragma unroll
        for (int o = 4; o; o >>= 1) t += __shfl_xor_sync(0xffffffffu, t, o);
        if (tid == 0) mu_s = t * (1.f / HH);
    }
    __syncthreads();
    const float mu = mu_s;
    float s2 = 0.f;
#pragma unroll
    for (int i = 0; i < 4; i++) { float d = v[i] - mu; s2 += d * d; }
#pragma unroll
    for (int o = 16; o; o >>= 1) s2 += __shfl_xor_sync(0xffffffffu, s2, o);
    __syncthreads();
    if ((tid & 31) == 0) smr[tid >> 5] = s2;
    __syncthreads();
    if (tid < 32) {
        float t = (tid < 8) ? smr[tid] : 0.f;
#pragma unroll
        for (int o = 4; o; o >>= 1) t += __shfl_xor_sync(0xffffffffu, t, o);
        if (tid == 0) var_s = t * (1.f / HH);
    }
    __syncthreads();
    const float inv = rsqrtf(var_s + 1e-5f);
    float4 g4 = *(const float4*)(g + c);
    float4 b4 = *(const float4*)(bt + c);
    float4 r4;
    r4.x = (v[0] - mu) * inv * g4.x + b4.x;
    r4.y = (v[1] - mu) * inv * g4.y + b4.y;
    r4.z = (v[2] - mu) * inv * g4.z + b4.z;
    r4.w = (v[3] - mu) * inv * g4.w + b4.w;
    *(float4*)(y + (size_t)row * HH + c) = r4;
    if (yh) {
        uint2 p;
        p.x = pack2h(__float2half_rn(r4.x), __float2half_rn(r4.y));
        p.y = pack2h(__float2half_rn(r4.z), __float2half_rn(r4.w));
        *(uint2*)&yh[(size_t)row * HH + c] = p;
    }
}

// ---------------- host ----------------
extern "C" void kernel_launch(void* const* d_in, const int* in_sizes, int n_in,
                              void* d_out, int out_size)
{
    (void)in_sizes; (void)n_in; (void)out_size;
    const float* x     = (const float*)d_in[0];
    const float* mask  = (const float*)d_in[1];
    const float* wq    = (const float*)d_in[2];
    const float* bq    = (const float*)d_in[3];
    const float* wk    = (const float*)d_in[4];
    const float* bk    = (const float*)d_in[5];
    const float* wv    = (const float*)d_in[6];
    const float* bv    = (const float*)d_in[7];
    const float* wo    = (const float*)d_in[8];
    const float* bo    = (const float*)d_in[9];
    const float* ln1g  = (const float*)d_in[10];
    const float* ln1b  = (const float*)d_in[11];
    const float* wi    = (const float*)d_in[12];
    const float* bi    = (const float*)d_in[13];
    const float* wo2   = (const float*)d_in[14];
    const float* bo2   = (const float*)d_in[15];
    const float* ln2g  = (const float*)d_in[16];
    const float* ln2b  = (const float*)d_in[17];
    float* out = (float*)d_out;

    __half *xh, *wqT, *wkT, *wvT, *woT, *wiT, *wo2T;
    __half *qh, *ql, *kh, *vh, *vl, *ctxh, *attnh, *interh;
    float *t1, *attn32, *t2;
    cudaGetSymbolAddress((void**)&xh,     g_xh);
    cudaGetSymbolAddress((void**)&wqT,    g_wqT);
    cudaGetSymbolAddress((void**)&wkT,    g_wkT);
    cudaGetSymbolAddress((void**)&wvT,    g_wvT);
    cudaGetSymbolAddress((void**)&woT,    g_woT);
    cudaGetSymbolAddress((void**)&wiT,    g_wiT);
    cudaGetSymbolAddress((void**)&wo2T,   g_wo2T);
    cudaGetSymbolAddress((void**)&qh,     g_qh);
    cudaGetSymbolAddress((void**)&ql,     g_ql);
    cudaGetSymbolAddress((void**)&kh,     g_kh);
    cudaGetSymbolAddress((void**)&vh,     g_vh);
    cudaGetSymbolAddress((void**)&vl,     g_vl);
    cudaGetSymbolAddress((void**)&ctxh,   g_ctxh);
    cudaGetSymbolAddress((void**)&attnh,  g_attnh);
    cudaGetSymbolAddress((void**)&interh, g_interh);
    cudaGetSymbolAddress((void**)&t1,     g_t1);
    cudaGetSymbolAddress((void**)&attn32, g_attn32);
    cudaGetSymbolAddress((void**)&t2,     g_t2);

    cudaFuncSetAttribute(gemm_hmma<0>, cudaFuncAttributeMaxDynamicSharedMemorySize, GEMM_SMEM);
    cudaFuncSetAttribute(gemm_hmma<1>, cudaFuncAttributeMaxDynamicSharedMemorySize, GEMM_SMEM);
    cudaFuncSetAttribute(gemm_hmma<2>, cudaFuncAttributeMaxDynamicSharedMemorySize, GEMM_SMEM);

    // ---- pre-pass: convert weights (transposed) and x to fp16 ----
    wt_kernel<<<dim3(HH / 32, HH / 32), 256>>>(wq, wqT, HH, HH);
    wt_kernel<<<dim3(HH / 32, HH / 32), 256>>>(wk, wkT, HH, HH);
    wt_kernel<<<dim3(HH / 32, HH / 32), 256>>>(wv, wvT, HH, HH);
    wt_kernel<<<dim3(HH / 32, HH / 32), 256>>>(wo, woT, HH, HH);
    wt_kernel<<<dim3(FFD / 32, HH / 32), 256>>>(wi, wiT, HH, FFD);
    wt_kernel<<<dim3(HH / 32, FFD / 32), 256>>>(wo2, wo2T, FFD, HH);
    hconv_kernel<<<MTOK * HH / 1024, 256>>>(x, xh);

    const dim3 blkG(128);
    const dim3 gH(HH / 128, MTOK / 128);
    const dim3 gF(FFD / 128, MTOK / 128);

    // QKV projections (fp16 outputs; q and v with hi/lo split)
    gemm_hmma<0><<<gH, blkG, GEMM_SMEM>>>(xh, wqT, bq, nullptr, nullptr, qh, ql, MTOK, HH, HH);
    gemm_hmma<0><<<gH, blkG, GEMM_SMEM>>>(xh, wkT, bk, nullptr, nullptr, kh, nullptr, MTOK, HH, HH);
    gemm_hmma<0><<<gH, blkG, GEMM_SMEM>>>(xh, wvT, bv, nullptr, nullptr, vh, vl, MTOK, HH, HH);

    // attention (fp16 in, fp16 ctx out)
    attn_kernel<<<dim3(SS / 64, NHEAD, BB), dim3(128)>>>(qh, ql, kh, vh, vl, mask, ctxh);

    // output proj + residual, LN1
    gemm_hmma<2><<<gH, blkG, GEMM_SMEM>>>(ctxh, woT, bo, x, t1, nullptr, nullptr, MTOK, HH, HH);
    ln_kernel<<<MTOK, dim3(256)>>>(t1, ln1g, ln1b, attn32, attnh);

    // FFN
    gemm_hmma<1><<<gF, blkG, GEMM_SMEM>>>(attnh, wiT, bi, nullptr, nullptr, interh, nullptr, MTOK, FFD, HH);
    gemm_hmma<2><<<gH, blkG, GEMM_SMEM>>>(interh, wo2T, bo2, attn32, t2, nullptr, nullptr, MTOK, HH, FFD);
    ln_kernel<<<MTOK, dim3(256)>>>(t2, ln2g, ln2b, out, nullptr);
}

// round 10
// speedup vs baseline: 6.9027x; 1.0957x over previous
#include <cuda_runtime.h>
#include <cuda_fp16.h>
#include <cstdint>
#include <math.h>

#define BB 8
#define SS 512
#define HH 1024
#define NHEAD 16
#define HDIM 64
#define FFD 4096
#define MTOK (BB*SS)   // 4096 tokens

// ---------------- scratch (static __device__, no allocs) ----------------
__device__ __half g_xh[MTOK*HH];
__device__ __half g_wqT[HH*HH];
__device__ __half g_wkT[HH*HH];
__device__ __half g_wvT[HH*HH];
__device__ __half g_woT[HH*HH];
__device__ __half g_wiT[(size_t)HH*FFD];    // [FFD][HH]
__device__ __half g_wo2T[(size_t)FFD*HH];   // [HH][FFD]
__device__ __half g_qh[MTOK*HH];
__device__ __half g_kh[MTOK*HH];
__device__ __half g_vh[MTOK*HH];
__device__ __half g_ctxh[MTOK*HH];
__device__ float  g_t1[MTOK*HH];
__device__ float  g_attn32[MTOK*HH];
__device__ __half g_attnh[MTOK*HH];
__device__ __half g_interh[(size_t)MTOK*FFD];
__device__ float  g_t2[MTOK*HH];

// ==================== helpers ====================
__device__ __forceinline__ uint32_t smem_u32(const void* p) {
    uint32_t a;
    asm("{ .reg .u64 t; cvta.to.shared.u64 t, %1; cvt.u32.u64 %0, t; }" : "=r"(a) : "l"(p));
    return a;
}
__device__ __forceinline__ uint32_t pack2h(__half a, __half b) {
    return (uint32_t)__half_as_ushort(a) | ((uint32_t)__half_as_ushort(b) << 16);
}
__device__ __forceinline__ void mma_f16(float& d0, float& d1, float& d2, float& d3,
                                        uint32_t a0, uint32_t a1, uint32_t a2, uint32_t a3,
                                        uint32_t b0, uint32_t b1) {
    asm volatile(
        "mma.sync.aligned.m16n8k16.row.col.f32.f16.f16.f32 "
        "{%0,%1,%2,%3}, {%4,%5,%6,%7}, {%8,%9}, {%0,%1,%2,%3};"
        : "+f"(d0), "+f"(d1), "+f"(d2), "+f"(d3)
        : "r"(a0), "r"(a1), "r"(a2), "r"(a3), "r"(b0), "r"(b1));
}
__device__ __forceinline__ void ldsm_x4(uint32_t& r0, uint32_t& r1, uint32_t& r2, uint32_t& r3, uint32_t a) {
    asm volatile("ldmatrix.sync.aligned.m8n8.x4.shared.b16 {%0,%1,%2,%3}, [%4];"
        : "=r"(r0), "=r"(r1), "=r"(r2), "=r"(r3) : "r"(a));
}
__device__ __forceinline__ void ldsm_x4_t(uint32_t& r0, uint32_t& r1, uint32_t& r2, uint32_t& r3, uint32_t a) {
    asm volatile("ldmatrix.sync.aligned.m8n8.x4.trans.shared.b16 {%0,%1,%2,%3}, [%4];"
        : "=r"(r0), "=r"(r1), "=r"(r2), "=r"(r3) : "r"(a));
}
#define CP_ASYNC16(s, g) asm volatile("cp.async.cg.shared.global [%0], [%1], 16;" :: "r"(s), "l"(g))
#define CP_ASYNC4(s, g)  asm volatile("cp.async.ca.shared.global [%0], [%1], 4;" :: "r"(s), "l"(g))
#define CP_COMMIT()      asm volatile("cp.async.commit_group;" ::: "memory")
#define CP_WAIT(n)       asm volatile("cp.async.wait_group %0;" :: "n"(n) : "memory")

// ==================== pre-pass: weight transpose+convert, x convert =====
__global__ __launch_bounds__(256)
void wt_kernel(const float* __restrict__ W, __half* __restrict__ WT, int K, int N)
{
    __shared__ __half t[32][33];
    const int n0 = blockIdx.x * 32, k0 = blockIdx.y * 32;
    const int tx = threadIdx.x & 31, ty = threadIdx.x >> 5;   // 32 x 8
#pragma unroll
    for (int i = 0; i < 4; i++)
        t[ty + i * 8][tx] = __float2half_rn(W[(size_t)(k0 + ty + i * 8) * N + n0 + tx]);
    __syncthreads();
#pragma unroll
    for (int i = 0; i < 4; i++)
        WT[(size_t)(n0 + ty + i * 8) * K + k0 + tx] = t[tx][ty + i * 8];
}

__global__ __launch_bounds__(256)
void hconv_kernel(const float* __restrict__ x, __half* __restrict__ xh)
{
    const size_t i = ((size_t)blockIdx.x * 256 + threadIdx.x) * 4;
    float4 v = *(const float4*)(x + i);
    uint2 p;
    p.x = pack2h(__float2half_rn(v.x), __float2half_rn(v.y));
    p.y = pack2h(__float2half_rn(v.z), __float2half_rn(v.w));
    *(uint2*)&xh[i] = p;
}

// ==================== HMMA GEMM (fp16 in, fp32 accum) ===================
// C = A[M,K](fp16) @ BT[N,K](fp16)^T + bias. CTA 128x128, BK=32.
// 4 warps (2m x 2n), warp tile 64x64. cp.async 3-stage pipeline.
// EPI 0: bias -> Ch. EPI 1: gelu -> Ch. EPI 2: +res -> C32.

#define GP 40                    // padded halfs per 32-elem row (80B, 16B-aligned)
#define BH_H 5120                // sB offset in halfs (128*40)
#define ST_H 10240               // stage size in halfs (20480 B)
#define NSTAGE 3
#define GEMM_SMEM (NSTAGE*ST_H*2)   // 61440 bytes

template<int EPI>
__global__ __launch_bounds__(128)
void gemm_hmma(const __half* __restrict__ A, const __half* __restrict__ BT,
               const float* __restrict__ bias, const float* __restrict__ res,
               float* __restrict__ C32, __half* __restrict__ Ch,
               int M, int N, int K)
{
    extern __shared__ __half smh[];
    const int tid = threadIdx.x;
    const int m0 = blockIdx.y * 128, n0 = blockIdx.x * 128;

    const int wid = tid >> 5, lane = tid & 31;
    const int wm = wid >> 1, wn = wid & 1;      // warp grid 2x2, tile 64x64
    const int g = lane >> 2, q = lane & 3;

    const int a_row_off = lane & 15;
    const int a_col_off = ((lane >> 4) << 3);
    const int b_row_off = (lane & 7) + ((lane >> 4) << 3);
    const int b_col_off = (lane & 8);

    float acc[4][8][4];
#pragma unroll
    for (int i = 0; i < 4; i++)
#pragma unroll
        for (int j = 0; j < 8; j++)
#pragma unroll
            for (int t = 0; t < 4; t++) acc[i][j][t] = 0.f;

    auto load_stage = [&](int k0, int buf) {
        __half* sA = smh + buf * ST_H;
        __half* sB = sA + BH_H;
#pragma unroll
        for (int i = 0; i < 4; i++) {
            const int lin = i * 128 + tid;
            const int row = lin >> 2, ch = (lin & 3) * 8;
            CP_ASYNC16(smem_u32(&sA[row * GP + ch]), A  + (size_t)(m0 + row) * K + k0 + ch);
            CP_ASYNC16(smem_u32(&sB[row * GP + ch]), BT + (size_t)(n0 + row) * K + k0 + ch);
        }
        CP_COMMIT();
    };

    auto compute_stage = [&](int buf) {
        const __half* sA = smh + buf * ST_H;
        const __half* sB = sA + BH_H;
#pragma unroll
        for (int kk = 0; kk < 2; kk++) {
            uint32_t af[4][4];
#pragma unroll
            for (int mt = 0; mt < 4; mt++) {
                uint32_t a = smem_u32(&sA[(wm * 64 + mt * 16 + a_row_off) * GP + kk * 16 + a_col_off]);
                ldsm_x4(af[mt][0], af[mt][1], af[mt][2], af[mt][3], a);
            }
#pragma unroll
            for (int nt = 0; nt < 4; nt++) {
                uint32_t r0, r1, r2, r3;
                uint32_t a = smem_u32(&sB[(wn * 64 + nt * 16 + b_row_off) * GP + kk * 16 + b_col_off]);
                ldsm_x4(r0, r1, r2, r3, a);
#pragma unroll
                for (int mt = 0; mt < 4; mt++) {
                    mma_f16(acc[mt][2*nt][0], acc[mt][2*nt][1], acc[mt][2*nt][2], acc[mt][2*nt][3],
                            af[mt][0], af[mt][1], af[mt][2], af[mt][3], r0, r1);
                    mma_f16(acc[mt][2*nt+1][0], acc[mt][2*nt+1][1], acc[mt][2*nt+1][2], acc[mt][2*nt+1][3],
                            af[mt][0], af[mt][1], af[mt][2], af[mt][3], r2, r3);
                }
            }
        }
    };

    const int NC = K >> 5;
    load_stage(0, 0);
    load_stage(32, 1);
    for (int c = 0; c < NC; c++) {
        CP_WAIT(1);
        __syncthreads();
        if (c + 2 < NC) load_stage((c + 2) << 5, (c + 2) % NSTAGE);
        compute_stage(c % NSTAGE);
    }

#pragma unroll
    for (int mt = 0; mt < 4; mt++) {
        const int r0 = m0 + wm * 64 + mt * 16 + g;
#pragma unroll
        for (int nj = 0; nj < 8; nj++) {
            const int col = n0 + wn * 64 + nj * 8 + q * 2;
            float b0 = bias[col], b1 = bias[col + 1];
#pragma unroll
            for (int h = 0; h < 2; h++) {
                const int row = r0 + h * 8;
                float v0 = acc[mt][nj][h * 2 + 0] + b0;
                float v1 = acc[mt][nj][h * 2 + 1] + b1;
                if (EPI == 1) {
                    v0 = 0.5f * v0 * (1.0f + erff(v0 * 0.70710678118654752440f));
                    v1 = 0.5f * v1 * (1.0f + erff(v1 * 0.70710678118654752440f));
                }
                if (EPI == 0 || EPI == 1) {
                    *(uint32_t*)&Ch[(size_t)row * N + col] =
                        pack2h(__float2half_rn(v0), __float2half_rn(v1));
                } else {
                    float2 r2 = *(const float2*)(res + (size_t)row * N + col);
                    *(float2*)(C32 + (size_t)row * N + col) = make_float2(v0 + r2.x, v1 + r2.y);
                }
            }
        }
    }
}

// ==================== flash attention (pure fp16, cp.async pipeline) ====
// CTA: (b, h, 64 q rows); 4 warps x 16 q rows. kv tiles of 64, double-buffered.
#define APAD 72    // halfs per smem row (144 B, 16B-aligned)

__global__ __launch_bounds__(128)
void attn_kernel(const __half* __restrict__ Qhg, const __half* __restrict__ Khg,
                 const __half* __restrict__ Vhg,
                 const float* __restrict__ mask, __half* __restrict__ O)
{
    __shared__ __align__(16) __half Qs[64*APAD];
    __shared__ __align__(16) __half Ks[2][64*APAD];
    __shared__ __align__(16) __half Vs[2][64*APAD];
    __shared__ float msk[2][64];

    const int qt = blockIdx.x, h = blockIdx.y, b = blockIdx.z;
    const int tid = threadIdx.x;
    const int wid = tid >> 5, lane = tid & 31;
    const int g = lane >> 2, t4 = lane & 3;
    const int q0 = qt * 64;
    const int base = (b * SS) * HH + h * HDIM;
    const int w16 = wid * 16;

    // ---- kv tile loader (cp.async; one commit group per tile) ----
    auto load_kv = [&](int kt, int buf) {
#pragma unroll
        for (int i = 0; i < 4; i++) {
            const int c = i * 128 + tid;        // chunk id 0..511
            const int row = c >> 3, ch = (c & 7) * 8;
            CP_ASYNC16(smem_u32(&Ks[buf][row * APAD + ch]),
                       Khg + base + (size_t)(kt + row) * HH + ch);
            CP_ASYNC16(smem_u32(&Vs[buf][row * APAD + ch]),
                       Vhg + base + (size_t)(kt + row) * HH + ch);
        }
        if (tid < 64)
            CP_ASYNC4(smem_u32(&msk[buf][tid]), mask + b * SS + kt + tid);
        CP_COMMIT();
    };

    // ---- stage Q ----
    {
        const int r = tid >> 1, c0 = (tid & 1) * 32;
        const __half* Qp = Qhg + base + (size_t)(q0 + r) * HH + c0;
#pragma unroll
        for (int i = 0; i < 4; i++)
            *(uint4*)&Qs[r * APAD + c0 + i * 8] = *(const uint4*)(Qp + i * 8);
    }
    load_kv(0, 0);
    __syncthreads();

    // ---- per-warp Q fragments (4 k16 steps) ----
    uint32_t qf[4][4];
    {
        const int row = w16 + (lane & 15);
        const int colb = (lane >> 4) << 3;
#pragma unroll
        for (int kk = 0; kk < 4; kk++) {
            uint32_t a = smem_u32(&Qs[row * APAD + kk * 16 + colb]);
            ldsm_x4(qf[kk][0], qf[kk][1], qf[kk][2], qf[kk][3], a);
        }
    }

    float oacc[8][4];
#pragma unroll
    for (int j = 0; j < 8; j++)
#pragma unroll
        for (int t = 0; t < 4; t++) oacc[j][t] = 0.f;
    float m0 = -1e30f, m1 = -1e30f, l0 = 0.f, l1 = 0.f;

    const int krow_off = (lane & 7) + ((lane >> 4) << 3);
    const int kcol_off = (lane & 8);
    const int vrow_off = (lane & 7) + (lane & 8);
    const int vcol_off = ((lane >> 4) << 3);

    for (int ti = 0; ti < SS / 64; ti++) {
        const int buf = ti & 1;
        if (ti + 1 < SS / 64) {
            load_kv((ti + 1) * 64, buf ^ 1);
            CP_WAIT(1);
        } else {
            CP_WAIT(0);
        }
        __syncthreads();                         // tile ti visible to all warps

        // ---- scores: S = Q K^T ----
        float sacc[8][4];
#pragma unroll
        for (int j = 0; j < 8; j++)
#pragma unroll
            for (int t = 0; t < 4; t++) sacc[j][t] = 0.f;
#pragma unroll
        for (int jp = 0; jp < 4; jp++) {
#pragma unroll
            for (int kk = 0; kk < 4; kk++) {
                uint32_t r0, r1, r2, r3;
                uint32_t a = smem_u32(&Ks[buf][(jp * 16 + krow_off) * APAD + kk * 16 + kcol_off]);
                ldsm_x4(r0, r1, r2, r3, a);
                mma_f16(sacc[2*jp][0], sacc[2*jp][1], sacc[2*jp][2], sacc[2*jp][3],
                        qf[kk][0], qf[kk][1], qf[kk][2], qf[kk][3], r0, r1);
                mma_f16(sacc[2*jp+1][0], sacc[2*jp+1][1], sacc[2*jp+1][2], sacc[2*jp+1][3],
                        qf[kk][0], qf[kk][1], qf[kk][2], qf[kk][3], r2, r3);
            }
        }

        // ---- scale + mask + online softmax ----
        float tm0 = -1e30f, tm1 = -1e30f;
#pragma unroll
        for (int j = 0; j < 8; j++) {
            const float mv0 = msk[buf][j * 8 + 2 * t4], mv1 = msk[buf][j * 8 + 2 * t4 + 1];
            sacc[j][0] = sacc[j][0] * 0.125f + mv0;
            sacc[j][1] = sacc[j][1] * 0.125f + mv1;
            sacc[j][2] = sacc[j][2] * 0.125f + mv0;
            sacc[j][3] = sacc[j][3] * 0.125f + mv1;
            tm0 = fmaxf(tm0, fmaxf(sacc[j][0], sacc[j][1]));
            tm1 = fmaxf(tm1, fmaxf(sacc[j][2], sacc[j][3]));
        }
        tm0 = fmaxf(tm0, __shfl_xor_sync(0xffffffffu, tm0, 1));
        tm0 = fmaxf(tm0, __shfl_xor_sync(0xffffffffu, tm0, 2));
        tm1 = fmaxf(tm1, __shfl_xor_sync(0xffffffffu, tm1, 1));
        tm1 = fmaxf(tm1, __shfl_xor_sync(0xffffffffu, tm1, 2));
        const float mn0 = fmaxf(m0, tm0), mn1 = fmaxf(m1, tm1);
        const float al0 = __expf(m0 - mn0), al1 = __expf(m1 - mn1);
        m0 = mn0; m1 = mn1;
        float ls0 = 0.f, ls1 = 0.f;
#pragma unroll
        for (int j = 0; j < 8; j++) {
            sacc[j][0] = __expf(sacc[j][0] - mn0);
            sacc[j][1] = __expf(sacc[j][1] - mn0);
            sacc[j][2] = __expf(sacc[j][2] - mn1);
            sacc[j][3] = __expf(sacc[j][3] - mn1);
            ls0 += sacc[j][0] + sacc[j][1];
            ls1 += sacc[j][2] + sacc[j][3];
        }
        l0 = l0 * al0 + ls0;
        l1 = l1 * al1 + ls1;
#pragma unroll
        for (int j = 0; j < 8; j++) {
            oacc[j][0] *= al0; oacc[j][1] *= al0;
            oacc[j][2] *= al1; oacc[j][3] *= al1;
        }

        // ---- P fragments ----
        uint32_t pf[4][4];
#pragma unroll
        for (int kk = 0; kk < 4; kk++) {
            pf[kk][0] = pack2h(__float2half_rn(sacc[2*kk][0]),   __float2half_rn(sacc[2*kk][1]));
            pf[kk][1] = pack2h(__float2half_rn(sacc[2*kk][2]),   __float2half_rn(sacc[2*kk][3]));
            pf[kk][2] = pack2h(__float2half_rn(sacc[2*kk+1][0]), __float2half_rn(sacc[2*kk+1][1]));
            pf[kk][3] = pack2h(__float2half_rn(sacc[2*kk+1][2]), __float2half_rn(sacc[2*kk+1][3]));
        }

        // ---- O += P @ V ----
#pragma unroll
        for (int dp = 0; dp < 4; dp++) {
#pragma unroll
            for (int kk = 0; kk < 4; kk++) {
                uint32_t r0, r1, r2, r3;
                uint32_t a = smem_u32(&Vs[buf][(kk * 16 + vrow_off) * APAD + dp * 16 + vcol_off]);
                ldsm_x4_t(r0, r1, r2, r3, a);
                mma_f16(oacc[2*dp][0], oacc[2*dp][1], oacc[2*dp][2], oacc[2*dp][3],
                        pf[kk][0], pf[kk][1], pf[kk][2], pf[kk][3], r0, r1);
                mma_f16(oacc[2*dp+1][0], oacc[2*dp+1][1], oacc[2*dp+1][2], oacc[2*dp+1][3],
                        pf[kk][0], pf[kk][1], pf[kk][2], pf[kk][3], r2, r3);
            }
        }
        __syncthreads();                         // done reading buf before overwrite
    }

    l0 += __shfl_xor_sync(0xffffffffu, l0, 1);
    l0 += __shfl_xor_sync(0xffffffffu, l0, 2);
    l1 += __shfl_xor_sync(0xffffffffu, l1, 1);
    l1 += __shfl_xor_sync(0xffffffffu, l1, 2);
    const float inv0 = 1.f / l0, inv1 = 1.f / l1;
    const int row0 = q0 + w16 + g;
#pragma unroll
    for (int j = 0; j < 8; j++) {
        const int col = j * 8 + 2 * t4;
        *(uint32_t*)&O[base + (size_t)row0 * HH + col] =
            pack2h(__float2half_rn(oacc[j][0] * inv0), __float2half_rn(oacc[j][1] * inv0));
        *(uint32_t*)&O[base + (size_t)(row0 + 8) * HH + col] =
            pack2h(__float2half_rn(oacc[j][2] * inv1), __float2half_rn(oacc[j][3] * inv1));
    }
}

// ---------------- layernorm (fp32 out + optional fp16 out) --------------
__global__ __launch_bounds__(256)
void ln_kernel(const float* __restrict__ x, const float* __restrict__ g,
               const float* __restrict__ bt, float* __restrict__ y,
               __half* __restrict__ yh)
{
    const int row = blockIdx.x;
    const int tid = threadIdx.x;
    const int c = tid * 4;
    const float* xr = x + (size_t)row * HH;
    float4 v4 = *(const float4*)(xr + c);
    float v[4] = {v4.x, v4.y, v4.z, v4.w};
    float s = v[0] + v[1] + v[2] + v[3];

    __shared__ float smr[8];
    __shared__ float mu_s, var_s;
#pragma unroll
    for (int o = 16; o; o >>= 1) s += __shfl_xor_sync(0xffffffffu, s, o);
    if ((tid & 31) == 0) smr[tid >> 5] = s;
    __syncthreads();
    if (tid < 32) {
        float t = (tid < 8) ? smr[tid] : 0.f;
#pragma unroll
        for (int o = 4; o; o >>= 1) t += __shfl_xor_sync(0xffffffffu, t, o);
        if (tid == 0) mu_s = t * (1.f / HH);
    }
    __syncthreads();
    const float mu = mu_s;
    float s2 = 0.f;
#pragma unroll
    for (int i = 0; i < 4; i++) { float d = v[i] - mu; s2 += d * d; }
#pragma unroll
    for (int o = 16; o; o >>= 1) s2 += __shfl_xor_sync(0xffffffffu, s2, o);
    __syncthreads();
    if ((tid & 31) == 0) smr[tid >> 5] = s2;
    __syncthreads();
    if (tid < 32) {
        float t = (tid < 8) ? smr[tid] : 0.f;
#pragma unroll
        for (int o = 4; o; o >>= 1) t += __shfl_xor_sync(0xffffffffu, t, o);
        if (tid == 0) var_s = t * (1.f / HH);
    }
    __syncthreads();
    const float inv = rsqrtf(var_s + 1e-5f);
    float4 g4 = *(const float4*)(g + c);
    float4 b4 = *(const float4*)(bt + c);
    float4 r4;
    r4.x = (v[0] - mu) * inv * g4.x + b4.x;
    r4.y = (v[1] - mu) * inv * g4.y + b4.y;
    r4.z = (v[2] - mu) * inv * g4.z + b4.z;
    r4.w = (v[3] - mu) * inv * g4.w + b4.w;
    *(float4*)(y + (size_t)row * HH + c) = r4;
    if (yh) {
        uint2 p;
        p.x = pack2h(__float2half_rn(r4.x), __float2half_rn(r4.y));
        p.y = pack2h(__float2half_rn(r4.z), __float2half_rn(r4.w));
        *(uint2*)&yh[(size_t)row * HH + c] = p;
    }
}

// ---------------- host ----------------
extern "C" void kernel_launch(void* const* d_in, const int* in_sizes, int n_in,
                              void* d_out, int out_size)
{
    (void)in_sizes; (void)n_in; (void)out_size;
    const float* x     = (const float*)d_in[0];
    const float* mask  = (const float*)d_in[1];
    const float* wq    = (const float*)d_in[2];
    const float* bq    = (const float*)d_in[3];
    const float* wk    = (const float*)d_in[4];
    const float* bk    = (const float*)d_in[5];
    const float* wv    = (const float*)d_in[6];
    const float* bv    = (const float*)d_in[7];
    const float* wo    = (const float*)d_in[8];
    const float* bo    = (const float*)d_in[9];
    const float* ln1g  = (const float*)d_in[10];
    const float* ln1b  = (const float*)d_in[11];
    const float* wi    = (const float*)d_in[12];
    const float* bi    = (const float*)d_in[13];
    const float* wo2   = (const float*)d_in[14];
    const float* bo2   = (const float*)d_in[15];
    const float* ln2g  = (const float*)d_in[16];
    const float* ln2b  = (const float*)d_in[17];
    float* out = (float*)d_out;

    __half *xh, *wqT, *wkT, *wvT, *woT, *wiT, *wo2T;
    __half *qh, *kh, *vh, *ctxh, *attnh, *interh;
    float *t1, *attn32, *t2;
    cudaGetSymbolAddress((void**)&xh,     g_xh);
    cudaGetSymbolAddress((void**)&wqT,    g_wqT);
    cudaGetSymbolAddress((void**)&wkT,    g_wkT);
    cudaGetSymbolAddress((void**)&wvT,    g_wvT);
    cudaGetSymbolAddress((void**)&woT,    g_woT);
    cudaGetSymbolAddress((void**)&wiT,    g_wiT);
    cudaGetSymbolAddress((void**)&wo2T,   g_wo2T);
    cudaGetSymbolAddress((void**)&qh,     g_qh);
    cudaGetSymbolAddress((void**)&kh,     g_kh);
    cudaGetSymbolAddress((void**)&vh,     g_vh);
    cudaGetSymbolAddress((void**)&ctxh,   g_ctxh);
    cudaGetSymbolAddress((void**)&attnh,  g_attnh);
    cudaGetSymbolAddress((void**)&interh, g_interh);
    cudaGetSymbolAddress((void**)&t1,     g_t1);
    cudaGetSymbolAddress((void**)&attn32, g_attn32);
    cudaGetSymbolAddress((void**)&t2,     g_t2);

    cudaFuncSetAttribute(gemm_hmma<0>, cudaFuncAttributeMaxDynamicSharedMemorySize, GEMM_SMEM);
    cudaFuncSetAttribute(gemm_hmma<1>, cudaFuncAttributeMaxDynamicSharedMemorySize, GEMM_SMEM);
    cudaFuncSetAttribute(gemm_hmma<2>, cudaFuncAttributeMaxDynamicSharedMemorySize, GEMM_SMEM);

    // ---- pre-pass: convert weights (transposed) and x to fp16 ----
    wt_kernel<<<dim3(HH / 32, HH / 32), 256>>>(wq, wqT, HH, HH);
    wt_kernel<<<dim3(HH / 32, HH / 32), 256>>>(wk, wkT, HH, HH);
    wt_kernel<<<dim3(HH / 32, HH / 32), 256>>>(wv, wvT, HH, HH);
    wt_kernel<<<dim3(HH / 32, HH / 32), 256>>>(wo, woT, HH, HH);
    wt_kernel<<<dim3(FFD / 32, HH / 32), 256>>>(wi, wiT, HH, FFD);
    wt_kernel<<<dim3(HH / 32, FFD / 32), 256>>>(wo2, wo2T, FFD, HH);
    hconv_kernel<<<MTOK * HH / 1024, 256>>>(x, xh);

    const dim3 blkG(128);
    const dim3 gH(HH / 128, MTOK / 128);
    const dim3 gF(FFD / 128, MTOK / 128);

    // QKV projections (pure fp16 outputs)
    gemm_hmma<0><<<gH, blkG, GEMM_SMEM>>>(xh, wqT, bq, nullptr, nullptr, qh, MTOK, HH, HH);
    gemm_hmma<0><<<gH, blkG, GEMM_SMEM>>>(xh, wkT, bk, nullptr, nullptr, kh, MTOK, HH, HH);
    gemm_hmma<0><<<gH, blkG, GEMM_SMEM>>>(xh, wvT, bv, nullptr, nullptr, vh, MTOK, HH, HH);

    // attention (fp16 in, fp16 ctx out)
    attn_kernel<<<dim3(SS / 64, NHEAD, BB), dim3(128)>>>(qh, kh, vh, mask, ctxh);

    // output proj + residual, LN1
    gemm_hmma<2><<<gH, blkG, GEMM_SMEM>>>(ctxh, woT, bo, x, t1, nullptr, MTOK, HH, HH);
    ln_kernel<<<MTOK, dim3(256)>>>(t1, ln1g, ln1b, attn32, attnh);

    // FFN
    gemm_hmma<1><<<gF, blkG, GEMM_SMEM>>>(attnh, wiT, bi, nullptr, nullptr, interh, MTOK, FFD, HH);
    gemm_hmma<2><<<gH, blkG, GEMM_SMEM>>>(interh, wo2T, bo2, attn32, t2, nullptr, MTOK, HH, FFD);
    ln_kernel<<<MTOK, dim3(256)>>>(t2, ln2g, ln2b, out, nullptr);
}

// round 12
// speedup vs baseline: 7.0863x; 1.0266x over previous
#include <cuda_runtime.h>
#include <cuda_fp16.h>
#include <cstdint>
#include <math.h>

#define BB 8
#define SS 512
#define HH 1024
#define NHEAD 16
#define HDIM 64
#define FFD 4096
#define MTOK (BB*SS)   // 4096 tokens
#define QKV3 3072

// ---------------- scratch (static __device__, no allocs) ----------------
__device__ __half g_xh[MTOK*HH];
__device__ __half g_wqkvT[(size_t)QKV3*HH];  // packed [3072][1024]
__device__ __half g_woT[HH*HH];
__device__ __half g_wiT[(size_t)HH*FFD];    // [FFD][HH]
__device__ __half g_wo2T[(size_t)FFD*HH];   // [HH][FFD]
__device__ float  g_bqkv[QKV3];
__device__ __half g_qkvh[(size_t)MTOK*QKV3];
__device__ __half g_ctxh[MTOK*HH];
__device__ float  g_t1[MTOK*HH];
__device__ float  g_attn32[MTOK*HH];
__device__ __half g_attnh[MTOK*HH];
__device__ __half g_interh[(size_t)MTOK*FFD];
__device__ float  g_t2[MTOK*HH];

// ==================== helpers ====================
__device__ __forceinline__ uint32_t smem_u32(const void* p) {
    uint32_t a;
    asm("{ .reg .u64 t; cvta.to.shared.u64 t, %1; cvt.u32.u64 %0, t; }" : "=r"(a) : "l"(p));
    return a;
}
__device__ __forceinline__ uint32_t pack2h(__half a, __half b) {
    return (uint32_t)__half_as_ushort(a) | ((uint32_t)__half_as_ushort(b) << 16);
}
__device__ __forceinline__ void mma_f16(float& d0, float& d1, float& d2, float& d3,
                                        uint32_t a0, uint32_t a1, uint32_t a2, uint32_t a3,
                                        uint32_t b0, uint32_t b1) {
    asm volatile(
        "mma.sync.aligned.m16n8k16.row.col.f32.f16.f16.f32 "
        "{%0,%1,%2,%3}, {%4,%5,%6,%7}, {%8,%9}, {%0,%1,%2,%3};"
        : "+f"(d0), "+f"(d1), "+f"(d2), "+f"(d3)
        : "r"(a0), "r"(a1), "r"(a2), "r"(a3), "r"(b0), "r"(b1));
}
__device__ __forceinline__ void ldsm_x4(uint32_t& r0, uint32_t& r1, uint32_t& r2, uint32_t& r3, uint32_t a) {
    asm volatile("ldmatrix.sync.aligned.m8n8.x4.shared.b16 {%0,%1,%2,%3}, [%4];"
        : "=r"(r0), "=r"(r1), "=r"(r2), "=r"(r3) : "r"(a));
}
__device__ __forceinline__ void ldsm_x4_t(uint32_t& r0, uint32_t& r1, uint32_t& r2, uint32_t& r3, uint32_t a) {
    asm volatile("ldmatrix.sync.aligned.m8n8.x4.trans.shared.b16 {%0,%1,%2,%3}, [%4];"
        : "=r"(r0), "=r"(r1), "=r"(r2), "=r"(r3) : "r"(a));
}
#define CP_ASYNC16(s, g) asm volatile("cp.async.cg.shared.global [%0], [%1], 16;" :: "r"(s), "l"(g))
#define CP_ASYNC4(s, g)  asm volatile("cp.async.ca.shared.global [%0], [%1], 4;" :: "r"(s), "l"(g))
#define CP_COMMIT()      asm volatile("cp.async.commit_group;" ::: "memory")
#define CP_WAIT(n)       asm volatile("cp.async.wait_group %0;" :: "n"(n) : "memory")

// ==================== pre-pass kernels ====================
// 4x 1024x1024 transposes in one launch: z=0..2 -> wq/wk/wv into packed wqkvT, z=3 -> wo.
__global__ __launch_bounds__(256)
void wt4_kernel(const float* __restrict__ wq, const float* __restrict__ wk,
                const float* __restrict__ wv, const float* __restrict__ wo,
                __half* __restrict__ wqkvT, __half* __restrict__ woT)
{
    __shared__ __half t[32][33];
    const int z = blockIdx.z;
    const float* W = (z == 0) ? wq : (z == 1) ? wk : (z == 2) ? wv : wo;
    const int n0 = blockIdx.x * 32, k0 = blockIdx.y * 32;
    const int tx = threadIdx.x & 31, ty = threadIdx.x >> 5;
#pragma unroll
    for (int i = 0; i < 4; i++)
        t[ty + i * 8][tx] = __float2half_rn(W[(size_t)(k0 + ty + i * 8) * HH + n0 + tx]);
    __syncthreads();
    __half* dst = (z < 3) ? (wqkvT + (size_t)z * HH * HH) : woT;
#pragma unroll
    for (int i = 0; i < 4; i++)
        dst[(size_t)(n0 + ty + i * 8) * HH + k0 + tx] = t[tx][ty + i * 8];
}

__global__ __launch_bounds__(256)
void wt_kernel(const float* __restrict__ W, __half* __restrict__ WT, int K, int N)
{
    __shared__ __half t[32][33];
    const int n0 = blockIdx.x * 32, k0 = blockIdx.y * 32;
    const int tx = threadIdx.x & 31, ty = threadIdx.x >> 5;
#pragma unroll
    for (int i = 0; i < 4; i++)
        t[ty + i * 8][tx] = __float2half_rn(W[(size_t)(k0 + ty + i * 8) * N + n0 + tx]);
    __syncthreads();
#pragma unroll
    for (int i = 0; i < 4; i++)
        WT[(size_t)(n0 + ty + i * 8) * K + k0 + tx] = t[tx][ty + i * 8];
}

__global__ __launch_bounds__(256)
void hconv_kernel(const float* __restrict__ x, __half* __restrict__ xh)
{
    const size_t i = ((size_t)blockIdx.x * 256 + threadIdx.x) * 4;
    float4 v = *(const float4*)(x + i);
    uint2 p;
    p.x = pack2h(__float2half_rn(v.x), __float2half_rn(v.y));
    p.y = pack2h(__float2half_rn(v.z), __float2half_rn(v.w));
    *(uint2*)&xh[i] = p;
}

__global__ __launch_bounds__(256)
void pack_bias_kernel(const float* __restrict__ bq, const float* __restrict__ bk,
                      const float* __restrict__ bv, float* __restrict__ bqkv)
{
    const int i = blockIdx.x * 256 + threadIdx.x;   // 0..3071
    const float* src = (i < HH) ? bq : (i < 2 * HH) ? bk : bv;
    bqkv[i] = src[i & (HH - 1)];
}

// ==================== HMMA GEMM (fp16 in, fp32 accum) ===================
// C = A[M,K](fp16) @ BT[N,K](fp16)^T + bias. CTA 128x128, BK=32.
// 4 warps (2m x 2n), warp tile 64x64. cp.async 3-stage pipeline.
// EPI 0: bias -> Ch. EPI 1: gelu -> Ch. EPI 2: +res -> C32.

#define GP 40                    // padded halfs per 32-elem row (80B, 16B-aligned)
#define BH_H 5120                // sB offset in halfs (128*40)
#define ST_H 10240               // stage size in halfs (20480 B)
#define NSTAGE 3
#define GEMM_SMEM (NSTAGE*ST_H*2)   // 61440 bytes

template<int EPI>
__global__ __launch_bounds__(128)
void gemm_hmma(const __half* __restrict__ A, const __half* __restrict__ BT,
               const float* __restrict__ bias, const float* __restrict__ res,
               float* __restrict__ C32, __half* __restrict__ Ch,
               int M, int N, int K)
{
    extern __shared__ __half smh[];
    const int tid = threadIdx.x;
    const int m0 = blockIdx.y * 128, n0 = blockIdx.x * 128;

    const int wid = tid >> 5, lane = tid & 31;
    const int wm = wid >> 1, wn = wid & 1;      // warp grid 2x2, tile 64x64
    const int g = lane >> 2, q = lane & 3;

    const int a_row_off = lane & 15;
    const int a_col_off = ((lane >> 4) << 3);
    const int b_row_off = (lane & 7) + ((lane >> 4) << 3);
    const int b_col_off = (lane & 8);

    float acc[4][8][4];
#pragma unroll
    for (int i = 0; i < 4; i++)
#pragma unroll
        for (int j = 0; j < 8; j++)
#pragma unroll
            for (int t = 0; t < 4; t++) acc[i][j][t] = 0.f;

    auto load_stage = [&](int k0, int buf) {
        __half* sA = smh + buf * ST_H;
        __half* sB = sA + BH_H;
#pragma unroll
        for (int i = 0; i < 4; i++) {
            const int lin = i * 128 + tid;
            const int row = lin >> 2, ch = (lin & 3) * 8;
            CP_ASYNC16(smem_u32(&sA[row * GP + ch]), A  + (size_t)(m0 + row) * K + k0 + ch);
            CP_ASYNC16(smem_u32(&sB[row * GP + ch]), BT + (size_t)(n0 + row) * K + k0 + ch);
        }
        CP_COMMIT();
    };

    auto compute_stage = [&](int buf) {
        const __half* sA = smh + buf * ST_H;
        const __half* sB = sA + BH_H;
#pragma unroll
        for (int kk = 0; kk < 2; kk++) {
            uint32_t af[4][4];
#pragma unroll
            for (int mt = 0; mt < 4; mt++) {
                uint32_t a = smem_u32(&sA[(wm * 64 + mt * 16 + a_row_off) * GP + kk * 16 + a_col_off]);
                ldsm_x4(af[mt][0], af[mt][1], af[mt][2], af[mt][3], a);
            }
#pragma unroll
            for (int nt = 0; nt < 4; nt++) {
                uint32_t r0, r1, r2, r3;
                uint32_t a = smem_u32(&sB[(wn * 64 + nt * 16 + b_row_off) * GP + kk * 16 + b_col_off]);
                ldsm_x4(r0, r1, r2, r3, a);
#pragma unroll
                for (int mt = 0; mt < 4; mt++) {
                    mma_f16(acc[mt][2*nt][0], acc[mt][2*nt][1], acc[mt][2*nt][2], acc[mt][2*nt][3],
                            af[mt][0], af[mt][1], af[mt][2], af[mt][3], r0, r1);
                    mma_f16(acc[mt][2*nt+1][0], acc[mt][2*nt+1][1], acc[mt][2*nt+1][2], acc[mt][2*nt+1][3],
                            af[mt][0], af[mt][1], af[mt][2], af[mt][3], r2, r3);
                }
            }
        }
    };

    const int NC = K >> 5;
    load_stage(0, 0);
    load_stage(32, 1);
    for (int c = 0; c < NC; c++) {
        CP_WAIT(1);
        __syncthreads();
        if (c + 2 < NC) load_stage((c + 2) << 5, (c + 2) % NSTAGE);
        compute_stage(c % NSTAGE);
    }

#pragma unroll
    for (int mt = 0; mt < 4; mt++) {
        const int r0 = m0 + wm * 64 + mt * 16 + g;
#pragma unroll
        for (int nj = 0; nj < 8; nj++) {
            const int col = n0 + wn * 64 + nj * 8 + q * 2;
            float b0 = bias[col], b1 = bias[col + 1];
#pragma unroll
            for (int h = 0; h < 2; h++) {
                const int row = r0 + h * 8;
                float v0 = acc[mt][nj][h * 2 + 0] + b0;
                float v1 = acc[mt][nj][h * 2 + 1] + b1;
                if (EPI == 1) {
                    v0 = 0.5f * v0 * (1.0f + erff(v0 * 0.70710678118654752440f));
                    v1 = 0.5f * v1 * (1.0f + erff(v1 * 0.70710678118654752440f));
                }
                if (EPI == 0 || EPI == 1) {
                    *(uint32_t*)&Ch[(size_t)row * N + col] =
                        pack2h(__float2half_rn(v0), __float2half_rn(v1));
                } else {
                    float2 r2 = *(const float2*)(res + (size_t)row * N + col);
                    *(float2*)(C32 + (size_t)row * N + col) = make_float2(v0 + r2.x, v1 + r2.y);
                }
            }
        }
    }
}

// ==================== flash attention (packed QKV fp16, cp.async) =======
// CTA: (b, h, 64 q rows); 4 warps x 16 q rows. kv tiles of 64, double-buffered.
// Q/K/V come from packed qkvh [MTOK][3072]: Q at +0, K at +1024, V at +2048.
#define APAD 72    // halfs per smem row (144 B, 16B-aligned)

__global__ __launch_bounds__(128)
void attn_kernel(const __half* __restrict__ qkv,
                 const float* __restrict__ mask, __half* __restrict__ O)
{
    __shared__ __align__(16) __half Qs[64*APAD];
    __shared__ __align__(16) __half Ks[2][64*APAD];
    __shared__ __align__(16) __half Vs[2][64*APAD];
    __shared__ float msk[2][64];

    const int qt = blockIdx.x, h = blockIdx.y, b = blockIdx.z;
    const int tid = threadIdx.x;
    const int wid = tid >> 5, lane = tid & 31;
    const int g = lane >> 2, t4 = lane & 3;
    const int q0 = qt * 64;
    const size_t basei = (size_t)(b * SS) * QKV3 + h * HDIM;   // input (packed)
    const int baseo = (b * SS) * HH + h * HDIM;                // output
    const int w16 = wid * 16;

    auto load_kv = [&](int kt, int buf) {
#pragma unroll
        for (int i = 0; i < 4; i++) {
            const int c = i * 128 + tid;        // chunk id 0..511
            const int row = c >> 3, ch = (c & 7) * 8;
            CP_ASYNC16(smem_u32(&Ks[buf][row * APAD + ch]),
                       qkv + basei + HH + (size_t)(kt + row) * QKV3 + ch);
            CP_ASYNC16(smem_u32(&Vs[buf][row * APAD + ch]),
                       qkv + basei + 2 * HH + (size_t)(kt + row) * QKV3 + ch);
        }
        if (tid < 64)
            CP_ASYNC4(smem_u32(&msk[buf][tid]), mask + b * SS + kt + tid);
        CP_COMMIT();
    };

    // ---- stage Q ----
    {
        const int r = tid >> 1, c0 = (tid & 1) * 32;
        const __half* Qp = qkv + basei + (size_t)(q0 + r) * QKV3 + c0;
#pragma unroll
        for (int i = 0; i < 4; i++)
            *(uint4*)&Qs[r * APAD + c0 + i * 8] = *(const uint4*)(Qp + i * 8);
    }
    load_kv(0, 0);
    __syncthreads();

    uint32_t qf[4][4];
    {
        const int row = w16 + (lane & 15);
        const int colb = (lane >> 4) << 3;
#pragma unroll
        for (int kk = 0; kk < 4; kk++) {
            uint32_t a = smem_u32(&Qs[row * APAD + kk * 16 + colb]);
            ldsm_x4(qf[kk][0], qf[kk][1], qf[kk][2], qf[kk][3], a);
        }
    }

    float oacc[8][4];
#pragma unroll
    for (int j = 0; j < 8; j++)
#pragma unroll
        for (int t = 0; t < 4; t++) oacc[j][t] = 0.f;
    float m0 = -1e30f, m1 = -1e30f, l0 = 0.f, l1 = 0.f;

    const int krow_off = (lane & 7) + ((lane >> 4) << 3);
    const int kcol_off = (lane & 8);
    const int vrow_off = (lane & 7) + (lane & 8);
    const int vcol_off = ((lane >> 4) << 3);

    for (int ti = 0; ti < SS / 64; ti++) {
        const int buf = ti & 1;
        if (ti + 1 < SS / 64) {
            load_kv((ti + 1) * 64, buf ^ 1);
            CP_WAIT(1);
        } else {
            CP_WAIT(0);
        }
        __syncthreads();

        float sacc[8][4];
#pragma unroll
        for (int j = 0; j < 8; j++)
#pragma unroll
            for (int t = 0; t < 4; t++) sacc[j][t] = 0.f;
#pragma unroll
        for (int jp = 0; jp < 4; jp++) {
#pragma unroll
            for (int kk = 0; kk < 4; kk++) {
                uint32_t r0, r1, r2, r3;
                uint32_t a = smem_u32(&Ks[buf][(jp * 16 + krow_off) * APAD + kk * 16 + kcol_off]);
                ldsm_x4(r0, r1, r2, r3, a);
                mma_f16(sacc[2*jp][0], sacc[2*jp][1], sacc[2*jp][2], sacc[2*jp][3],
                        qf[kk][0], qf[kk][1], qf[kk][2], qf[kk][3], r0, r1);
                mma_f16(sacc[2*jp+1][0], sacc[2*jp+1][1], sacc[2*jp+1][2], sacc[2*jp+1][3],
                        qf[kk][0], qf[kk][1], qf[kk][2], qf[kk][3], r2, r3);
            }
        }

        float tm0 = -1e30f, tm1 = -1e30f;
#pragma unroll
        for (int j = 0; j < 8; j++) {
            const float mv0 = msk[buf][j * 8 + 2 * t4], mv1 = msk[buf][j * 8 + 2 * t4 + 1];
            sacc[j][0] = sacc[j][0] * 0.125f + mv0;
            sacc[j][1] = sacc[j][1] * 0.125f + mv1;
            sacc[j][2] = sacc[j][2] * 0.125f + mv0;
            sacc[j][3] = sacc[j][3] * 0.125f + mv1;
            tm0 = fmaxf(tm0, fmaxf(sacc[j][0], sacc[j][1]));
            tm1 = fmaxf(tm1, fmaxf(sacc[j][2], sacc[j][3]));
        }
        tm0 = fmaxf(tm0, __shfl_xor_sync(0xffffffffu, tm0, 1));
        tm0 = fmaxf(tm0, __shfl_xor_sync(0xffffffffu, tm0, 2));
        tm1 = fmaxf(tm1, __shfl_xor_sync(0xffffffffu, tm1, 1));
        tm1 = fmaxf(tm1, __shfl_xor_sync(0xffffffffu, tm1, 2));
        const float mn0 = fmaxf(m0, tm0), mn1 = fmaxf(m1, tm1);
        const float al0 = __expf(m0 - mn0), al1 = __expf(m1 - mn1);
        m0 = mn0; m1 = mn1;
        float ls0 = 0.f, ls1 = 0.f;
#pragma unroll
        for (int j = 0; j < 8; j++) {
            sacc[j][0] = __expf(sacc[j][0] - mn0);
            sacc[j][1] = __expf(sacc[j][1] - mn0);
            sacc[j][2] = __expf(sacc[j][2] - mn1);
            sacc[j][3] = __expf(sacc[j][3] - mn1);
            ls0 += sacc[j][0] + sacc[j][1];
            ls1 += sacc[j][2] + sacc[j][3];
        }
        l0 = l0 * al0 + ls0;
        l1 = l1 * al1 + ls1;
#pragma unroll
        for (int j = 0; j < 8; j++) {
            oacc[j][0] *= al0; oacc[j][1] *= al0;
            oacc[j][2] *= al1; oacc[j][3] *= al1;
        }

        uint32_t pf[4][4];
#pragma unroll
        for (int kk = 0; kk < 4; kk++) {
            pf[kk][0] = pack2h(__float2half_rn(sacc[2*kk][0]),   __float2half_rn(sacc[2*kk][1]));
            pf[kk][1] = pack2h(__float2half_rn(sacc[2*kk][2]),   __float2half_rn(sacc[2*kk][3]));
            pf[kk][2] = pack2h(__float2half_rn(sacc[2*kk+1][0]), __float2half_rn(sacc[2*kk+1][1]));
            pf[kk][3] = pack2h(__float2half_rn(sacc[2*kk+1][2]), __float2half_rn(sacc[2*kk+1][3]));
        }

#pragma unroll
        for (int dp = 0; dp < 4; dp++) {
#pragma unroll
            for (int kk = 0; kk < 4; kk++) {
                uint32_t r0, r1, r2, r3;
                uint32_t a = smem_u32(&Vs[buf][(kk * 16 + vrow_off) * APAD + dp * 16 + vcol_off]);
                ldsm_x4_t(r0, r1, r2, r3, a);
                mma_f16(oacc[2*dp][0], oacc[2*dp][1], oacc[2*dp][2], oacc[2*dp][3],
                        pf[kk][0], pf[kk][1], pf[kk][2], pf[kk][3], r0, r1);
                mma_f16(oacc[2*dp+1][0], oacc[2*dp+1][1], oacc[2*dp+1][2], oacc[2*dp+1][3],
                        pf[kk][0], pf[kk][1], pf[kk][2], pf[kk][3], r2, r3);
            }
        }
        __syncthreads();
    }

    l0 += __shfl_xor_sync(0xffffffffu, l0, 1);
    l0 += __shfl_xor_sync(0xffffffffu, l0, 2);
    l1 += __shfl_xor_sync(0xffffffffu, l1, 1);
    l1 += __shfl_xor_sync(0xffffffffu, l1, 2);
    const float inv0 = 1.f / l0, inv1 = 1.f / l1;
    const int row0 = q0 + w16 + g;
#pragma unroll
    for (int j = 0; j < 8; j++) {
        const int col = j * 8 + 2 * t4;
        *(uint32_t*)&O[baseo + (size_t)row0 * HH + col] =
            pack2h(__float2half_rn(oacc[j][0] * inv0), __float2half_rn(oacc[j][1] * inv0));
        *(uint32_t*)&O[baseo + (size_t)(row0 + 8) * HH + col] =
            pack2h(__float2half_rn(oacc[j][2] * inv1), __float2half_rn(oacc[j][3] * inv1));
    }
}

// ---------------- layernorm (fp32 out + optional fp16 out) --------------
__global__ __launch_bounds__(256)
void ln_kernel(const float* __restrict__ x, const float* __restrict__ g,
               const float* __restrict__ bt, float* __restrict__ y,
               __half* __restrict__ yh)
{
    const int row = blockIdx.x;
    const int tid = threadIdx.x;
    const int c = tid * 4;
    const float* xr = x + (size_t)row * HH;
    float4 v4 = *(const float4*)(xr + c);
    float v[4] = {v4.x, v4.y, v4.z, v4.w};
    float s = v[0] + v[1] + v[2] + v[3];

    __shared__ float smr[8];
    __shared__ float mu_s, var_s;
#pragma unroll
    for (int o = 16; o; o >>= 1) s += __shfl_xor_sync(0xffffffffu, s, o);
    if ((tid & 31) == 0) smr[tid >> 5] = s;
    __syncthreads();
    if (tid < 32) {
        float t = (tid < 8) ? smr[tid] : 0.f;
#pragma unroll
        for (int o = 4; o; o >>= 1) t += __shfl_xor_sync(0xffffffffu, t, o);
        if (tid == 0) mu_s = t * (1.f / HH);
    }
    __syncthreads();
    const float mu = mu_s;
    float s2 = 0.f;
#pragma unroll
    for (int i = 0; i < 4; i++) { float d = v[i] - mu; s2 += d * d; }
#pragma unroll
    for (int o = 16; o; o >>= 1) s2 += __shfl_xor_sync(0xffffffffu, s2, o);
    __syncthreads();
    if ((tid & 31) == 0) smr[tid >> 5] = s2;
    __syncthreads();
    if (tid < 32) {
        float t = (tid < 8) ? smr[tid] : 0.f;
#pragma unroll
        for (int o = 4; o; o >>= 1) t += __shfl_xor_sync(0xffffffffu, t, o);
        if (tid == 0) var_s = t * (1.f / HH);
    }
    __syncthreads();
    const float inv = rsqrtf(var_s + 1e-5f);
    float4 g4 = *(const float4*)(g + c);
    float4 b4 = *(const float4*)(bt + c);
    float4 r4;
    r4.x = (v[0] - mu) * inv * g4.x + b4.x;
    r4.y = (v[1] - mu) * inv * g4.y + b4.y;
    r4.z = (v[2] - mu) * inv * g4.z + b4.z;
    r4.w = (v[3] - mu) * inv * g4.w + b4.w;
    *(float4*)(y + (size_t)row * HH + c) = r4;
    if (yh) {
        uint2 p;
        p.x = pack2h(__float2half_rn(r4.x), __float2half_rn(r4.y));
        p.y = pack2h(__float2half_rn(r4.z), __float2half_rn(r4.w));
        *(uint2*)&yh[(size_t)row * HH + c] = p;
    }
}

// ---------------- host ----------------
extern "C" void kernel_launch(void* const* d_in, const int* in_sizes, int n_in,
                              void* d_out, int out_size)
{
    (void)in_sizes; (void)n_in; (void)out_size;
    const float* x     = (const float*)d_in[0];
    const float* mask  = (const float*)d_in[1];
    const float* wq    = (const float*)d_in[2];
    const float* bq    = (const float*)d_in[3];
    const float* wk    = (const float*)d_in[4];
    const float* bk    = (const float*)d_in[5];
    const float* wv    = (const float*)d_in[6];
    const float* bv    = (const float*)d_in[7];
    const float* wo    = (const float*)d_in[8];
    const float* bo    = (const float*)d_in[9];
    const float* ln1g  = (const float*)d_in[10];
    const float* ln1b  = (const float*)d_in[11];
    const float* wi    = (const float*)d_in[12];
    const float* bi    = (const float*)d_in[13];
    const float* wo2   = (const float*)d_in[14];
    const float* bo2   = (const float*)d_in[15];
    const float* ln2g  = (const float*)d_in[16];
    const float* ln2b  = (const float*)d_in[17];
    float* out = (float*)d_out;

    __half *xh, *wqkvT, *woT, *wiT, *wo2T;
    __half *qkvh, *ctxh, *attnh, *interh;
    float *bqkv, *t1, *attn32, *t2;
    cudaGetSymbolAddress((void**)&xh,     g_xh);
    cudaGetSymbolAddress((void**)&wqkvT,  g_wqkvT);
    cudaGetSymbolAddress((void**)&woT,    g_woT);
    cudaGetSymbolAddress((void**)&wiT,    g_wiT);
    cudaGetSymbolAddress((void**)&wo2T,   g_wo2T);
    cudaGetSymbolAddress((void**)&bqkv,   g_bqkv);
    cudaGetSymbolAddress((void**)&qkvh,   g_qkvh);
    cudaGetSymbolAddress((void**)&ctxh,   g_ctxh);
    cudaGetSymbolAddress((void**)&attnh,  g_attnh);
    cudaGetSymbolAddress((void**)&interh, g_interh);
    cudaGetSymbolAddress((void**)&t1,     g_t1);
    cudaGetSymbolAddress((void**)&attn32, g_attn32);
    cudaGetSymbolAddress((void**)&t2,     g_t2);

    cudaFuncSetAttribute(gemm_hmma<0>, cudaFuncAttributeMaxDynamicSharedMemorySize, GEMM_SMEM);
    cudaFuncSetAttribute(gemm_hmma<1>, cudaFuncAttributeMaxDynamicSharedMemorySize, GEMM_SMEM);
    cudaFuncSetAttribute(gemm_hmma<2>, cudaFuncAttributeMaxDynamicSharedMemorySize, GEMM_SMEM);

    // ---- pre-pass: weights (transposed fp16), x fp16, packed qkv bias ----
    wt4_kernel<<<dim3(HH / 32, HH / 32, 4), 256>>>(wq, wk, wv, wo, wqkvT, woT);
    wt_kernel<<<dim3(FFD / 32, HH / 32), 256>>>(wi, wiT, HH, FFD);
    wt_kernel<<<dim3(HH / 32, FFD / 32), 256>>>(wo2, wo2T, FFD, HH);
    hconv_kernel<<<MTOK * HH / 1024, 256>>>(x, xh);
    pack_bias_kernel<<<QKV3 / 256, 256>>>(bq, bk, bv, bqkv);

    const dim3 blkG(128);
    const dim3 gQKV(QKV3 / 128, MTOK / 128);   // (24, 32)
    const dim3 gH(HH / 128, MTOK / 128);
    const dim3 gF(FFD / 128, MTOK / 128);

    // fused QKV projection (N=3072, packed output)
    gemm_hmma<0><<<gQKV, blkG, GEMM_SMEM>>>(xh, wqkvT, bqkv, nullptr, nullptr, qkvh, MTOK, QKV3, HH);

    // attention (packed fp16 qkv in, fp16 ctx out)
    attn_kernel<<<dim3(SS / 64, NHEAD, BB), dim3(128)>>>(qkvh, mask, ctxh);

    // output proj + residual, LN1
    gemm_hmma<2><<<gH, blkG, GEMM_SMEM>>>(ctxh, woT, bo, x, t1, nullptr, MTOK, HH, HH);
    ln_kernel<<<MTOK, dim3(256)>>>(t1, ln1g, ln1b, attn32, attnh);

    // FFN
    gemm_hmma<1><<<gF, blkG, GEMM_SMEM>>>(attnh, wiT, bi, nullptr, nullptr, interh, MTOK, FFD, HH);
    gemm_hmma<2><<<gH, blkG, GEMM_SMEM>>>(interh, wo2T, bo2, attn32, t2, nullptr, MTOK, HH, FFD);
    ln_kernel<<<MTOK, dim3(256)>>>(t2, ln2g, ln2b, out, nullptr);
}

// round 17
// speedup vs baseline: 7.3708x; 1.0401x over previous
#include <cuda_runtime.h>
#include <cuda_fp16.h>
#include <cstdint>
#include <math.h>

#define BB 8
#define SS 512
#define HH 1024
#define NHEAD 16
#define HDIM 64
#define FFD 4096
#define MTOK (BB*SS)   // 4096 tokens
#define QKV3 3072

// ---------------- scratch (static __device__, no allocs) ----------------
__device__ __half g_xh[MTOK*HH];
__device__ __half g_wqkvT[(size_t)QKV3*HH];  // packed [3072][1024]
__device__ __half g_woT[HH*HH];
__device__ __half g_wiT[(size_t)HH*FFD];    // [FFD][HH]
__device__ __half g_wo2T[(size_t)FFD*HH];   // [HH][FFD]
__device__ float  g_bqkv[QKV3];
__device__ __half g_qkvh[(size_t)MTOK*QKV3];
__device__ __half g_ctxh[MTOK*HH];
__device__ float  g_part[(size_t)2*MTOK*HH];   // split-K partials (reused)
__device__ float  g_attn32[MTOK*HH];
__device__ __half g_attnh[MTOK*HH];
__device__ __half g_interh[(size_t)MTOK*FFD];

// ==================== helpers ====================
__device__ __forceinline__ uint32_t smem_u32(const void* p) {
    uint32_t a;
    asm("{ .reg .u64 t; cvta.to.shared.u64 t, %1; cvt.u32.u64 %0, t; }" : "=r"(a) : "l"(p));
    return a;
}
__device__ __forceinline__ uint32_t pack2h(__half a, __half b) {
    return (uint32_t)__half_as_ushort(a) | ((uint32_t)__half_as_ushort(b) << 16);
}
__device__ __forceinline__ void mma_f16(float& d0, float& d1, float& d2, float& d3,
                                        uint32_t a0, uint32_t a1, uint32_t a2, uint32_t a3,
                                        uint32_t b0, uint32_t b1) {
    asm volatile(
        "mma.sync.aligned.m16n8k16.row.col.f32.f16.f16.f32 "
        "{%0,%1,%2,%3}, {%4,%5,%6,%7}, {%8,%9}, {%0,%1,%2,%3};"
        : "+f"(d0), "+f"(d1), "+f"(d2), "+f"(d3)
        : "r"(a0), "r"(a1), "r"(a2), "r"(a3), "r"(b0), "r"(b1));
}
__device__ __forceinline__ void ldsm_x4(uint32_t& r0, uint32_t& r1, uint32_t& r2, uint32_t& r3, uint32_t a) {
    asm volatile("ldmatrix.sync.aligned.m8n8.x4.shared.b16 {%0,%1,%2,%3}, [%4];"
        : "=r"(r0), "=r"(r1), "=r"(r2), "=r"(r3) : "r"(a));
}
__device__ __forceinline__ void ldsm_x4_t(uint32_t& r0, uint32_t& r1, uint32_t& r2, uint32_t& r3, uint32_t a) {
    asm volatile("ldmatrix.sync.aligned.m8n8.x4.trans.shared.b16 {%0,%1,%2,%3}, [%4];"
        : "=r"(r0), "=r"(r1), "=r"(r2), "=r"(r3) : "r"(a));
}
#define CP_ASYNC16(s, g) asm volatile("cp.async.cg.shared.global [%0], [%1], 16;" :: "r"(s), "l"(g))
#define CP_ASYNC4(s, g)  asm volatile("cp.async.ca.shared.global [%0], [%1], 4;" :: "r"(s), "l"(g))
#define CP_COMMIT()      asm volatile("cp.async.commit_group;" ::: "memory")
#define CP_WAIT(n)       asm volatile("cp.async.wait_group %0;" :: "n"(n) : "memory")

// ==================== pre-pass kernels ====================
__global__ __launch_bounds__(256)
void wt4_kernel(const float* __restrict__ wq, const float* __restrict__ wk,
                const float* __restrict__ wv, const float* __restrict__ wo,
                __half* __restrict__ wqkvT, __half* __restrict__ woT)
{
    __shared__ __half t[32][33];
    const int z = blockIdx.z;
    const float* W = (z == 0) ? wq : (z == 1) ? wk : (z == 2) ? wv : wo;
    const int n0 = blockIdx.x * 32, k0 = blockIdx.y * 32;
    const int tx = threadIdx.x & 31, ty = threadIdx.x >> 5;
#pragma unroll
    for (int i = 0; i < 4; i++)
        t[ty + i * 8][tx] = __float2half_rn(W[(size_t)(k0 + ty + i * 8) * HH + n0 + tx]);
    __syncthreads();
    __half* dst = (z < 3) ? (wqkvT + (size_t)z * HH * HH) : woT;
#pragma unroll
    for (int i = 0; i < 4; i++)
        dst[(size_t)(n0 + ty + i * 8) * HH + k0 + tx] = t[tx][ty + i * 8];
}

__global__ __launch_bounds__(256)
void wt_kernel(const float* __restrict__ W, __half* __restrict__ WT, int K, int N)
{
    __shared__ __half t[32][33];
    const int n0 = blockIdx.x * 32, k0 = blockIdx.y * 32;
    const int tx = threadIdx.x & 31, ty = threadIdx.x >> 5;
#pragma unroll
    for (int i = 0; i < 4; i++)
        t[ty + i * 8][tx] = __float2half_rn(W[(size_t)(k0 + ty + i * 8) * N + n0 + tx]);
    __syncthreads();
#pragma unroll
    for (int i = 0; i < 4; i++)
        WT[(size_t)(n0 + ty + i * 8) * K + k0 + tx] = t[tx][ty + i * 8];
}

__global__ __launch_bounds__(256)
void hconv_kernel(const float* __restrict__ x, __half* __restrict__ xh)
{
    const size_t i = ((size_t)blockIdx.x * 256 + threadIdx.x) * 8;
    float4 v0 = *(const float4*)(x + i);
    float4 v1 = *(const float4*)(x + i + 4);
    uint4 p;
    p.x = pack2h(__float2half_rn(v0.x), __float2half_rn(v0.y));
    p.y = pack2h(__float2half_rn(v0.z), __float2half_rn(v0.w));
    p.z = pack2h(__float2half_rn(v1.x), __float2half_rn(v1.y));
    p.w = pack2h(__float2half_rn(v1.z), __float2half_rn(v1.w));
    *(uint4*)&xh[i] = p;
}

__global__ __launch_bounds__(256)
void pack_bias_kernel(const float* __restrict__ bq, const float* __restrict__ bk,
                      const float* __restrict__ bv, float* __restrict__ bqkv)
{
    const int i = blockIdx.x * 256 + threadIdx.x;   // 0..3071
    const float* src = (i < HH) ? bq : (i < 2 * HH) ? bk : bv;
    bqkv[i] = src[i & (HH - 1)];
}

// ==================== HMMA GEMM (fp16 in, fp32 accum) ===================
// C = A[M,*](fp16, row stride lda) @ BT[N,*](fp16, row stride lda)^T (+ bias).
// CTA 128x128, BK=32, 4 warps (2m x 2n), warp tile 64x64, cp.async 3-stage.
// blockIdx.z selects a K-split chunk: koff = z*K (loop length K).
// EPI 0: bias -> Ch. EPI 1: gelu(bias+x) -> Ch. EPI 3: raw partial -> C32 + z*M*N.

#define GP 40
#define BH_H 5120
#define ST_H 10240
#define NSTAGE 3
#define GEMM_SMEM (NSTAGE*ST_H*2)   // 61440 bytes

template<int EPI>
__global__ __launch_bounds__(128)
void gemm_hmma(const __half* __restrict__ A, const __half* __restrict__ BT,
               const float* __restrict__ bias,
               float* __restrict__ C32, __half* __restrict__ Ch,
               int M, int N, int K, int lda)
{
    extern __shared__ __half smh[];
    const int tid = threadIdx.x;
    const int m0 = blockIdx.y * 128, n0 = blockIdx.x * 128;
    const int koff = blockIdx.z * K;

    const int wid = tid >> 5, lane = tid & 31;
    const int wm = wid >> 1, wn = wid & 1;
    const int g = lane >> 2, q = lane & 3;

    const int a_row_off = lane & 15;
    const int a_col_off = ((lane >> 4) << 3);
    const int b_row_off = (lane & 7) + ((lane >> 4) << 3);
    const int b_col_off = (lane & 8);

    float acc[4][8][4];
#pragma unroll
    for (int i = 0; i < 4; i++)
#pragma unroll
        for (int j = 0; j < 8; j++)
#pragma unroll
            for (int t = 0; t < 4; t++) acc[i][j][t] = 0.f;

    auto load_stage = [&](int k0, int buf) {
        __half* sA = smh + buf * ST_H;
        __half* sB = sA + BH_H;
#pragma unroll
        for (int i = 0; i < 4; i++) {
            const int lin = i * 128 + tid;
            const int row = lin >> 2, ch = (lin & 3) * 8;
            CP_ASYNC16(smem_u32(&sA[row * GP + ch]), A  + (size_t)(m0 + row) * lda + koff + k0 + ch);
            CP_ASYNC16(smem_u32(&sB[row * GP + ch]), BT + (size_t)(n0 + row) * lda + koff + k0 + ch);
        }
        CP_COMMIT();
    };

    auto compute_stage = [&](int buf) {
        const __half* sA = smh + buf * ST_H;
        const __half* sB = sA + BH_H;
#pragma unroll
        for (int kk = 0; kk < 2; kk++) {
            uint32_t af[4][4];
#pragma unroll
            for (int mt = 0; mt < 4; mt++) {
                uint32_t a = smem_u32(&sA[(wm * 64 + mt * 16 + a_row_off) * GP + kk * 16 + a_col_off]);
                ldsm_x4(af[mt][0], af[mt][1], af[mt][2], af[mt][3], a);
            }
#pragma unroll
            for (int nt = 0; nt < 4; nt++) {
                uint32_t r0, r1, r2, r3;
                uint32_t a = smem_u32(&sB[(wn * 64 + nt * 16 + b_row_off) * GP + kk * 16 + b_col_off]);
                ldsm_x4(r0, r1, r2, r3, a);
#pragma unroll
                for (int mt = 0; mt < 4; mt++) {
                    mma_f16(acc[mt][2*nt][0], acc[mt][2*nt][1], acc[mt][2*nt][2], acc[mt][2*nt][3],
                            af[mt][0], af[mt][1], af[mt][2], af[mt][3], r0, r1);
                    mma_f16(acc[mt][2*nt+1][0], acc[mt][2*nt+1][1], acc[mt][2*nt+1][2], acc[mt][2*nt+1][3],
                            af[mt][0], af[mt][1], af[mt][2], af[mt][3], r2, r3);
                }
            }
        }
    };

    const int NC = K >> 5;
    load_stage(0, 0);
    load_stage(32, 1);
    for (int c = 0; c < NC; c++) {
        CP_WAIT(1);
        __syncthreads();
        if (c + 2 < NC) load_stage((c + 2) << 5, (c + 2) % NSTAGE);
        compute_stage(c % NSTAGE);
    }

    float* Pout = (EPI == 3) ? (C32 + (size_t)blockIdx.z * M * N) : C32;
#pragma unroll
    for (int mt = 0; mt < 4; mt++) {
        const int r0 = m0 + wm * 64 + mt * 16 + g;
#pragma unroll
        for (int nj = 0; nj < 8; nj++) {
            const int col = n0 + wn * 64 + nj * 8 + q * 2;
            float b0 = 0.f, b1 = 0.f;
            if (EPI != 3) { b0 = bias[col]; b1 = bias[col + 1]; }
#pragma unroll
            for (int h = 0; h < 2; h++) {
                const int row = r0 + h * 8;
                float v0 = acc[mt][nj][h * 2 + 0] + b0;
                float v1 = acc[mt][nj][h * 2 + 1] + b1;
                if (EPI == 1) {
                    v0 = 0.5f * v0 * (1.0f + erff(v0 * 0.70710678118654752440f));
                    v1 = 0.5f * v1 * (1.0f + erff(v1 * 0.70710678118654752440f));
                }
                if (EPI == 0 || EPI == 1) {
                    *(uint32_t*)&Ch[(size_t)row * N + col] =
                        pack2h(__float2half_rn(v0), __float2half_rn(v1));
                } else {
                    *(float2*)(Pout + (size_t)row * N + col) = make_float2(v0, v1);
                }
            }
        }
    }
}

// ==================== flash attention (packed QKV fp16, cp.async) =======
#define APAD 72

__global__ __launch_bounds__(128)
void attn_kernel(const __half* __restrict__ qkv,
                 const float* __restrict__ mask, __half* __restrict__ O)
{
    __shared__ __align__(16) __half Qs[64*APAD];
    __shared__ __align__(16) __half Ks[2][64*APAD];
    __shared__ __align__(16) __half Vs[2][64*APAD];
    __shared__ float msk[2][64];

    const int qt = blockIdx.x, h = blockIdx.y, b = blockIdx.z;
    const int tid = threadIdx.x;
    const int wid = tid >> 5, lane = tid & 31;
    const int g = lane >> 2, t4 = lane & 3;
    const int q0 = qt * 64;
    const size_t basei = (size_t)(b * SS) * QKV3 + h * HDIM;
    const int baseo = (b * SS) * HH + h * HDIM;
    const int w16 = wid * 16;

    auto load_kv = [&](int kt, int buf) {
#pragma unroll
        for (int i = 0; i < 4; i++) {
            const int c = i * 128 + tid;
            const int row = c >> 3, ch = (c & 7) * 8;
            CP_ASYNC16(smem_u32(&Ks[buf][row * APAD + ch]),
                       qkv + basei + HH + (size_t)(kt + row) * QKV3 + ch);
            CP_ASYNC16(smem_u32(&Vs[buf][row * APAD + ch]),
                       qkv + basei + 2 * HH + (size_t)(kt + row) * QKV3 + ch);
        }
        if (tid < 64)
            CP_ASYNC4(smem_u32(&msk[buf][tid]), mask + b * SS + kt + tid);
        CP_COMMIT();
    };

    {
        const int r = tid >> 1, c0 = (tid & 1) * 32;
        const __half* Qp = qkv + basei + (size_t)(q0 + r) * QKV3 + c0;
#pragma unroll
        for (int i = 0; i < 4; i++)
            *(uint4*)&Qs[r * APAD + c0 + i * 8] = *(const uint4*)(Qp + i * 8);
    }
    load_kv(0, 0);
    __syncthreads();

    uint32_t qf[4][4];
    {
        const int row = w16 + (lane & 15);
        const int colb = (lane >> 4) << 3;
#pragma unroll
        for (int kk = 0; kk < 4; kk++) {
            uint32_t a = smem_u32(&Qs[row * APAD + kk * 16 + colb]);
            ldsm_x4(qf[kk][0], qf[kk][1], qf[kk][2], qf[kk][3], a);
        }
    }

    float oacc[8][4];
#pragma unroll
    for (int j = 0; j < 8; j++)
#pragma unroll
        for (int t = 0; t < 4; t++) oacc[j][t] = 0.f;
    float m0 = -1e30f, m1 = -1e30f, l0 = 0.f, l1 = 0.f;

    const int krow_off = (lane & 7) + ((lane >> 4) << 3);
    const int kcol_off = (lane & 8);
    const int vrow_off = (lane & 7) + (lane & 8);
    const int vcol_off = ((lane >> 4) << 3);

    for (int ti = 0; ti < SS / 64; ti++) {
        const int buf = ti & 1;
        if (ti + 1 < SS / 64) {
            load_kv((ti + 1) * 64, buf ^ 1);
            CP_WAIT(1);
        } else {
            CP_WAIT(0);
        }
        __syncthreads();

        float sacc[8][4];
#pragma unroll
        for (int j = 0; j < 8; j++)
#pragma unroll
            for (int t = 0; t < 4; t++) sacc[j][t] = 0.f;
#pragma unroll
        for (int jp = 0; jp < 4; jp++) {
#pragma unroll
            for (int kk = 0; kk < 4; kk++) {
                uint32_t r0, r1, r2, r3;
                uint32_t a = smem_u32(&Ks[buf][(jp * 16 + krow_off) * APAD + kk * 16 + kcol_off]);
                ldsm_x4(r0, r1, r2, r3, a);
                mma_f16(sacc[2*jp][0], sacc[2*jp][1], sacc[2*jp][2], sacc[2*jp][3],
                        qf[kk][0], qf[kk][1], qf[kk][2], qf[kk][3], r0, r1);
                mma_f16(sacc[2*jp+1][0], sacc[2*jp+1][1], sacc[2*jp+1][2], sacc[2*jp+1][3],
                        qf[kk][0], qf[kk][1], qf[kk][2], qf[kk][3], r2, r3);
            }
        }

        float tm0 = -1e30f, tm1 = -1e30f;
#pragma unroll
        for (int j = 0; j < 8; j++) {
            const float mv0 = msk[buf][j * 8 + 2 * t4], mv1 = msk[buf][j * 8 + 2 * t4 + 1];
            sacc[j][0] = sacc[j][0] * 0.125f + mv0;
            sacc[j][1] = sacc[j][1] * 0.125f + mv1;
            sacc[j][2] = sacc[j][2] * 0.125f + mv0;
            sacc[j][3] = sacc[j][3] * 0.125f + mv1;
            tm0 = fmaxf(tm0, fmaxf(sacc[j][0], sacc[j][1]));
            tm1 = fmaxf(tm1, fmaxf(sacc[j][2], sacc[j][3]));
        }
        tm0 = fmaxf(tm0, __shfl_xor_sync(0xffffffffu, tm0, 1));
        tm0 = fmaxf(tm0, __shfl_xor_sync(0xffffffffu, tm0, 2));
        tm1 = fmaxf(tm1, __shfl_xor_sync(0xffffffffu, tm1, 1));
        tm1 = fmaxf(tm1, __shfl_xor_sync(0xffffffffu, tm1, 2));
        const float mn0 = fmaxf(m0, tm0), mn1 = fmaxf(m1, tm1);
        const float al0 = __expf(m0 - mn0), al1 = __expf(m1 - mn1);
        m0 = mn0; m1 = mn1;
        float ls0 = 0.f, ls1 = 0.f;
#pragma unroll
        for (int j = 0; j < 8; j++) {
            sacc[j][0] = __expf(sacc[j][0] - mn0);
            sacc[j][1] = __expf(sacc[j][1] - mn0);
            sacc[j][2] = __expf(sacc[j][2] - mn1);
            sacc[j][3] = __expf(sacc[j][3] - mn1);
            ls0 += sacc[j][0] + sacc[j][1];
            ls1 += sacc[j][2] + sacc[j][3];
        }
        l0 = l0 * al0 + ls0;
        l1 = l1 * al1 + ls1;
#pragma unroll
        for (int j = 0; j < 8; j++) {
            oacc[j][0] *= al0; oacc[j][1] *= al0;
            oacc[j][2] *= al1; oacc[j][3] *= al1;
        }

        uint32_t pf[4][4];
#pragma unroll
        for (int kk = 0; kk < 4; kk++) {
            pf[kk][0] = pack2h(__float2half_rn(sacc[2*kk][0]),   __float2half_rn(sacc[2*kk][1]));
            pf[kk][1] = pack2h(__float2half_rn(sacc[2*kk][2]),   __float2half_rn(sacc[2*kk][3]));
            pf[kk][2] = pack2h(__float2half_rn(sacc[2*kk+1][0]), __float2half_rn(sacc[2*kk+1][1]));
            pf[kk][3] = pack2h(__float2half_rn(sacc[2*kk+1][2]), __float2half_rn(sacc[2*kk+1][3]));
        }

#pragma unroll
        for (int dp = 0; dp < 4; dp++) {
#pragma unroll
            for (int kk = 0; kk < 4; kk++) {
                uint32_t r0, r1, r2, r3;
                uint32_t a = smem_u32(&Vs[buf][(kk * 16 + vrow_off) * APAD + dp * 16 + vcol_off]);
                ldsm_x4_t(r0, r1, r2, r3, a);
                mma_f16(oacc[2*dp][0], oacc[2*dp][1], oacc[2*dp][2], oacc[2*dp][3],
                        pf[kk][0], pf[kk][1], pf[kk][2], pf[kk][3], r0, r1);
                mma_f16(oacc[2*dp+1][0], oacc[2*dp+1][1], oacc[2*dp+1][2], oacc[2*dp+1][3],
                        pf[kk][0], pf[kk][1], pf[kk][2], pf[kk][3], r2, r3);
            }
        }
        __syncthreads();
    }

    l0 += __shfl_xor_sync(0xffffffffu, l0, 1);
    l0 += __shfl_xor_sync(0xffffffffu, l0, 2);
    l1 += __shfl_xor_sync(0xffffffffu, l1, 1);
    l1 += __shfl_xor_sync(0xffffffffu, l1, 2);
    const float inv0 = 1.f / l0, inv1 = 1.f / l1;
    const int row0 = q0 + w16 + g;
#pragma unroll
    for (int j = 0; j < 8; j++) {
        const int col = j * 8 + 2 * t4;
        *(uint32_t*)&O[baseo + (size_t)row0 * HH + col] =
            pack2h(__float2half_rn(oacc[j][0] * inv0), __float2half_rn(oacc[j][1] * inv0));
        *(uint32_t*)&O[baseo + (size_t)(row0 + 8) * HH + col] =
            pack2h(__float2half_rn(oacc[j][2] * inv1), __float2half_rn(oacc[j][3] * inv1));
    }
}

// ---------------- fused split-K-reduce + bias + residual + layernorm ----
__global__ __launch_bounds__(256)
void ln_fuse_kernel(const float* __restrict__ p, const float* __restrict__ bias,
                    const float* __restrict__ res,
                    const float* __restrict__ g, const float* __restrict__ bt,
                    float* __restrict__ y, __half* __restrict__ yh)
{
    const int row = blockIdx.x;
    const int tid = threadIdx.x;
    const int c = tid * 4;
    float4 a4 = *(const float4*)(p + (size_t)row * HH + c);
    float4 b4p = *(const float4*)(p + (size_t)(MTOK + row) * HH + c);
    float4 r4i = *(const float4*)(res + (size_t)row * HH + c);
    float4 bi4 = *(const float4*)(bias + c);
    float v[4];
    v[0] = a4.x + b4p.x + r4i.x + bi4.x;
    v[1] = a4.y + b4p.y + r4i.y + bi4.y;
    v[2] = a4.z + b4p.z + r4i.z + bi4.z;
    v[3] = a4.w + b4p.w + r4i.w + bi4.w;
    float s = v[0] + v[1] + v[2] + v[3];

    __shared__ float smr[8];
    __shared__ float mu_s, var_s;
#pragma unroll
    for (int o = 16; o; o >>= 1) s += __shfl_xor_sync(0xffffffffu, s, o);
    if ((tid & 31) == 0) smr[tid >> 5] = s;
    __syncthreads();
    if (tid < 32) {
        float t = (tid < 8) ? smr[tid] : 0.f;
#pragma unroll
        for (int o = 4; o; o >>= 1) t += __shfl_xor_sync(0xffffffffu, t, o);
        if (tid == 0) mu_s = t * (1.f / HH);
    }
    __syncthreads();
    const float mu = mu_s;
    float s2 = 0.f;
#pragma unroll
    for (int i = 0; i < 4; i++) { float d = v[i] - mu; s2 += d * d; }
#pragma unroll
    for (int o = 16; o; o >>= 1) s2 += __shfl_xor_sync(0xffffffffu, s2, o);
    __syncthreads();
    if ((tid & 31) == 0) smr[tid >> 5] = s2;
    __syncthreads();
    if (tid < 32) {
        float t = (tid < 8) ? smr[tid] : 0.f;
#pragma unroll
        for (int o = 4; o; o >>= 1) t += __shfl_xor_sync(0xffffffffu, t, o);
        if (tid == 0) var_s = t * (1.f / HH);
    }
    __syncthreads();
    const float inv = rsqrtf(var_s + 1e-5f);
    float4 g4 = *(const float4*)(g + c);
    float4 bt4 = *(const float4*)(bt + c);
    float4 r4;
    r4.x = (v[0] - mu) * inv * g4.x + bt4.x;
    r4.y = (v[1] - mu) * inv * g4.y + bt4.y;
    r4.z = (v[2] - mu) * inv * g4.z + bt4.z;
    r4.w = (v[3] - mu) * inv * g4.w + bt4.w;
    *(float4*)(y + (size_t)row * HH + c) = r4;
    if (yh) {
        uint2 pk;
        pk.x = pack2h(__float2half_rn(r4.x), __float2half_rn(r4.y));
        pk.y = pack2h(__float2half_rn(r4.z), __float2half_rn(r4.w));
        *(uint2*)&yh[(size_t)row * HH + c] = pk;
    }
}

// ---------------- host ----------------
extern "C" void kernel_launch(void* const* d_in, const int* in_sizes, int n_in,
                              void* d_out, int out_size)
{
    (void)in_sizes; (void)n_in; (void)out_size;
    const float* x     = (const float*)d_in[0];
    const float* mask  = (const float*)d_in[1];
    const float* wq    = (const float*)d_in[2];
    const float* bq    = (const float*)d_in[3];
    const float* wk    = (const float*)d_in[4];
    const float* bk    = (const float*)d_in[5];
    const float* wv    = (const float*)d_in[6];
    const float* bv    = (const float*)d_in[7];
    const float* wo    = (const float*)d_in[8];
    const float* bo    = (const float*)d_in[9];
    const float* ln1g  = (const float*)d_in[10];
    const float* ln1b  = (const float*)d_in[11];
    const float* wi    = (const float*)d_in[12];
    const float* bi    = (const float*)d_in[13];
    const float* wo2   = (const float*)d_in[14];
    const float* bo2   = (const float*)d_in[15];
    const float* ln2g  = (const float*)d_in[16];
    const float* ln2b  = (const float*)d_in[17];
    float* out = (float*)d_out;

    __half *xh, *wqkvT, *woT, *wiT, *wo2T;
    __half *qkvh, *ctxh, *attnh, *interh;
    float *bqkv, *part, *attn32;
    cudaGetSymbolAddress((void**)&xh,     g_xh);
    cudaGetSymbolAddress((void**)&wqkvT,  g_wqkvT);
    cudaGetSymbolAddress((void**)&woT,    g_woT);
    cudaGetSymbolAddress((void**)&wiT,    g_wiT);
    cudaGetSymbolAddress((void**)&wo2T,   g_wo2T);
    cudaGetSymbolAddress((void**)&bqkv,   g_bqkv);
    cudaGetSymbolAddress((void**)&qkvh,   g_qkvh);
    cudaGetSymbolAddress((void**)&ctxh,   g_ctxh);
    cudaGetSymbolAddress((void**)&attnh,  g_attnh);
    cudaGetSymbolAddress((void**)&interh, g_interh);
    cudaGetSymbolAddress((void**)&part,   g_part);
    cudaGetSymbolAddress((void**)&attn32, g_attn32);

    cudaFuncSetAttribute(gemm_hmma<0>, cudaFuncAttributeMaxDynamicSharedMemorySize, GEMM_SMEM);
    cudaFuncSetAttribute(gemm_hmma<1>, cudaFuncAttributeMaxDynamicSharedMemorySize, GEMM_SMEM);
    cudaFuncSetAttribute(gemm_hmma<3>, cudaFuncAttributeMaxDynamicSharedMemorySize, GEMM_SMEM);

    // ---- pre-pass ----
    wt4_kernel<<<dim3(HH / 32, HH / 32, 4), 256>>>(wq, wk, wv, wo, wqkvT, woT);
    wt_kernel<<<dim3(FFD / 32, HH / 32), 256>>>(wi, wiT, HH, FFD);
    wt_kernel<<<dim3(HH / 32, FFD / 32), 256>>>(wo2, wo2T, FFD, HH);
    hconv_kernel<<<MTOK * HH / 2048, 256>>>(x, xh);
    pack_bias_kernel<<<QKV3 / 256, 256>>>(bq, bk, bv, bqkv);

    const dim3 blkG(128);
    const dim3 gQKV(QKV3 / 128, MTOK / 128);          // (24, 32)
    const dim3 gHs(HH / 128, MTOK / 128, 2);          // split-K=2
    const dim3 gF(FFD / 128, MTOK / 128);

    // fused QKV projection (N=3072)
    gemm_hmma<0><<<gQKV, blkG, GEMM_SMEM>>>(xh, wqkvT, bqkv, nullptr, qkvh, MTOK, QKV3, HH, HH);

    // attention
    attn_kernel<<<dim3(SS / 64, NHEAD, BB), dim3(128)>>>(qkvh, mask, ctxh);

    // output proj: split-K=2 partials, then fused reduce+bias+residual+LN1
    gemm_hmma<3><<<gHs, blkG, GEMM_SMEM>>>(ctxh, woT, nullptr, part, nullptr, MTOK, HH, HH / 2, HH);
    ln_fuse_kernel<<<MTOK, dim3(256)>>>(part, bo, x, ln1g, ln1b, attn32, attnh);

    // FFN1 (gelu)
    gemm_hmma<1><<<gF, blkG, GEMM_SMEM>>>(attnh, wiT, bi, nullptr, interh, MTOK, FFD, HH, HH);

    // FFN2: split-K=2 partials, then fused reduce+bias+residual+LN2
    gemm_hmma<3><<<gHs, blkG, GEMM_SMEM>>>(interh, wo2T, nullptr, part, nullptr, MTOK, HH, FFD / 2, FFD);
    ln_fuse_kernel<<<MTOK, dim3(256)>>>(part, bo2, attn32, ln2g, ln2b, out, nullptr);
}